// round 5
// baseline (speedup 1.0000x reference)
#include <cuda_runtime.h>
#include <cuda_bf16.h>
#include <cstdint>

// Problem constants
#define TT      10
#define DD      64
#define HH      4
#define DH      16
#define LL      3
#define FF      256
#define NSEQ    8
#define MM      (NSEQ*TT)   // 80 rows per CTA
#define NTHREADS 256

// Shared memory layout (floats)
#define B_STR   260
#define W_STR   68          // 68 mod 32 = 4 -> conflict-free LDS.128 / STS.128
#define B_ELEMS (MM*B_STR)          // 20800
#define W_ELEMS (64*W_STR)          // 4352
#define SMEM_FLOATS (B_ELEMS + W_ELEMS)
#define SMEM_BYTES  (SMEM_FLOATS*4) // 100608 -> 2 CTAs/SM

// ---------------- packed f32x2 helpers ----------------
__device__ __forceinline__ void fma2(unsigned long long &d,
                                     unsigned long long a,
                                     unsigned long long b) {
    asm("fma.rn.f32x2 %0, %1, %2, %0;" : "+l"(d) : "l"(a), "l"(b));
}
__device__ __forceinline__ float2 unpack2(unsigned long long v) {
    float2 f;
    asm("mov.b64 {%0, %1}, %2;" : "=f"(f.x), "=f"(f.y) : "l"(v));
    return f;
}

// Fast exact-GELU: Abramowitz-Stegun 7.1.26 erf (|abs err| <= 1.5e-7)
__device__ __forceinline__ float gelu_fast(float v) {
    float t = fabsf(v) * 0.70710678118654752f;
    float u = __fdividef(1.0f, fmaf(0.3275911f, t, 1.0f));
    float p = fmaf(1.061405429f, u, -1.453152027f);
    p = fmaf(p, u, 1.421413741f);
    p = fmaf(p, u, -0.284496736f);
    p = fmaf(p, u, 0.254829592f);
    p *= u;
    float e = __expf(-t * t);
    float erf_abs = fmaf(-p, e, 1.0f);
    float sgn = copysignf(erf_abs, v);
    return 0.5f * v * (1.0f + sgn);
}

// 16-lane (half-warp) sum: the 16 lanes differing in bits 0..3 own one row
__device__ __forceinline__ float hsum16(float v) {
    v += __shfl_xor_sync(0xffffffffu, v, 1);
    v += __shfl_xor_sync(0xffffffffu, v, 2);
    v += __shfl_xor_sync(0xffffffffu, v, 4);
    v += __shfl_xor_sync(0xffffffffu, v, 8);
    return v;
}

// ---------------- weight tile staging (64x64), transposed to Wt[j][k] --------
// Each thread owns column j = tid&63, k-groups k4 = (tid>>6)+4i. Global loads
// are coalesced (consecutive j per lane); commit is one STS.128 per group,
// bank-conflict-free with W_STR=68.
struct WFrag { float4 v[4]; };

__device__ __forceinline__ WFrag fetch_w64(const float* __restrict__ g, int gStride) {
    WFrag f;
    const int j  = threadIdx.x & 63;
    const int kb = threadIdx.x >> 6;   // 0..3
#pragma unroll
    for (int i = 0; i < 4; i++) {
        int k4 = kb + 4 * i;           // 0..15
        const float* gp = g + (k4 * 4) * gStride + j;
        float4 v;
        v.x = gp[0];
        v.y = gp[gStride];
        v.z = gp[2 * gStride];
        v.w = gp[3 * gStride];
        f.v[i] = v;
    }
    return f;
}

__device__ __forceinline__ void commit_wt(const WFrag& f, float* __restrict__ wt) {
    const int j  = threadIdx.x & 63;
    const int kb = threadIdx.x >> 6;
#pragma unroll
    for (int i = 0; i < 4; i++) {
        int k4 = kb + 4 * i;
        *reinterpret_cast<float4*>(wt + j * W_STR + k4 * 4) = f.v[i];
    }
}

// ---------------- GEMM tile: [80 x 64] = A[80 x 64] * W[64 x 64] --------------
// tr = tid>>4 (0..15) -> rows tr*5..tr*5+4 ; tc = tid&15 -> cols {tc,tc+16,tc+32,tc+48}
// Residual h lives in registers (hreg[5][4]) with the SAME mapping.
template<bool GELU, bool ACCH, bool STORE, bool LN>
__device__ __forceinline__ void gemm_tile(
    const float* __restrict__ Asm,      // stride B_STR
    const float* __restrict__ wt,
    float (&hreg)[5][4],
    float* __restrict__ Osm,            // stride B_STR (if STORE)
    const float* __restrict__ bias,     // nullptr if none
    float* __restrict__ lnDst,          // stride B_STR (if LN)
    const float* __restrict__ lnG, const float* __restrict__ lnB)
{
    const int tr = threadIdx.x >> 4;
    const int tc = threadIdx.x & 15;
    const float* A0 = Asm + (tr * 5) * B_STR;

    unsigned long long acc[5][4];
#pragma unroll
    for (int u = 0; u < 5; u++)
#pragma unroll
        for (int c = 0; c < 4; c++) acc[u][c] = 0ULL;

#pragma unroll 4
    for (int k4 = 0; k4 < 16; k4++) {
        unsigned long long a0[5], a1[5];
#pragma unroll
        for (int u = 0; u < 5; u++) {
            ulonglong2 av = *reinterpret_cast<const ulonglong2*>(A0 + u * B_STR + k4 * 4);
            a0[u] = av.x;
            a1[u] = av.y;
        }
#pragma unroll
        for (int c = 0; c < 4; c++) {
            ulonglong2 w = *reinterpret_cast<const ulonglong2*>(
                wt + (tc + 16 * c) * W_STR + k4 * 4);
#pragma unroll
            for (int u = 0; u < 5; u++) {
                fma2(acc[u][c], a0[u], w.x);
                fma2(acc[u][c], a1[u], w.y);
            }
        }
    }

    float bv[4], gv[4], bbv[4];
#pragma unroll
    for (int c = 0; c < 4; c++) {
        int j = tc + 16 * c;
        bv[c] = bias ? bias[j] : 0.f;
        if (LN) { gv[c] = lnG[j]; bbv[c] = lnB[j]; }
    }

#pragma unroll
    for (int u = 0; u < 5; u++) {
        float hv[4];
#pragma unroll
        for (int c = 0; c < 4; c++) {
            float2 v = unpack2(acc[u][c]);
            float x = v.x + v.y + bv[c];
            if (GELU) x = gelu_fast(x);
            if (ACCH) { x += hreg[u][c]; hreg[u][c] = x; }
            hv[c] = x;
        }
        if (STORE) {
            float* orow = Osm + (tr * 5 + u) * B_STR;
#pragma unroll
            for (int c = 0; c < 4; c++) orow[tc + 16 * c] = hv[c];
        }
        if (LN) {
            float s  = hv[0] + hv[1] + hv[2] + hv[3];
            float s2 = hv[0]*hv[0] + hv[1]*hv[1] + hv[2]*hv[2] + hv[3]*hv[3];
            s  = hsum16(s);
            s2 = hsum16(s2);
            float m   = s * (1.f / DD);
            float inv = rsqrtf(s2 * (1.f / DD) - m * m + 1e-5f);
            float* lrow = lnDst + (tr * 5 + u) * B_STR;
#pragma unroll
            for (int c = 0; c < 4; c++)
                lrow[tc + 16 * c] = (hv[c] - m) * inv * gv[c] + bbv[c];
        }
    }
}

__global__ __launch_bounds__(NTHREADS, 2)
void waypoint_kernel(
    const float* __restrict__ x,
    const float* __restrict__ embed_w, const float* __restrict__ embed_b,
    const float* __restrict__ ln1_g,   const float* __restrict__ ln1_b,
    const float* __restrict__ qkv_w,   const float* __restrict__ proj_w,
    const float* __restrict__ ln2_g,   const float* __restrict__ ln2_b,
    const float* __restrict__ ffn_w1,  const float* __restrict__ ffn_b1,
    const float* __restrict__ ffn_w2,  const float* __restrict__ ffn_b2,
    const float* __restrict__ lnf_g,   const float* __restrict__ lnf_b,
    const float* __restrict__ head_w,  const float* __restrict__ head_b,
    float* __restrict__ out)
{
    extern __shared__ float smx[];
    float* buf = smx;                // [80][260]
    float* wt  = smx + B_ELEMS;      // [64][68] transposed weight tile

    const int tid = threadIdx.x;
    const int tr  = tid >> 4;
    const int tc  = tid & 15;
    const int rowBase = blockIdx.x * MM;

    float hreg[5][4];                // residual stream, register-resident

    // Prefetch layer-0 qkv tile 0 early (overlaps embed compute)
    WFrag wf = fetch_w64(qkv_w, 3 * DD);

    // -------- embed into hreg (+ fused ln1 of layer 0 -> buf[:,192:256]) -----
    {
        float wcol[4][4], bcol[4], gcol[4], lbcol[4];
#pragma unroll
        for (int c = 0; c < 4; c++) {
            int j = tc + 16 * c;
            wcol[c][0] = embed_w[j];
            wcol[c][1] = embed_w[64 + j];
            wcol[c][2] = embed_w[128 + j];
            wcol[c][3] = embed_w[192 + j];
            bcol[c]  = embed_b[j];
            gcol[c]  = ln1_g[j];
            lbcol[c] = ln1_b[j];
        }
#pragma unroll
        for (int u = 0; u < 5; u++) {
            int r = tr * 5 + u;
            float4 xv = reinterpret_cast<const float4*>(x)[rowBase + r];
            float hv[4];
#pragma unroll
            for (int c = 0; c < 4; c++) {
                float v = bcol[c];
                v = fmaf(xv.x, wcol[c][0], v);
                v = fmaf(xv.y, wcol[c][1], v);
                v = fmaf(xv.z, wcol[c][2], v);
                v = fmaf(xv.w, wcol[c][3], v);
                hreg[u][c] = v;
                hv[c] = v;
            }
            float s  = hv[0] + hv[1] + hv[2] + hv[3];
            float s2 = hv[0]*hv[0] + hv[1]*hv[1] + hv[2]*hv[2] + hv[3]*hv[3];
            s  = hsum16(s);
            s2 = hsum16(s2);
            float m   = s * (1.f / DD);
            float inv = rsqrtf(s2 * (1.f / DD) - m * m + 1e-5f);
            float* lrow = buf + 192 + r * B_STR;
#pragma unroll
            for (int c = 0; c < 4; c++)
                lrow[tc + 16 * c] = (hv[c] - m) * inv * gcol[c] + lbcol[c];
        }
    }

    for (int i = 0; i < LL; i++) {
        const float* l_qkv = qkv_w  + i * DD * 3 * DD;
        const float* l_prj = proj_w + i * DD * DD;
        const float* l_w1  = ffn_w1 + i * DD * FF;
        const float* l_w2  = ffn_w2 + i * FF * DD;

        // -------- qkv: buf[:,0:192] = ln1 @ qkv_w --------
        for (int nt = 0; nt < 3; nt++) {
            __syncthreads();          // prior buf writes + wt free
            commit_wt(wf, wt);
            if (nt < 2)  wf = fetch_w64(l_qkv + (nt + 1) * 64, 3 * DD);
            else         wf = fetch_w64(l_prj, DD);
            __syncthreads();
            gemm_tile<false,false,true,false>(buf + 192, wt, hreg, buf + nt * 64,
                                              nullptr, nullptr, nullptr, nullptr);
        }
        __syncthreads();

        // -------- attention (causal, T=10, dh=16), float4 --------
        {
            int pair = tid >> 3;       // 0..31 : (seq, head)
            int sub  = tid & 7;
            int s  = pair >> 2;        // 0..7
            int hd = pair & 3;         // 0..3
            const float4* qb = reinterpret_cast<const float4*>(buf + hd * DH);
            const float4* kb = reinterpret_cast<const float4*>(buf + 64  + hd * DH);
            const float4* vb = reinterpret_cast<const float4*>(buf + 128 + hd * DH);
            float4* yb = reinterpret_cast<float4*>(buf + 192 + hd * DH);
            const int RS = B_STR / 4;  // 65

            for (int q = sub; q < TT; q += 8) {
                int rq = s * TT + q;
                float4 qv[4];
#pragma unroll
                for (int d = 0; d < 4; d++) qv[d] = qb[rq * RS + d];

                float sc[TT];
                float mx = -1e30f;
                for (int kk = 0; kk <= q; kk++) {
                    const float4* kr = kb + (s * TT + kk) * RS;
                    float a = 0.f;
#pragma unroll
                    for (int d = 0; d < 4; d++) {
                        float4 kv = kr[d];
                        a = fmaf(qv[d].x, kv.x, a);
                        a = fmaf(qv[d].y, kv.y, a);
                        a = fmaf(qv[d].z, kv.z, a);
                        a = fmaf(qv[d].w, kv.w, a);
                    }
                    a *= 0.25f;
                    sc[kk] = a;
                    mx = fmaxf(mx, a);
                }
                float ssum = 0.f;
                for (int kk = 0; kk <= q; kk++) {
                    sc[kk] = __expf(sc[kk] - mx);
                    ssum += sc[kk];
                }
                float inv = __fdividef(1.f, ssum);
                float4 y[4];
#pragma unroll
                for (int d = 0; d < 4; d++) y[d] = make_float4(0.f, 0.f, 0.f, 0.f);
                for (int kk = 0; kk <= q; kk++) {
                    float a = sc[kk] * inv;
                    const float4* vr = vb + (s * TT + kk) * RS;
#pragma unroll
                    for (int d = 0; d < 4; d++) {
                        float4 vv = vr[d];
                        y[d].x = fmaf(a, vv.x, y[d].x);
                        y[d].y = fmaf(a, vv.y, y[d].y);
                        y[d].z = fmaf(a, vv.z, y[d].z);
                        y[d].w = fmaf(a, vv.w, y[d].w);
                    }
                }
#pragma unroll
                for (int d = 0; d < 4; d++) yb[rq * RS + d] = y[d];
            }
        }
        __syncthreads();

        // -------- proj: h += y @ proj_w  (+ fused ln2 -> buf[:,0:64]) --------
        commit_wt(wf, wt);
        wf = fetch_w64(l_w1, FF);
        __syncthreads();
        gemm_tile<false,true,false,true>(buf + 192, wt, hreg, nullptr, nullptr,
                                         buf, ln2_g + i * DD, ln2_b + i * DD);

        // -------- FFN, N tiled 4x64 --------
        for (int ft = 0; ft < 4; ft++) {
            // z = gelu(ln2 @ w1 + b1) -> buf[:,64:128]
            __syncthreads();
            commit_wt(wf, wt);
            wf = fetch_w64(l_w2 + ft * 64 * DD, DD);
            __syncthreads();
            gemm_tile<true,false,true,false>(buf, wt, hreg, buf + 64,
                                             ffn_b1 + i * FF + ft * 64,
                                             nullptr, nullptr, nullptr);
            __syncthreads();

            // h += z @ w2 (+ b2 at ft==0; fused LN at ft==3)
            commit_wt(wf, wt);
            if (ft < 3)      wf = fetch_w64(l_w1 + (ft + 1) * 64, FF);
            else if (i < 2)  wf = fetch_w64(qkv_w + (i + 1) * DD * 3 * DD, 3 * DD);
            else             wf = fetch_w64(qkv_w, 3 * DD);   // harmless tail
            __syncthreads();
            const float* b2 = (ft == 0) ? (ffn_b2 + i * DD) : nullptr;
            if (ft < 3) {
                gemm_tile<false,true,false,false>(buf + 64, wt, hreg, nullptr, b2,
                                                  nullptr, nullptr, nullptr);
            } else if (i < 2) {
                gemm_tile<false,true,false,true>(buf + 64, wt, hreg, nullptr, b2,
                                                 buf + 192,
                                                 ln1_g + (i + 1) * DD, ln1_b + (i + 1) * DD);
            } else {
                gemm_tile<false,true,false,true>(buf + 64, wt, hreg, nullptr, b2,
                                                 buf, lnf_g, lnf_b);
            }
        }
    }
    __syncthreads();

    // -------- head: out[s, j] = lnf[last token] @ head_w + head_b --------
    if (tid < NSEQ * 10) {
        int s = tid / 10;
        int j = tid % 10;
        const float* r = buf + (s * TT + TT - 1) * B_STR;
        float a = head_b[j];
#pragma unroll 16
        for (int d = 0; d < DD; d++) a = fmaf(r[d], head_w[d * 10 + j], a);
        out[(blockIdx.x * NSEQ + s) * 10 + j] = a;
    }
}

extern "C" void kernel_launch(void* const* d_in, const int* in_sizes, int n_in,
                              void* d_out, int out_size)
{
    const float* x       = (const float*)d_in[0];
    const float* embed_w = (const float*)d_in[1];
    const float* embed_b = (const float*)d_in[2];
    const float* ln1_g   = (const float*)d_in[3];
    const float* ln1_b   = (const float*)d_in[4];
    const float* qkv_w   = (const float*)d_in[5];
    const float* proj_w  = (const float*)d_in[6];
    const float* ln2_g   = (const float*)d_in[7];
    const float* ln2_b   = (const float*)d_in[8];
    const float* ffn_w1  = (const float*)d_in[9];
    const float* ffn_b1  = (const float*)d_in[10];
    const float* ffn_w2  = (const float*)d_in[11];
    const float* ffn_b2  = (const float*)d_in[12];
    const float* lnf_g   = (const float*)d_in[13];
    const float* lnf_b   = (const float*)d_in[14];
    const float* head_w  = (const float*)d_in[15];
    const float* head_b  = (const float*)d_in[16];
    float* out = (float*)d_out;

    int nTokens = in_sizes[0] / 4;
    int nB = nTokens / TT;
    int grid = nB / NSEQ;              // 2048

    cudaFuncSetAttribute(waypoint_kernel,
                         cudaFuncAttributeMaxDynamicSharedMemorySize, SMEM_BYTES);

    waypoint_kernel<<<grid, NTHREADS, SMEM_BYTES>>>(
        x, embed_w, embed_b, ln1_g, ln1_b, qkv_w, proj_w,
        ln2_g, ln2_b, ffn_w1, ffn_b1, ffn_w2, ffn_b2,
        lnf_g, lnf_b, head_w, head_b, out);
}

// round 7
// speedup vs baseline: 1.3816x; 1.3816x over previous
#include <cuda_runtime.h>
#include <cuda_bf16.h>
#include <cstdint>

// ---------------- problem constants ----------------
#define TT      10
#define DD      64
#define LL      3
#define FF      256
#define NSEQ    16
#define MROWS   160
#define NTH     320

// ---------------- SMEM layout (bytes) ----------------
#define OUT_OFF   0               // fp32 [160][68]
#define OUT_STR   68
#define A0H_OFF   43520           // bf16 [160][72]
#define A0L_OFF   66560
#define A1H_OFF   89600           // bf16 [160][72]  (doubles as fp32 kbuf [160][72])
#define A1L_OFF   112640
#define W_OFF(s)  (135680 + (s) * 18432)   // slot: hi at +0, lo at +9216
#define WLO       9216
#define S_OFF     172544          // fp32 [16][4][10][12]
#define SMEM_BYTES 203264

#define AB_STR    144             // bf16 row stride in bytes (72 halves)

// ---------------- helpers ----------------
__device__ __forceinline__ uint32_t smem_u32_of(const void* p) {
    uint32_t a;
    asm("{ .reg .u64 t; cvta.to.shared.u64 t, %1; cvt.u32.u64 %0, t; }" : "=r"(a) : "l"(p));
    return a;
}

__device__ __forceinline__ void ldm4(uint32_t& r0, uint32_t& r1, uint32_t& r2, uint32_t& r3,
                                     uint32_t a) {
    asm volatile("ldmatrix.sync.aligned.m8n8.x4.shared.b16 {%0,%1,%2,%3}, [%4];"
                 : "=r"(r0), "=r"(r1), "=r"(r2), "=r"(r3) : "r"(a));
}

__device__ __forceinline__ void mma16816(float* d,
                                         uint32_t a0, uint32_t a1, uint32_t a2, uint32_t a3,
                                         uint32_t b0, uint32_t b1) {
    asm volatile("mma.sync.aligned.m16n8k16.row.col.f32.bf16.bf16.f32 "
                 "{%0,%1,%2,%3}, {%4,%5,%6,%7}, {%8,%9}, {%0,%1,%2,%3};"
                 : "+f"(d[0]), "+f"(d[1]), "+f"(d[2]), "+f"(d[3])
                 : "r"(a0), "r"(a1), "r"(a2), "r"(a3), "r"(b0), "r"(b1));
}

__device__ __forceinline__ float gelu_fast(float v) {
    float t = fabsf(v) * 0.70710678118654752f;
    float u = __fdividef(1.0f, fmaf(0.3275911f, t, 1.0f));
    float p = fmaf(1.061405429f, u, -1.453152027f);
    p = fmaf(p, u, 1.421413741f);
    p = fmaf(p, u, -0.284496736f);
    p = fmaf(p, u, 0.254829592f);
    p *= u;
    float e = __expf(-t * t);
    float erf_abs = fmaf(-p, e, 1.0f);
    return 0.5f * v * (1.0f + copysignf(erf_abs, v));
}

__device__ __forceinline__ void ld_row32(const float* p, float* v) {
    const float4* q = reinterpret_cast<const float4*>(p);
#pragma unroll
    for (int i = 0; i < 8; i++) {
        float4 t = q[i];
        v[4*i] = t.x; v[4*i+1] = t.y; v[4*i+2] = t.z; v[4*i+3] = t.w;
    }
}

// store 32 fp32 as bf16 hi/lo split, row-major stride AB_STR
__device__ __forceinline__ void st_a32(char* hi, char* lo, int row, int c0, const float* v) {
#pragma unroll
    for (int g = 0; g < 4; g++) {
        uint32_t ph[4], pl[4];
#pragma unroll
        for (int i = 0; i < 4; i++) {
            float x0 = v[g*8 + 2*i], x1 = v[g*8 + 2*i + 1];
            float h0 = __bfloat162float(__float2bfloat16(x0));
            float h1 = __bfloat162float(__float2bfloat16(x1));
            __nv_bfloat162 hp = __floats2bfloat162_rn(h0, h1);
            __nv_bfloat162 lp = __floats2bfloat162_rn(x0 - h0, x1 - h1);
            ph[i] = *reinterpret_cast<uint32_t*>(&hp);
            pl[i] = *reinterpret_cast<uint32_t*>(&lp);
        }
        *reinterpret_cast<uint4*>(hi + row*AB_STR + c0*2 + g*16) = make_uint4(ph[0], ph[1], ph[2], ph[3]);
        *reinterpret_cast<uint4*>(lo + row*AB_STR + c0*2 + g*16) = make_uint4(pl[0], pl[1], pl[2], pl[3]);
    }
}

// ---------------- MMA stage: dst[160x64] = A @ Wt, K=64, bf16-split 3 passes ----
__device__ __forceinline__ void mma_stage(uint32_t aHi, uint32_t aLo,
                                          uint32_t wHi, uint32_t wLo,
                                          float* dstF, int dstStr)
{
    const int w    = threadIdx.x >> 5;
    const int lane = threadIdx.x & 31;
    const uint32_t lrow   = lane & 15;
    const uint32_t lchunk = (lane >> 4) & 1;

    float d[4][2][4];
#pragma unroll
    for (int i = 0; i < 4; i++)
#pragma unroll
        for (int t = 0; t < 2; t++)
#pragma unroll
            for (int j = 0; j < 4; j++) d[i][t][j] = 0.f;

    uint32_t offA[4], offB[4];
#pragma unroll
    for (int i = 0; i < 4; i++) {
        int u = w + 10 * i;
        int mt = u >> 2, cg = u & 3;
        offA[i] = (mt * 16 + lrow) * AB_STR + lchunk * 16;
        offB[i] = (cg * 16 + lrow) * AB_STR + lchunk * 16;
    }

#pragma unroll
    for (int ks = 0; ks < 4; ks++) {
#pragma unroll
        for (int i = 0; i < 4; i++) {
            uint32_t ah0, ah1, ah2, ah3, al0, al1, al2, al3;
            uint32_t bh0, bh1, bh2, bh3, bl0, bl1, bl2, bl3;
            ldm4(ah0, ah1, ah2, ah3, aHi + offA[i] + ks * 32);
            ldm4(al0, al1, al2, al3, aLo + offA[i] + ks * 32);
            ldm4(bh0, bh1, bh2, bh3, wHi + offB[i] + ks * 32);
            ldm4(bl0, bl1, bl2, bl3, wLo + offB[i] + ks * 32);
            mma16816(d[i][0], ah0, ah1, ah2, ah3, bh0, bh2);
            mma16816(d[i][1], ah0, ah1, ah2, ah3, bh1, bh3);
            mma16816(d[i][0], ah0, ah1, ah2, ah3, bl0, bl2);
            mma16816(d[i][1], ah0, ah1, ah2, ah3, bl1, bl3);
            mma16816(d[i][0], al0, al1, al2, al3, bh0, bh2);
            mma16816(d[i][1], al0, al1, al2, al3, bh1, bh3);
        }
    }

#pragma unroll
    for (int i = 0; i < 4; i++) {
        int u = w + 10 * i;
        int mt = u >> 2, cg = u & 3;
        int r0 = mt * 16 + (lane >> 2);
        int c0 = cg * 16 + (lane & 3) * 2;
#pragma unroll
        for (int t = 0; t < 2; t++) {
            *reinterpret_cast<float2*>(dstF + r0 * dstStr + c0 + t * 8) =
                make_float2(d[i][t][0], d[i][t][1]);
            *reinterpret_cast<float2*>(dstF + (r0 + 8) * dstStr + c0 + t * 8) =
                make_float2(d[i][t][2], d[i][t][3]);
        }
    }
}

// ---------------- W staging ----------------
struct WF { float v[16]; };

__device__ __forceinline__ WF fetch_w(const float* __restrict__ g, int ldg) {
    WF f;
    int t = threadIdx.x;
    if (t < 256) {
        int n = t & 63, kb = t >> 6;
#pragma unroll
        for (int i = 0; i < 16; i++) f.v[i] = __ldg(g + (kb * 16 + i) * ldg + n);
    }
    return f;
}

__device__ __forceinline__ void commit_w(const WF& f, char* hi, char* lo) {
    int t = threadIdx.x;
    if (t < 256) {
        int n = t & 63, kb = t >> 6;
#pragma unroll
        for (int i = 0; i < 16; i += 2) {
            float x0 = f.v[i], x1 = f.v[i + 1];
            float h0 = __bfloat162float(__float2bfloat16(x0));
            float h1 = __bfloat162float(__float2bfloat16(x1));
            __nv_bfloat162 hp = __floats2bfloat162_rn(h0, h1);
            __nv_bfloat162 lp = __floats2bfloat162_rn(x0 - h0, x1 - h1);
            *reinterpret_cast<uint32_t*>(hi + n * AB_STR + (kb * 16 + i) * 2) =
                *reinterpret_cast<uint32_t*>(&hp);
            *reinterpret_cast<uint32_t*>(lo + n * AB_STR + (kb * 16 + i) * 2) =
                *reinterpret_cast<uint32_t*>(&lp);
        }
    }
}

__device__ __forceinline__ const float* wptr_for(int st, int& ldg,
    const float* qkv_w, const float* proj_w, const float* w1, const float* w2)
{
    if (st >= 36) { ldg = 192; return qkv_w; }
    int li = st / 12, k = st % 12;
    switch (k) {
        case 0:  ldg = 192; return qkv_w + li * 64 * 192;
        case 1:  ldg = 192; return qkv_w + li * 64 * 192 + 64;
        case 2:  ldg = 192; return qkv_w + li * 64 * 192 + 128;
        case 3:  ldg = 64;  return proj_w + li * 64 * 64;
        case 4: case 6: case 8: case 10: {
            int ft = (k - 4) >> 1; ldg = 256; return w1 + li * 64 * 256 + ft * 64;
        }
        default: {
            int ft = (k - 5) >> 1; ldg = 64;  return w2 + li * 256 * 64 + ft * 64 * 64;
        }
    }
}

// =====================================================================
__global__ __launch_bounds__(NTH, 1)
void waypoint_mma_kernel(
    const float* __restrict__ x,
    const float* __restrict__ embed_w, const float* __restrict__ embed_b,
    const float* __restrict__ ln1_g,   const float* __restrict__ ln1_b,
    const float* __restrict__ qkv_w,   const float* __restrict__ proj_w,
    const float* __restrict__ ln2_g,   const float* __restrict__ ln2_b,
    const float* __restrict__ ffn_w1,  const float* __restrict__ ffn_b1,
    const float* __restrict__ ffn_w2,  const float* __restrict__ ffn_b2,
    const float* __restrict__ lnf_g,   const float* __restrict__ lnf_b,
    const float* __restrict__ head_w,  const float* __restrict__ head_b,
    float* __restrict__ out)
{
    extern __shared__ char smc[];
    const uint32_t su = smem_u32_of(smc);
    float* outF = reinterpret_cast<float*>(smc + OUT_OFF);
    float* kF   = reinterpret_cast<float*>(smc + A1H_OFF);   // fp32 view, stride 72
    float* SB   = reinterpret_cast<float*>(smc + S_OFF);

    const int tid  = threadIdx.x;
    const int er   = tid >> 1;        // row 0..159
    const int c0e  = (tid & 1) * 32;  // column half
    const int rowBase = blockIdx.x * MROWS;

    float hreg[32];                   // residual stream slice (row er, cols c0e..+31)

    WF wf = fetch_w(qkv_w, 192);      // stage 0 weights (q of layer 0)

    // -------- embed + ln1(layer0) -> A0 --------
    {
        float4 xv = reinterpret_cast<const float4*>(x)[rowBase + er];
        float v[32];
#pragma unroll
        for (int i = 0; i < 32; i++) {
            int j = c0e + i;
            float a = embed_b[j];
            a = fmaf(xv.x, embed_w[j],       a);
            a = fmaf(xv.y, embed_w[64 + j],  a);
            a = fmaf(xv.z, embed_w[128 + j], a);
            a = fmaf(xv.w, embed_w[192 + j], a);
            hreg[i] = a; v[i] = a;
        }
        float s = 0.f, s2 = 0.f;
#pragma unroll
        for (int i = 0; i < 32; i++) { s += v[i]; s2 += v[i] * v[i]; }
        s  += __shfl_xor_sync(0xffffffffu, s, 1);
        s2 += __shfl_xor_sync(0xffffffffu, s2, 1);
        float m   = s * (1.f / 64.f);
        float inv = rsqrtf(s2 * (1.f / 64.f) - m * m + 1e-5f);
        float o[32];
#pragma unroll
        for (int i = 0; i < 32; i++)
            o[i] = (v[i] - m) * inv * ln1_g[c0e + i] + ln1_b[c0e + i];
        st_a32(smc + A0H_OFF, smc + A0L_OFF, er, c0e, o);
    }
    // commit stage-0 W; fetch stage-1 W
    commit_w(wf, smc + W_OFF(0), smc + W_OFF(0) + WLO);
    {
        int ldg; const float* p = wptr_for(1, ldg, qkv_w, proj_w, ffn_w1, ffn_w2);
        wf = fetch_w(p, ldg);
    }
    __syncthreads();

    for (int st = 0; st < 36; st++) {
        const int kind = st % 12;
        const int li   = st / 12;
        const int cur  = st & 1;
        const bool fromA1 = (kind == 3) || (kind >= 4 && ((kind - 4) & 1));  // proj + ffn2

        uint32_t aH = su + (fromA1 ? A1H_OFF : A0H_OFF);
        uint32_t aL = su + (fromA1 ? A1L_OFF : A0L_OFF);
        uint32_t wH = su + W_OFF(cur);
        uint32_t wL = wH + WLO;

        if (kind == 1) mma_stage(aH, aL, wH, wL, kF, 72);
        else           mma_stage(aH, aL, wH, wL, outF, OUT_STR);
        __syncthreads();

        // ---------------- epilogue ----------------
        if (kind == 1) {
            // S phase: probabilities from q (outF) and k (kF)
#pragma unroll
            for (int j = 0; j < 2; j++) {
                int id = tid + NTH * j;            // 0..639
                int s  = id / 40;
                int rem = id % 40;
                int h  = rem / 10;
                int q  = rem % 10;
                const float4* qp = reinterpret_cast<const float4*>(outF + (s*TT + q) * OUT_STR + h * 16);
                float4 qv[4];
#pragma unroll
                for (int d = 0; d < 4; d++) qv[d] = qp[d];
                float sc[TT];
                float mx = -1e30f;
                for (int kk = 0; kk <= q; kk++) {
                    const float4* kp = reinterpret_cast<const float4*>(kF + (s*TT + kk) * 72 + h * 16);
                    float a = 0.f;
#pragma unroll
                    for (int d = 0; d < 4; d++) {
                        float4 kv = kp[d];
                        a = fmaf(qv[d].x, kv.x, a);
                        a = fmaf(qv[d].y, kv.y, a);
                        a = fmaf(qv[d].z, kv.z, a);
                        a = fmaf(qv[d].w, kv.w, a);
                    }
                    a *= 0.25f;
                    sc[kk] = a;
                    mx = fmaxf(mx, a);
                }
                float ss = 0.f;
                for (int kk = 0; kk <= q; kk++) { sc[kk] = __expf(sc[kk] - mx); ss += sc[kk]; }
                float inv = __fdividef(1.f, ss);
                float* sp = SB + ((s * 4 + h) * TT + q) * 12;
#pragma unroll
                for (int kk = 0; kk < TT; kk++) sp[kk] = (kk <= q) ? sc[kk] * inv : 0.f;
            }
        } else if (kind == 2) {
            // y phase: y = S @ v  -> A1 (bf16 split)
            int s = er / TT, q = er % TT;
            int h0 = c0e >> 4;  // 0 or 2
            const float* s0 = SB + ((s * 4 + h0) * TT + q) * 12;
            const float* s1 = SB + ((s * 4 + h0 + 1) * TT + q) * 12;
            float y[32];
#pragma unroll
            for (int i = 0; i < 32; i++) y[i] = 0.f;
            for (int kk = 0; kk < TT; kk++) {
                float w0 = s0[kk], w1 = s1[kk];
                const float4* vp = reinterpret_cast<const float4*>(outF + (s*TT + kk) * OUT_STR + c0e);
#pragma unroll
                for (int d = 0; d < 8; d++) {
                    float4 vv = vp[d];
                    float wgt = (d < 4) ? w0 : w1;
                    y[d*4+0] = fmaf(wgt, vv.x, y[d*4+0]);
                    y[d*4+1] = fmaf(wgt, vv.y, y[d*4+1]);
                    y[d*4+2] = fmaf(wgt, vv.z, y[d*4+2]);
                    y[d*4+3] = fmaf(wgt, vv.w, y[d*4+3]);
                }
            }
            st_a32(smc + A1H_OFF, smc + A1L_OFF, er, c0e, y);
        } else if (kind == 3) {
            // proj: h += out ; ln2 -> A0
            float v[32];
            ld_row32(outF + er * OUT_STR + c0e, v);
#pragma unroll
            for (int i = 0; i < 32; i++) { v[i] += hreg[i]; hreg[i] = v[i]; }
            float s = 0.f, s2 = 0.f;
#pragma unroll
            for (int i = 0; i < 32; i++) { s += v[i]; s2 += v[i] * v[i]; }
            s  += __shfl_xor_sync(0xffffffffu, s, 1);
            s2 += __shfl_xor_sync(0xffffffffu, s2, 1);
            float m   = s * (1.f / 64.f);
            float inv = rsqrtf(s2 * (1.f / 64.f) - m * m + 1e-5f);
            float o[32];
#pragma unroll
            for (int i = 0; i < 32; i++)
                o[i] = (v[i] - m) * inv * ln2_g[li*DD + c0e + i] + ln2_b[li*DD + c0e + i];
            st_a32(smc + A0H_OFF, smc + A0L_OFF, er, c0e, o);
        } else if (kind >= 4 && !((kind - 4) & 1)) {
            // ffn1 chunk: gelu(out + b1) -> A1
            int ft = (kind - 4) >> 1;
            float v[32];
            ld_row32(outF + er * OUT_STR + c0e, v);
            float o[32];
#pragma unroll
            for (int i = 0; i < 32; i++)
                o[i] = gelu_fast(v[i] + ffn_b1[li*FF + ft*64 + c0e + i]);
            st_a32(smc + A1H_OFF, smc + A1L_OFF, er, c0e, o);
        } else if (kind >= 5) {
            // ffn2 chunk: h += out (+b2 at ft0); at ft3: LN -> A0 / outF
            int ft = (kind - 5) >> 1;
            float v[32];
            ld_row32(outF + er * OUT_STR + c0e, v);
            if (ft == 0) {
#pragma unroll
                for (int i = 0; i < 32; i++)
                    hreg[i] += v[i] + ffn_b2[li*DD + c0e + i];
            } else {
#pragma unroll
                for (int i = 0; i < 32; i++) hreg[i] += v[i];
            }
            if (ft == 3) {
                float vv[32];
#pragma unroll
                for (int i = 0; i < 32; i++) vv[i] = hreg[i];
                float s = 0.f, s2 = 0.f;
#pragma unroll
                for (int i = 0; i < 32; i++) { s += vv[i]; s2 += vv[i] * vv[i]; }
                s  += __shfl_xor_sync(0xffffffffu, s, 1);
                s2 += __shfl_xor_sync(0xffffffffu, s2, 1);
                float m   = s * (1.f / 64.f);
                float inv = rsqrtf(s2 * (1.f / 64.f) - m * m + 1e-5f);
                if (li < 2) {
                    float o[32];
#pragma unroll
                    for (int i = 0; i < 32; i++)
                        o[i] = (vv[i] - m) * inv * ln1_g[(li+1)*DD + c0e + i]
                             + ln1_b[(li+1)*DD + c0e + i];
                    st_a32(smc + A0H_OFF, smc + A0L_OFF, er, c0e, o);
                } else {
                    float* dst = outF + er * OUT_STR + c0e;
#pragma unroll
                    for (int i = 0; i < 32; i++)
                        dst[i] = (vv[i] - m) * inv * lnf_g[c0e + i] + lnf_b[c0e + i];
                }
            }
        }
        // (kind == 0: no epilogue — q stays in outF)

        // stage n+1's W commit + stage n+2's W fetch
        commit_w(wf, smc + W_OFF(cur ^ 1), smc + W_OFF(cur ^ 1) + WLO);
        {
            int ldg; const float* p = wptr_for(st + 2, ldg, qkv_w, proj_w, ffn_w1, ffn_w2);
            wf = fetch_w(p, ldg);
        }
        __syncthreads();
    }

    // -------- head --------
    if (tid < NSEQ * TT) {
        int s = tid / TT;
        int j = tid % TT;
        const float* r = outF + (s * TT + TT - 1) * OUT_STR;
        float a = head_b[j];
#pragma unroll 16
        for (int d = 0; d < DD; d++) a = fmaf(r[d], head_w[d * 10 + j], a);
        out[(blockIdx.x * NSEQ + s) * 10 + j] = a;
    }
}

extern "C" void kernel_launch(void* const* d_in, const int* in_sizes, int n_in,
                              void* d_out, int out_size)
{
    const float* x       = (const float*)d_in[0];
    const float* embed_w = (const float*)d_in[1];
    const float* embed_b = (const float*)d_in[2];
    const float* ln1_g   = (const float*)d_in[3];
    const float* ln1_b   = (const float*)d_in[4];
    const float* qkv_w   = (const float*)d_in[5];
    const float* proj_w  = (const float*)d_in[6];
    const float* ln2_g   = (const float*)d_in[7];
    const float* ln2_b   = (const float*)d_in[8];
    const float* ffn_w1  = (const float*)d_in[9];
    const float* ffn_b1  = (const float*)d_in[10];
    const float* ffn_w2  = (const float*)d_in[11];
    const float* ffn_b2  = (const float*)d_in[12];
    const float* lnf_g   = (const float*)d_in[13];
    const float* lnf_b   = (const float*)d_in[14];
    const float* head_w  = (const float*)d_in[15];
    const float* head_b  = (const float*)d_in[16];
    float* out = (float*)d_out;

    int nTokens = in_sizes[0] / 4;       // B*T
    int grid = nTokens / MROWS;          // 1024

    cudaFuncSetAttribute(waypoint_mma_kernel,
                         cudaFuncAttributeMaxDynamicSharedMemorySize, SMEM_BYTES);

    waypoint_mma_kernel<<<grid, NTH, SMEM_BYTES>>>(
        x, embed_w, embed_b, ln1_g, ln1_b, qkv_w, proj_w,
        ln2_g, ln2_b, ffn_w1, ffn_b1, ffn_w2, ffn_b2,
        lnf_g, lnf_b, head_w, head_b, out);
}

// round 8
// speedup vs baseline: 1.4876x; 1.0767x over previous
#include <cuda_runtime.h>
#include <cuda_bf16.h>
#include <cstdint>

// ---------------- problem constants ----------------
#define TT 10
#define DD 64
#define LL 3
#define FF 256
#define NSEQ 8
#define MROWS 80
#define NTH 320

// ---------------- SMEM layout (bytes) ----------------
#define OUT_OFF 0            // fp32 [80][68]
#define OUT_STR 68
#define KF_OFF  21760        // fp32 [80][68]
#define A0H_OFF 43520        // bf16 [80][64] xor-swizzled, 128B rows
#define A0L_OFF 53760
#define A1H_OFF 64000
#define A1L_OFF 74240
#define WH_OFF  84480        // bf16 [64][64] swizzled
#define WL_OFF  92672
#define S_OFF   100864       // fp32 [8][4][10][10]
#define SMEM_BYTES 113664

// ---------------- helpers ----------------
__device__ __forceinline__ uint32_t smem_u32_of(const void* p) {
    uint32_t a;
    asm("{ .reg .u64 t; cvta.to.shared.u64 t, %1; cvt.u32.u64 %0, t; }" : "=r"(a) : "l"(p));
    return a;
}

__device__ __forceinline__ void ldm4(uint32_t& r0, uint32_t& r1, uint32_t& r2, uint32_t& r3,
                                     uint32_t a) {
    asm volatile("ldmatrix.sync.aligned.m8n8.x4.shared.b16 {%0,%1,%2,%3}, [%4];"
                 : "=r"(r0), "=r"(r1), "=r"(r2), "=r"(r3) : "r"(a));
}

__device__ __forceinline__ void mma16816(float* d,
                                         uint32_t a0, uint32_t a1, uint32_t a2, uint32_t a3,
                                         uint32_t b0, uint32_t b1) {
    asm volatile("mma.sync.aligned.m16n8k16.row.col.f32.bf16.bf16.f32 "
                 "{%0,%1,%2,%3}, {%4,%5,%6,%7}, {%8,%9}, {%0,%1,%2,%3};"
                 : "+f"(d[0]), "+f"(d[1]), "+f"(d[2]), "+f"(d[3])
                 : "r"(a0), "r"(a1), "r"(a2), "r"(a3), "r"(b0), "r"(b1));
}

__device__ __forceinline__ float gelu_fast(float v) {
    float t = fabsf(v) * 0.70710678118654752f;
    float u = __fdividef(1.0f, fmaf(0.3275911f, t, 1.0f));
    float p = fmaf(1.061405429f, u, -1.453152027f);
    p = fmaf(p, u, 1.421413741f);
    p = fmaf(p, u, -0.284496736f);
    p = fmaf(p, u, 0.254829592f);
    p *= u;
    float e = __expf(-t * t);
    float erf_abs = fmaf(-p, e, 1.0f);
    return 0.5f * v * (1.0f + copysignf(erf_abs, v));
}

// 4-lane row sum (lanes differing in bits 0..1 share a row)
__device__ __forceinline__ float hsum4(float v) {
    v += __shfl_xor_sync(0xffffffffu, v, 1);
    v += __shfl_xor_sync(0xffffffffu, v, 2);
    return v;
}

__device__ __forceinline__ void ld_row16(const float* p, float* v) {
    const float4* q = reinterpret_cast<const float4*>(p);
#pragma unroll
    for (int i = 0; i < 4; i++) {
        float4 t = q[i];
        v[4*i] = t.x; v[4*i+1] = t.y; v[4*i+2] = t.z; v[4*i+3] = t.w;
    }
}

// store 16 fp32 as bf16 hi/lo split into xor-swizzled 128B-row tile
__device__ __forceinline__ void st_a16(char* hi, char* lo, int row, int c0, const float* v) {
    const uint32_t sw = (uint32_t)(row & 7);
#pragma unroll
    for (int g = 0; g < 2; g++) {
        uint32_t ph[4], pl[4];
#pragma unroll
        for (int i = 0; i < 4; i++) {
            float x0 = v[g*8 + 2*i], x1 = v[g*8 + 2*i + 1];
            float h0 = __bfloat162float(__float2bfloat16(x0));
            float h1 = __bfloat162float(__float2bfloat16(x1));
            __nv_bfloat162 hp = __floats2bfloat162_rn(h0, h1);
            __nv_bfloat162 lp = __floats2bfloat162_rn(x0 - h0, x1 - h1);
            ph[i] = *reinterpret_cast<uint32_t*>(&hp);
            pl[i] = *reinterpret_cast<uint32_t*>(&lp);
        }
        uint32_t chunk = ((uint32_t)(c0 >> 3) + g) ^ sw;
        *reinterpret_cast<uint4*>(hi + row*128 + chunk*16) = make_uint4(ph[0], ph[1], ph[2], ph[3]);
        *reinterpret_cast<uint4*>(lo + row*128 + chunk*16) = make_uint4(pl[0], pl[1], pl[2], pl[3]);
    }
}

// ---------------- W staging (single buffer, swizzled) ----------------
struct WF { float v[16]; };

__device__ __forceinline__ WF fetch_w(const float* __restrict__ g, int ldg) {
    WF f;
    int t = threadIdx.x;
    if (t < 256) {
        int n = t & 63, kb = t >> 6;
#pragma unroll
        for (int i = 0; i < 16; i++) f.v[i] = __ldg(g + (kb * 16 + i) * ldg + n);
    }
    return f;
}

__device__ __forceinline__ void commit_w(const WF& f, char* hi, char* lo) {
    int t = threadIdx.x;
    if (t < 256) {
        int n = t & 63, kb = t >> 6;
        const uint32_t sw = (uint32_t)(n & 7);
#pragma unroll
        for (int g = 0; g < 2; g++) {
            uint32_t ph[4], pl[4];
#pragma unroll
            for (int i = 0; i < 4; i++) {
                float x0 = f.v[g*8 + 2*i], x1 = f.v[g*8 + 2*i + 1];
                float h0 = __bfloat162float(__float2bfloat16(x0));
                float h1 = __bfloat162float(__float2bfloat16(x1));
                __nv_bfloat162 hp = __floats2bfloat162_rn(h0, h1);
                __nv_bfloat162 lp = __floats2bfloat162_rn(x0 - h0, x1 - h1);
                ph[i] = *reinterpret_cast<uint32_t*>(&hp);
                pl[i] = *reinterpret_cast<uint32_t*>(&lp);
            }
            uint32_t chunk = ((uint32_t)(2*kb + g)) ^ sw;
            *reinterpret_cast<uint4*>(hi + n*128 + chunk*16) = make_uint4(ph[0], ph[1], ph[2], ph[3]);
            *reinterpret_cast<uint4*>(lo + n*128 + chunk*16) = make_uint4(pl[0], pl[1], pl[2], pl[3]);
        }
    }
}

__device__ __forceinline__ const float* wptr_for(int st, int& ldg,
    const float* qkv_w, const float* proj_w, const float* w1, const float* w2)
{
    if (st >= 36) { ldg = 192; return qkv_w; }
    int li = st / 12, k = st % 12;
    switch (k) {
        case 0:  ldg = 192; return qkv_w + li * 64 * 192;
        case 1:  ldg = 192; return qkv_w + li * 64 * 192 + 64;
        case 2:  ldg = 192; return qkv_w + li * 64 * 192 + 128;
        case 3:  ldg = 64;  return proj_w + li * 64 * 64;
        case 4: case 6: case 8: case 10: {
            int ft = (k - 4) >> 1; ldg = 256; return w1 + li * 64 * 256 + ft * 64;
        }
        default: {
            int ft = (k - 5) >> 1; ldg = 64;  return w2 + li * 256 * 64 + ft * 64 * 64;
        }
    }
}

// ---------------- MMA stage: dst[80x64] = A @ Wt, split-bf16 3 passes ----------
// warp w: m-tile mt=w>>1, cg pair hf=w&1 -> n16 groups {2hf, 2hf+1}
__device__ __forceinline__ void mma_stage(uint32_t su, uint32_t aHoff, uint32_t aLoff,
                                          float* dstF, int dstStr)
{
    const int w    = threadIdx.x >> 5;
    const int lane = threadIdx.x & 31;
    const int mt = w >> 1;
    const int hf = w & 1;
    const int rl = (lane & 7) | (((lane >> 3) & 1) << 3);
    const int klane = lane >> 4;
    const int l7 = lane & 7;

    const uint32_t aH = su + aHoff + (uint32_t)(mt*16 + rl) * 128;
    const uint32_t aL = su + aLoff + (uint32_t)(mt*16 + rl) * 128;
    const uint32_t bH = su + WH_OFF + (uint32_t)(hf*32 + rl) * 128;
    const uint32_t bL = su + WL_OFF + (uint32_t)(hf*32 + rl) * 128;

    float d[2][2][4];
#pragma unroll
    for (int c = 0; c < 2; c++)
#pragma unroll
        for (int t = 0; t < 2; t++)
#pragma unroll
            for (int j = 0; j < 4; j++) d[c][t][j] = 0.f;

#pragma unroll
    for (int ks = 0; ks < 4; ks++) {
        const uint32_t coff = (uint32_t)(((ks*2 + klane) ^ l7) << 4);
        uint32_t ah0, ah1, ah2, ah3, al0, al1, al2, al3;
        ldm4(ah0, ah1, ah2, ah3, aH + coff);
        ldm4(al0, al1, al2, al3, aL + coff);
#pragma unroll
        for (int c = 0; c < 2; c++) {
            uint32_t bh0, bh1, bh2, bh3, bl0, bl1, bl2, bl3;
            ldm4(bh0, bh1, bh2, bh3, bH + (uint32_t)c*2048 + coff);
            ldm4(bl0, bl1, bl2, bl3, bL + (uint32_t)c*2048 + coff);
            mma16816(d[c][0], ah0, ah1, ah2, ah3, bh0, bh2);
            mma16816(d[c][1], ah0, ah1, ah2, ah3, bh1, bh3);
            mma16816(d[c][0], ah0, ah1, ah2, ah3, bl0, bl2);
            mma16816(d[c][1], ah0, ah1, ah2, ah3, bl1, bl3);
            mma16816(d[c][0], al0, al1, al2, al3, bh0, bh2);
            mma16816(d[c][1], al0, al1, al2, al3, bh1, bh3);
        }
    }

    const int r0 = mt*16 + (lane >> 2);
    const int cb = (lane & 3) * 2;
#pragma unroll
    for (int c = 0; c < 2; c++) {
        int cg = hf*2 + c;
#pragma unroll
        for (int t = 0; t < 2; t++) {
            *reinterpret_cast<float2*>(dstF + r0 * dstStr + cg*16 + cb + t*8) =
                make_float2(d[c][t][0], d[c][t][1]);
            *reinterpret_cast<float2*>(dstF + (r0 + 8) * dstStr + cg*16 + cb + t*8) =
                make_float2(d[c][t][2], d[c][t][3]);
        }
    }
}

// =====================================================================
__global__ __launch_bounds__(NTH, 2)
void waypoint_mma_kernel(
    const float* __restrict__ x,
    const float* __restrict__ embed_w, const float* __restrict__ embed_b,
    const float* __restrict__ ln1_g,   const float* __restrict__ ln1_b,
    const float* __restrict__ qkv_w,   const float* __restrict__ proj_w,
    const float* __restrict__ ln2_g,   const float* __restrict__ ln2_b,
    const float* __restrict__ ffn_w1,  const float* __restrict__ ffn_b1,
    const float* __restrict__ ffn_w2,  const float* __restrict__ ffn_b2,
    const float* __restrict__ lnf_g,   const float* __restrict__ lnf_b,
    const float* __restrict__ head_w,  const float* __restrict__ head_b,
    float* __restrict__ out)
{
    extern __shared__ char smc[];
    const uint32_t su = smem_u32_of(smc);
    float* outF = reinterpret_cast<float*>(smc + OUT_OFF);
    float* kF   = reinterpret_cast<float*>(smc + KF_OFF);
    float* SB   = reinterpret_cast<float*>(smc + S_OFF);

    const int tid  = threadIdx.x;
    const int er   = tid >> 2;         // row 0..79
    const int c0e  = (tid & 3) * 16;   // 16-col slice
    const int rowBase = blockIdx.x * MROWS;

    float hreg[16];                    // residual slice (row er, cols c0e..+15)

    // -------- embed + ln1(layer0) -> A0 --------
    {
        float4 xv = reinterpret_cast<const float4*>(x)[rowBase + er];
        float v[16];
#pragma unroll
        for (int i = 0; i < 16; i++) {
            int j = c0e + i;
            float a = embed_b[j];
            a = fmaf(xv.x, embed_w[j],       a);
            a = fmaf(xv.y, embed_w[64 + j],  a);
            a = fmaf(xv.z, embed_w[128 + j], a);
            a = fmaf(xv.w, embed_w[192 + j], a);
            hreg[i] = a; v[i] = a;
        }
        float s = 0.f, s2 = 0.f;
#pragma unroll
        for (int i = 0; i < 16; i++) { s += v[i]; s2 += v[i] * v[i]; }
        s = hsum4(s); s2 = hsum4(s2);
        float m   = s * (1.f / 64.f);
        float inv = rsqrtf(s2 * (1.f / 64.f) - m * m + 1e-5f);
        float o[16];
#pragma unroll
        for (int i = 0; i < 16; i++)
            o[i] = (v[i] - m) * inv * ln1_g[c0e + i] + ln1_b[c0e + i];
        st_a16(smc + A0H_OFF, smc + A0L_OFF, er, c0e, o);
    }
    // stage-0 W
    {
        WF wf = fetch_w(qkv_w, 192);
        commit_w(wf, smc + WH_OFF, smc + WL_OFF);
    }
    __syncthreads();

    for (int st = 0; st < 36; st++) {
        const int kind = st % 12;
        const int li   = st / 12;
        const bool fromA1 = (kind == 3) || (kind >= 5 && (kind & 1));

        mma_stage(su, fromA1 ? A1H_OFF : A0H_OFF, fromA1 ? A1L_OFF : A0L_OFF,
                  (kind == 1) ? kF : outF, OUT_STR);
        __syncthreads();

        // start next-stage W fetch early (latency overlapped with epilogue)
        int ldg; const float* wp = wptr_for(st + 1, ldg, qkv_w, proj_w, ffn_w1, ffn_w2);
        WF wf = fetch_w(wp, ldg);

        // ---------------- epilogue ----------------
        if (kind == 1) {
            // S phase: one (seq, head, q) per thread
            int s   = tid / 40;
            int rem = tid % 40;
            int h   = rem / 10;
            int q   = rem % 10;
            const float4* qp = reinterpret_cast<const float4*>(outF + (s*TT + q) * OUT_STR + h * 16);
            float4 qv[4];
#pragma unroll
            for (int d = 0; d < 4; d++) qv[d] = qp[d];
            float sc[TT];
            float mx = -1e30f;
            for (int kk = 0; kk <= q; kk++) {
                const float4* kp = reinterpret_cast<const float4*>(kF + (s*TT + kk) * OUT_STR + h * 16);
                float a = 0.f;
#pragma unroll
                for (int d = 0; d < 4; d++) {
                    float4 kv = kp[d];
                    a = fmaf(qv[d].x, kv.x, a);
                    a = fmaf(qv[d].y, kv.y, a);
                    a = fmaf(qv[d].z, kv.z, a);
                    a = fmaf(qv[d].w, kv.w, a);
                }
                a *= 0.25f;
                sc[kk] = a;
                mx = fmaxf(mx, a);
            }
            float ss = 0.f;
            for (int kk = 0; kk <= q; kk++) { sc[kk] = __expf(sc[kk] - mx); ss += sc[kk]; }
            float inv = __fdividef(1.f, ss);
            float* sp = SB + ((s * 4 + h) * TT + q) * TT;
#pragma unroll
            for (int kk = 0; kk < TT; kk++) sp[kk] = (kk <= q) ? sc[kk] * inv : 0.f;
        } else if (kind == 2) {
            // y phase: row er, head h = tid&3
            int s = er / TT, q = er % TT;
            int h = tid & 3;
            const float* sp = SB + ((s * 4 + h) * TT + q) * TT;
            float y[16];
#pragma unroll
            for (int i = 0; i < 16; i++) y[i] = 0.f;
            for (int kk = 0; kk < TT; kk++) {
                float wgt = sp[kk];
                const float4* vp = reinterpret_cast<const float4*>(outF + (s*TT + kk) * OUT_STR + h * 16);
#pragma unroll
                for (int d = 0; d < 4; d++) {
                    float4 vv = vp[d];
                    y[d*4+0] = fmaf(wgt, vv.x, y[d*4+0]);
                    y[d*4+1] = fmaf(wgt, vv.y, y[d*4+1]);
                    y[d*4+2] = fmaf(wgt, vv.z, y[d*4+2]);
                    y[d*4+3] = fmaf(wgt, vv.w, y[d*4+3]);
                }
            }
            st_a16(smc + A1H_OFF, smc + A1L_OFF, er, c0e, y);
        } else if (kind == 3) {
            // proj: h += out ; ln2 -> A0
            float v[16];
            ld_row16(outF + er * OUT_STR + c0e, v);
#pragma unroll
            for (int i = 0; i < 16; i++) { v[i] += hreg[i]; hreg[i] = v[i]; }
            float s = 0.f, s2 = 0.f;
#pragma unroll
            for (int i = 0; i < 16; i++) { s += v[i]; s2 += v[i] * v[i]; }
            s = hsum4(s); s2 = hsum4(s2);
            float m   = s * (1.f / 64.f);
            float inv = rsqrtf(s2 * (1.f / 64.f) - m * m + 1e-5f);
            float o[16];
#pragma unroll
            for (int i = 0; i < 16; i++)
                o[i] = (v[i] - m) * inv * ln2_g[li*DD + c0e + i] + ln2_b[li*DD + c0e + i];
            st_a16(smc + A0H_OFF, smc + A0L_OFF, er, c0e, o);
        } else if (kind >= 4 && !(kind & 1)) {
            // ffn1 chunk: gelu(out + b1) -> A1
            int ft = (kind - 4) >> 1;
            float v[16];
            ld_row16(outF + er * OUT_STR + c0e, v);
            float o[16];
#pragma unroll
            for (int i = 0; i < 16; i++)
                o[i] = gelu_fast(v[i] + ffn_b1[li*FF + ft*64 + c0e + i]);
            st_a16(smc + A1H_OFF, smc + A1L_OFF, er, c0e, o);
        } else if (kind >= 5) {
            // ffn2 chunk: h += out (+b2 at ft0); at ft3: LN
            int ft = (kind - 5) >> 1;
            float v[16];
            ld_row16(outF + er * OUT_STR + c0e, v);
            if (ft == 0) {
#pragma unroll
                for (int i = 0; i < 16; i++)
                    hreg[i] += v[i] + ffn_b2[li*DD + c0e + i];
            } else {
#pragma unroll
                for (int i = 0; i < 16; i++) hreg[i] += v[i];
            }
            if (ft == 3) {
                float s = 0.f, s2 = 0.f;
#pragma unroll
                for (int i = 0; i < 16; i++) { s += hreg[i]; s2 += hreg[i] * hreg[i]; }
                s = hsum4(s); s2 = hsum4(s2);
                float m   = s * (1.f / 64.f);
                float inv = rsqrtf(s2 * (1.f / 64.f) - m * m + 1e-5f);
                if (li < 2) {
                    float o[16];
#pragma unroll
                    for (int i = 0; i < 16; i++)
                        o[i] = (hreg[i] - m) * inv * ln1_g[(li+1)*DD + c0e + i]
                             + ln1_b[(li+1)*DD + c0e + i];
                    st_a16(smc + A0H_OFF, smc + A0L_OFF, er, c0e, o);
                } else {
                    float* dst = outF + er * OUT_STR + c0e;
#pragma unroll
                    for (int i = 0; i < 16; i++)
                        dst[i] = (hreg[i] - m) * inv * lnf_g[c0e + i] + lnf_b[c0e + i];
                }
            }
        }
        // (kind == 0: q stays in outF, no epilogue)

        commit_w(wf, smc + WH_OFF, smc + WL_OFF);
        __syncthreads();
    }

    // -------- head --------
    if (tid < NSEQ * TT) {
        int s = tid / TT;
        int j = tid % TT;
        const float* r = outF + (s * TT + TT - 1) * OUT_STR;
        float a = head_b[j];
#pragma unroll 16
        for (int d = 0; d < DD; d++) a = fmaf(r[d], head_w[d * 10 + j], a);
        out[(blockIdx.x * NSEQ + s) * 10 + j] = a;
    }
}

extern "C" void kernel_launch(void* const* d_in, const int* in_sizes, int n_in,
                              void* d_out, int out_size)
{
    const float* x       = (const float*)d_in[0];
    const float* embed_w = (const float*)d_in[1];
    const float* embed_b = (const float*)d_in[2];
    const float* ln1_g   = (const float*)d_in[3];
    const float* ln1_b   = (const float*)d_in[4];
    const float* qkv_w   = (const float*)d_in[5];
    const float* proj_w  = (const float*)d_in[6];
    const float* ln2_g   = (const float*)d_in[7];
    const float* ln2_b   = (const float*)d_in[8];
    const float* ffn_w1  = (const float*)d_in[9];
    const float* ffn_b1  = (const float*)d_in[10];
    const float* ffn_w2  = (const float*)d_in[11];
    const float* ffn_b2  = (const float*)d_in[12];
    const float* lnf_g   = (const float*)d_in[13];
    const float* lnf_b   = (const float*)d_in[14];
    const float* head_w  = (const float*)d_in[15];
    const float* head_b  = (const float*)d_in[16];
    float* out = (float*)d_out;

    int nTokens = in_sizes[0] / 4;       // B*T
    int grid = nTokens / MROWS;          // 2048

    cudaFuncSetAttribute(waypoint_mma_kernel,
                         cudaFuncAttributeMaxDynamicSharedMemorySize, SMEM_BYTES);

    waypoint_mma_kernel<<<grid, NTH, SMEM_BYTES>>>(
        x, embed_w, embed_b, ln1_g, ln1_b, qkv_w, proj_w,
        ln2_g, ln2_b, ffn_w1, ffn_b1, ffn_w2, ffn_b2,
        lnf_g, lnf_b, head_w, head_b, out);
}

// round 9
// speedup vs baseline: 1.6626x; 1.1177x over previous
#include <cuda_runtime.h>
#include <cuda_bf16.h>
#include <cstdint>

// ---------------- problem constants ----------------
#define TT 10
#define DD 64
#define LL 3
#define FF 256
#define NSEQ 8
#define MROWS 80
#define NTH 320

// ---------------- SMEM layout (bytes) ----------------
#define OUT_OFF 0        // fp32 [80][68]
#define OUT_STR 68
#define A0H_OFF 21760    // bf16 [80][64] xor-swizzled, 128B rows
#define A0L_OFF 32000
#define KF_OFF  42240    // fp32 [80][68]  (aliases A1 tiles; never live together)
#define A1H_OFF 42240
#define A1L_OFF 52480
#define W0H_OFF 64000    // W double buffer, lo always at +8192
#define W1H_OFF 80384
#define S_OFF   96768    // fp32 [8][4][10][10]
#define RED_OFF 109568   // float2 [80][2]
#define SMEM_BYTES 110848

// ---------------- helpers ----------------
__device__ __forceinline__ uint32_t smem_u32_of(const void* p) {
    uint32_t a;
    asm("{ .reg .u64 t; cvta.to.shared.u64 t, %1; cvt.u32.u64 %0, t; }" : "=r"(a) : "l"(p));
    return a;
}

__device__ __forceinline__ void ldm4(uint32_t& r0, uint32_t& r1, uint32_t& r2, uint32_t& r3,
                                     uint32_t a) {
    asm volatile("ldmatrix.sync.aligned.m8n8.x4.shared.b16 {%0,%1,%2,%3}, [%4];"
                 : "=r"(r0), "=r"(r1), "=r"(r2), "=r"(r3) : "r"(a));
}

__device__ __forceinline__ void mma16816(float* d,
                                         uint32_t a0, uint32_t a1, uint32_t a2, uint32_t a3,
                                         uint32_t b0, uint32_t b1) {
    asm volatile("mma.sync.aligned.m16n8k16.row.col.f32.bf16.bf16.f32 "
                 "{%0,%1,%2,%3}, {%4,%5,%6,%7}, {%8,%9}, {%0,%1,%2,%3};"
                 : "+f"(d[0]), "+f"(d[1]), "+f"(d[2]), "+f"(d[3])
                 : "r"(a0), "r"(a1), "r"(a2), "r"(a3), "r"(b0), "r"(b1));
}

__device__ __forceinline__ float gelu_fast(float v) {
    float t = fabsf(v) * 0.70710678118654752f;
    float u = __fdividef(1.0f, fmaf(0.3275911f, t, 1.0f));
    float p = fmaf(1.061405429f, u, -1.453152027f);
    p = fmaf(p, u, 1.421413741f);
    p = fmaf(p, u, -0.284496736f);
    p = fmaf(p, u, 0.254829592f);
    p *= u;
    float e = __expf(-t * t);
    float erf_abs = fmaf(-p, e, 1.0f);
    return 0.5f * v * (1.0f + copysignf(erf_abs, v));
}

// sum over the 4 lanes sharing a fragment row (lane bits 0..1)
__device__ __forceinline__ float sum4(float v) {
    v += __shfl_xor_sync(0xffffffffu, v, 1);
    v += __shfl_xor_sync(0xffffffffu, v, 2);
    return v;
}

__device__ __forceinline__ void pack_split(float x0, float x1, uint32_t& hw, uint32_t& lw) {
    float h0 = __bfloat162float(__float2bfloat16(x0));
    float h1 = __bfloat162float(__float2bfloat16(x1));
    __nv_bfloat162 hp = __floats2bfloat162_rn(h0, h1);
    __nv_bfloat162 lp = __floats2bfloat162_rn(x0 - h0, x1 - h1);
    hw = *reinterpret_cast<uint32_t*>(&hp);
    lw = *reinterpret_cast<uint32_t*>(&lp);
}

// fragment store of an adjacent column pair into a swizzled bf16 tile
__device__ __forceinline__ void fst(char* hi, char* lo, int row, int col2, float x0, float x1) {
    uint32_t off = (uint32_t)row * 128
                 + ((((uint32_t)col2 >> 3) ^ ((uint32_t)row & 7)) << 4)
                 + (((uint32_t)(col2 & 7)) << 1);
    uint32_t hw, lw;
    pack_split(x0, x1, hw, lw);
    *reinterpret_cast<uint32_t*>(hi + off) = hw;
    *reinterpret_cast<uint32_t*>(lo + off) = lw;
}

// row-major 16-value store (er-layout) used by the attention y-phase
__device__ __forceinline__ void st_a16(char* hi, char* lo, int row, int c0, const float* v) {
    const uint32_t sw = (uint32_t)(row & 7);
#pragma unroll
    for (int g = 0; g < 2; g++) {
        uint32_t ph[4], pl[4];
#pragma unroll
        for (int i = 0; i < 4; i++)
            pack_split(v[g*8 + 2*i], v[g*8 + 2*i + 1], ph[i], pl[i]);
        uint32_t chunk = ((uint32_t)(c0 >> 3) + g) ^ sw;
        *reinterpret_cast<uint4*>(hi + row*128 + chunk*16) = make_uint4(ph[0], ph[1], ph[2], ph[3]);
        *reinterpret_cast<uint4*>(lo + row*128 + chunk*16) = make_uint4(pl[0], pl[1], pl[2], pl[3]);
    }
}

// ---------------- W staging ----------------
struct WF { float v[16]; };

__device__ __forceinline__ WF fetch_w(const float* __restrict__ g, int ldg) {
    WF f;
    int t = threadIdx.x;
    if (t < 256) {
        int n = t & 63, kb = t >> 6;
#pragma unroll
        for (int i = 0; i < 16; i++) f.v[i] = __ldg(g + (kb * 16 + i) * ldg + n);
    }
    return f;
}

__device__ __forceinline__ void commit_w(const WF& f, char* hi, char* lo) {
    int t = threadIdx.x;
    if (t < 256) {
        int n = t & 63, kb = t >> 6;
        const uint32_t sw = (uint32_t)(n & 7);
#pragma unroll
        for (int g = 0; g < 2; g++) {
            uint32_t ph[4], pl[4];
#pragma unroll
            for (int i = 0; i < 4; i++)
                pack_split(f.v[g*8 + 2*i], f.v[g*8 + 2*i + 1], ph[i], pl[i]);
            uint32_t chunk = ((uint32_t)(2*kb + g)) ^ sw;
            *reinterpret_cast<uint4*>(hi + n*128 + chunk*16) = make_uint4(ph[0], ph[1], ph[2], ph[3]);
            *reinterpret_cast<uint4*>(lo + n*128 + chunk*16) = make_uint4(pl[0], pl[1], pl[2], pl[3]);
        }
    }
}

__device__ __forceinline__ const float* wptr_for(int st, int& ldg,
    const float* qkv_w, const float* proj_w, const float* w1, const float* w2)
{
    if (st >= 36) { ldg = 192; return qkv_w; }
    int li = st / 12, k = st % 12;
    switch (k) {
        case 0:  ldg = 192; return qkv_w + li * 64 * 192;
        case 1:  ldg = 192; return qkv_w + li * 64 * 192 + 64;
        case 2:  ldg = 192; return qkv_w + li * 64 * 192 + 128;
        case 3:  ldg = 64;  return proj_w + li * 64 * 64;
        case 4: case 6: case 8: case 10: {
            int ft = (k - 4) >> 1; ldg = 256; return w1 + li * 64 * 256 + ft * 64;
        }
        default: {
            int ft = (k - 5) >> 1; ldg = 64;  return w2 + li * 256 * 64 + ft * 64 * 64;
        }
    }
}

// ---------------- MMA mainloop: d[2][2][4] = A @ W, split-bf16 3 passes ----------
__device__ __forceinline__ void mma_compute(uint32_t su, uint32_t aHoff, uint32_t aLoff,
                                            uint32_t wHoff, float d[2][2][4])
{
    const int w    = threadIdx.x >> 5;
    const int lane = threadIdx.x & 31;
    const int mt = w >> 1;
    const int hf = w & 1;
    const int rl = (lane & 7) | (((lane >> 3) & 1) << 3);
    const int klane = lane >> 4;
    const int l7 = lane & 7;

    const uint32_t aH = su + aHoff + (uint32_t)(mt*16 + rl) * 128;
    const uint32_t aL = su + aLoff + (uint32_t)(mt*16 + rl) * 128;
    const uint32_t bH = su + wHoff + (uint32_t)(hf*32 + rl) * 128;
    const uint32_t bL = bH + 8192;

#pragma unroll
    for (int c = 0; c < 2; c++)
#pragma unroll
        for (int t = 0; t < 2; t++)
#pragma unroll
            for (int j = 0; j < 4; j++) d[c][t][j] = 0.f;

#pragma unroll
    for (int ks = 0; ks < 4; ks++) {
        const uint32_t coff = (uint32_t)(((ks*2 + klane) ^ l7) << 4);
        uint32_t ah0, ah1, ah2, ah3, al0, al1, al2, al3;
        ldm4(ah0, ah1, ah2, ah3, aH + coff);
        ldm4(al0, al1, al2, al3, aL + coff);
#pragma unroll
        for (int c = 0; c < 2; c++) {
            uint32_t bh0, bh1, bh2, bh3, bl0, bl1, bl2, bl3;
            ldm4(bh0, bh1, bh2, bh3, bH + (uint32_t)c*2048 + coff);
            ldm4(bl0, bl1, bl2, bl3, bL + (uint32_t)c*2048 + coff);
            mma16816(d[c][0], ah0, ah1, ah2, ah3, bh0, bh2);
            mma16816(d[c][1], ah0, ah1, ah2, ah3, bh1, bh3);
            mma16816(d[c][0], ah0, ah1, ah2, ah3, bl0, bl2);
            mma16816(d[c][1], ah0, ah1, ah2, ah3, bl1, bl3);
            mma16816(d[c][0], al0, al1, al2, al3, bh0, bh2);
            mma16816(d[c][1], al0, al1, al2, al3, bh1, bh3);
        }
    }
}

// fragment -> row-major fp32 (for q/k/v stages)
__device__ __forceinline__ void frag_to_f32(const float d[2][2][4], float* dstF) {
    const int w    = threadIdx.x >> 5;
    const int lane = threadIdx.x & 31;
    const int mt = w >> 1, hf = w & 1;
    const int r0 = mt*16 + (lane >> 2);
    const int cb = (lane & 3) * 2;
#pragma unroll
    for (int c = 0; c < 2; c++) {
        int cg = hf*2 + c;
#pragma unroll
        for (int t = 0; t < 2; t++) {
            *reinterpret_cast<float2*>(dstF + r0 * OUT_STR + cg*16 + cb + t*8) =
                make_float2(d[c][t][0], d[c][t][1]);
            *reinterpret_cast<float2*>(dstF + (r0 + 8) * OUT_STR + cg*16 + cb + t*8) =
                make_float2(d[c][t][2], d[c][t][3]);
        }
    }
}

// fragment LayerNorm stats: v[2][8] (2 rows x 8 cols), cross-warp-pair via named barrier
__device__ __forceinline__ void frag_ln(const float v[2][8], int rA, int hf, int mt, int lane,
                                        float2* red2, float m[2], float iv[2])
{
    float s0 = 0.f, q0 = 0.f, s1 = 0.f, q1 = 0.f;
#pragma unroll
    for (int j = 0; j < 8; j++) {
        s0 += v[0][j]; q0 += v[0][j]*v[0][j];
        s1 += v[1][j]; q1 += v[1][j]*v[1][j];
    }
    s0 = sum4(s0); q0 = sum4(q0); s1 = sum4(s1); q1 = sum4(q1);
    if ((lane & 3) == 0) {
        red2[rA*2 + hf]       = make_float2(s0, q0);
        red2[(rA+8)*2 + hf]   = make_float2(s1, q1);
    }
    asm volatile("bar.sync %0, %1;" :: "r"(mt + 1), "r"(64) : "memory");
    float2 o0 = red2[rA*2 + (hf^1)];
    float2 o1 = red2[(rA+8)*2 + (hf^1)];
    float S0 = s0 + o0.x, Q0 = q0 + o0.y;
    float S1 = s1 + o1.x, Q1 = q1 + o1.y;
    m[0] = S0 * (1.f/64.f);
    iv[0] = rsqrtf(Q0 * (1.f/64.f) - m[0]*m[0] + 1e-5f);
    m[1] = S1 * (1.f/64.f);
    iv[1] = rsqrtf(Q1 * (1.f/64.f) - m[1]*m[1] + 1e-5f);
}

// =====================================================================
__global__ __launch_bounds__(NTH, 2)
void waypoint_mma_kernel(
    const float* __restrict__ x,
    const float* __restrict__ embed_w, const float* __restrict__ embed_b,
    const float* __restrict__ ln1_g,   const float* __restrict__ ln1_b,
    const float* __restrict__ qkv_w,   const float* __restrict__ proj_w,
    const float* __restrict__ ln2_g,   const float* __restrict__ ln2_b,
    const float* __restrict__ ffn_w1,  const float* __restrict__ ffn_b1,
    const float* __restrict__ ffn_w2,  const float* __restrict__ ffn_b2,
    const float* __restrict__ lnf_g,   const float* __restrict__ lnf_b,
    const float* __restrict__ head_w,  const float* __restrict__ head_b,
    float* __restrict__ out)
{
    extern __shared__ char smc[];
    const uint32_t su = smem_u32_of(smc);
    float*  outF = reinterpret_cast<float*>(smc + OUT_OFF);
    float*  kF   = reinterpret_cast<float*>(smc + KF_OFF);
    float*  SB   = reinterpret_cast<float*>(smc + S_OFF);
    float2* red2 = reinterpret_cast<float2*>(smc + RED_OFF);

    const int tid  = threadIdx.x;
    const int w    = tid >> 5;
    const int lane = tid & 31;
    const int mt   = w >> 1;
    const int hf   = w & 1;
    const int rA   = mt*16 + (lane >> 2);
    const int cb   = (lane & 3) * 2;
    const int rowBase = blockIdx.x * MROWS;

    // fragment column for index j = c*4 + t*2 + e
    int colv[8];
#pragma unroll
    for (int j = 0; j < 8; j++)
        colv[j] = hf*32 + (j>>2)*16 + ((j>>1)&1)*8 + cb + (j&1);

    float hreg[2][8];   // residual stream in MMA-fragment layout

    // -------- embed + ln1(layer0) -> A0, fragment layout --------
    {
        float v[2][8];
#pragma unroll
        for (int r = 0; r < 2; r++) {
            int row = rA + 8*r;
            float4 xv = reinterpret_cast<const float4*>(x)[rowBase + row];
#pragma unroll
            for (int j = 0; j < 8; j++) {
                int col = colv[j];
                float a = embed_b[col];
                a = fmaf(xv.x, embed_w[col],       a);
                a = fmaf(xv.y, embed_w[64 + col],  a);
                a = fmaf(xv.z, embed_w[128 + col], a);
                a = fmaf(xv.w, embed_w[192 + col], a);
                v[r][j] = a; hreg[r][j] = a;
            }
        }
        // LN stats with full barrier (pre-loop)
        float s0=0,q0=0,s1=0,q1=0;
#pragma unroll
        for (int j = 0; j < 8; j++) {
            s0 += v[0][j]; q0 += v[0][j]*v[0][j];
            s1 += v[1][j]; q1 += v[1][j]*v[1][j];
        }
        s0=sum4(s0); q0=sum4(q0); s1=sum4(s1); q1=sum4(q1);
        if ((lane & 3) == 0) {
            red2[rA*2 + hf]     = make_float2(s0, q0);
            red2[(rA+8)*2 + hf] = make_float2(s1, q1);
        }
        __syncthreads();
        float2 o0 = red2[rA*2 + (hf^1)];
        float2 o1 = red2[(rA+8)*2 + (hf^1)];
        float m0 = (s0+o0.x)*(1.f/64.f), i0 = rsqrtf((q0+o0.y)*(1.f/64.f)-m0*m0+1e-5f);
        float m1 = (s1+o1.x)*(1.f/64.f), i1 = rsqrtf((q1+o1.y)*(1.f/64.f)-m1*m1+1e-5f);
#pragma unroll
        for (int j = 0; j < 8; j += 2) {
            int col2 = colv[j];
            fst(smc+A0H_OFF, smc+A0L_OFF, rA,
                col2, (v[0][j]-m0)*i0*ln1_g[col2]+ln1_b[col2],
                      (v[0][j+1]-m0)*i0*ln1_g[col2+1]+ln1_b[col2+1]);
            fst(smc+A0H_OFF, smc+A0L_OFF, rA+8,
                col2, (v[1][j]-m1)*i1*ln1_g[col2]+ln1_b[col2],
                      (v[1][j+1]-m1)*i1*ln1_g[col2+1]+ln1_b[col2+1]);
        }
    }
    // stage-0 W into buffer 0
    {
        WF wf0 = fetch_w(qkv_w, 192);
        commit_w(wf0, smc + W0H_OFF, smc + W0H_OFF + 8192);
    }
    __syncthreads();

    for (int st = 0; st < 36; st++) {
        const int kind = st % 12;
        const int li   = st / 12;
        const bool fromA1 = (kind == 3) || (kind >= 5 && (kind & 1));
        const uint32_t wB = (st & 1) ? W1H_OFF : W0H_OFF;

        float d[2][2][4];
        mma_compute(su, fromA1 ? A1H_OFF : A0H_OFF, fromA1 ? A1L_OFF : A0L_OFF, wB, d);

        if (kind == 0 || kind == 2) frag_to_f32(d, outF);
        else if (kind == 1)         frag_to_f32(d, kF);
        if (kind == 1 || kind == 2) __syncthreads();

        int ldg; const float* wp = wptr_for(st + 1, ldg, qkv_w, proj_w, ffn_w1, ffn_w2);
        WF wf = fetch_w(wp, ldg);

        // ---------------- epilogue ----------------
        if (kind == 1) {
            // S phase: one (seq, head, q) per thread
            int s   = tid / 40;
            int rem = tid % 40;
            int h   = rem / 10;
            int q   = rem % 10;
            const float4* qp = reinterpret_cast<const float4*>(outF + (s*TT + q) * OUT_STR + h * 16);
            float4 qv[4];
#pragma unroll
            for (int dd = 0; dd < 4; dd++) qv[dd] = qp[dd];
            float sc[TT];
            float mx = -1e30f;
            for (int kk = 0; kk <= q; kk++) {
                const float4* kp = reinterpret_cast<const float4*>(kF + (s*TT + kk) * OUT_STR + h * 16);
                float a = 0.f;
#pragma unroll
                for (int dd = 0; dd < 4; dd++) {
                    float4 kv = kp[dd];
                    a = fmaf(qv[dd].x, kv.x, a);
                    a = fmaf(qv[dd].y, kv.y, a);
                    a = fmaf(qv[dd].z, kv.z, a);
                    a = fmaf(qv[dd].w, kv.w, a);
                }
                a *= 0.25f;
                sc[kk] = a;
                mx = fmaxf(mx, a);
            }
            float ss = 0.f;
            for (int kk = 0; kk <= q; kk++) { sc[kk] = __expf(sc[kk] - mx); ss += sc[kk]; }
            float inv = __fdividef(1.f, ss);
            float* sp = SB + ((s * 4 + h) * TT + q) * TT;
#pragma unroll
            for (int kk = 0; kk < TT; kk++) sp[kk] = (kk <= q) ? sc[kk] * inv : 0.f;
        } else if (kind == 2) {
            // y phase (er layout): row er=tid>>2, head h=tid&3 -> A1 tiles
            int er = tid >> 2;
            int s = er / TT, q = er % TT;
            int h = tid & 3;
            const float* sp = SB + ((s * 4 + h) * TT + q) * TT;
            float y[16];
#pragma unroll
            for (int i = 0; i < 16; i++) y[i] = 0.f;
            for (int kk = 0; kk < TT; kk++) {
                float wgt = sp[kk];
                const float4* vp = reinterpret_cast<const float4*>(outF + (s*TT + kk) * OUT_STR + h * 16);
#pragma unroll
                for (int dd = 0; dd < 4; dd++) {
                    float4 vv = vp[dd];
                    y[dd*4+0] = fmaf(wgt, vv.x, y[dd*4+0]);
                    y[dd*4+1] = fmaf(wgt, vv.y, y[dd*4+1]);
                    y[dd*4+2] = fmaf(wgt, vv.z, y[dd*4+2]);
                    y[dd*4+3] = fmaf(wgt, vv.w, y[dd*4+3]);
                }
            }
            st_a16(smc + A1H_OFF, smc + A1L_OFF, er, h * 16, y);
        } else if (kind == 3) {
            // proj: h += d ; ln2 -> A0   (fragment-resident)
            float v[2][8];
#pragma unroll
            for (int j = 0; j < 8; j++) {
                int c = j>>2, t = (j>>1)&1, e = j&1;
                v[0][j] = d[c][t][e]   + hreg[0][j]; hreg[0][j] = v[0][j];
                v[1][j] = d[c][t][2+e] + hreg[1][j]; hreg[1][j] = v[1][j];
            }
            float m[2], iv[2];
            frag_ln(v, rA, hf, mt, lane, red2, m, iv);
            const float* g = ln2_g + li*DD;
            const float* b = ln2_b + li*DD;
#pragma unroll
            for (int j = 0; j < 8; j += 2) {
                int col2 = colv[j];
                fst(smc+A0H_OFF, smc+A0L_OFF, rA, col2,
                    (v[0][j]-m[0])*iv[0]*g[col2]+b[col2],
                    (v[0][j+1]-m[0])*iv[0]*g[col2+1]+b[col2+1]);
                fst(smc+A0H_OFF, smc+A0L_OFF, rA+8, col2,
                    (v[1][j]-m[1])*iv[1]*g[col2]+b[col2],
                    (v[1][j+1]-m[1])*iv[1]*g[col2+1]+b[col2+1]);
            }
        } else if (kind >= 4 && !(kind & 1)) {
            // ffn1 chunk: gelu(d + b1) -> A1   (fragment-resident)
            int ft = (kind - 4) >> 1;
            const float* b1 = ffn_b1 + li*FF + ft*64;
#pragma unroll
            for (int j = 0; j < 8; j += 2) {
                int c = j>>2, t = (j>>1)&1;
                int col2 = colv[j];
                fst(smc+A1H_OFF, smc+A1L_OFF, rA, col2,
                    gelu_fast(d[c][t][0] + b1[col2]),
                    gelu_fast(d[c][t][1] + b1[col2+1]));
                fst(smc+A1H_OFF, smc+A1L_OFF, rA+8, col2,
                    gelu_fast(d[c][t][2] + b1[col2]),
                    gelu_fast(d[c][t][3] + b1[col2+1]));
            }
        } else if (kind >= 5) {
            // ffn2 chunk: h += d (+b2 at ft0); at ft3: LN
            int ft = (kind - 5) >> 1;
#pragma unroll
            for (int j = 0; j < 8; j++) {
                int c = j>>2, t = (j>>1)&1, e = j&1;
                float add0 = d[c][t][e], add1 = d[c][t][2+e];
                if (ft == 0) {
                    float bb = ffn_b2[li*DD + colv[j]];
                    add0 += bb; add1 += bb;
                }
                hreg[0][j] += add0;
                hreg[1][j] += add1;
            }
            if (ft == 3) {
                float m[2], iv[2];
                frag_ln(hreg, rA, hf, mt, lane, red2, m, iv);
                if (li < 2) {
                    const float* g = ln1_g + (li+1)*DD;
                    const float* b = ln1_b + (li+1)*DD;
#pragma unroll
                    for (int j = 0; j < 8; j += 2) {
                        int col2 = colv[j];
                        fst(smc+A0H_OFF, smc+A0L_OFF, rA, col2,
                            (hreg[0][j]-m[0])*iv[0]*g[col2]+b[col2],
                            (hreg[0][j+1]-m[0])*iv[0]*g[col2+1]+b[col2+1]);
                        fst(smc+A0H_OFF, smc+A0L_OFF, rA+8, col2,
                            (hreg[1][j]-m[1])*iv[1]*g[col2]+b[col2],
                            (hreg[1][j+1]-m[1])*iv[1]*g[col2+1]+b[col2+1]);
                    }
                } else {
#pragma unroll
                    for (int j = 0; j < 8; j += 2) {
                        int col2 = colv[j];
                        *reinterpret_cast<float2*>(outF + rA*OUT_STR + col2) =
                            make_float2((hreg[0][j]-m[0])*iv[0]*lnf_g[col2]+lnf_b[col2],
                                        (hreg[0][j+1]-m[0])*iv[0]*lnf_g[col2+1]+lnf_b[col2+1]);
                        *reinterpret_cast<float2*>(outF + (rA+8)*OUT_STR + col2) =
                            make_float2((hreg[1][j]-m[1])*iv[1]*lnf_g[col2]+lnf_b[col2],
                                        (hreg[1][j+1]-m[1])*iv[1]*lnf_g[col2+1]+lnf_b[col2+1]);
                    }
                }
            }
        }
        // (kind == 0: q stays in outF, no epilogue)

        commit_w(wf, smc + ((st+1)&1 ? W1H_OFF : W0H_OFF),
                     smc + ((st+1)&1 ? W1H_OFF : W0H_OFF) + 8192);
        __syncthreads();
    }

    // -------- head --------
    if (tid < NSEQ * TT) {
        int s = tid / TT;
        int j = tid % TT;
        const float* r = outF + (s * TT + TT - 1) * OUT_STR;
        float a = head_b[j];
#pragma unroll 16
        for (int dd = 0; dd < DD; dd++) a = fmaf(r[dd], head_w[dd * 10 + j], a);
        out[(blockIdx.x * NSEQ + s) * 10 + j] = a;
    }
}

extern "C" void kernel_launch(void* const* d_in, const int* in_sizes, int n_in,
                              void* d_out, int out_size)
{
    const float* x       = (const float*)d_in[0];
    const float* embed_w = (const float*)d_in[1];
    const float* embed_b = (const float*)d_in[2];
    const float* ln1_g   = (const float*)d_in[3];
    const float* ln1_b   = (const float*)d_in[4];
    const float* qkv_w   = (const float*)d_in[5];
    const float* proj_w  = (const float*)d_in[6];
    const float* ln2_g   = (const float*)d_in[7];
    const float* ln2_b   = (const float*)d_in[8];
    const float* ffn_w1  = (const float*)d_in[9];
    const float* ffn_b1  = (const float*)d_in[10];
    const float* ffn_w2  = (const float*)d_in[11];
    const float* ffn_b2  = (const float*)d_in[12];
    const float* lnf_g   = (const float*)d_in[13];
    const float* lnf_b   = (const float*)d_in[14];
    const float* head_w  = (const float*)d_in[15];
    const float* head_b  = (const float*)d_in[16];
    float* out = (float*)d_out;

    int nTokens = in_sizes[0] / 4;       // B*T
    int grid = nTokens / MROWS;          // 2048

    cudaFuncSetAttribute(waypoint_mma_kernel,
                         cudaFuncAttributeMaxDynamicSharedMemorySize, SMEM_BYTES);

    waypoint_mma_kernel<<<grid, NTH, SMEM_BYTES>>>(
        x, embed_w, embed_b, ln1_g, ln1_b, qkv_w, proj_w,
        ln2_g, ln2_b, ffn_w1, ffn_b1, ffn_w2, ffn_b2,
        lnf_g, lnf_b, head_w, head_b, out);
}

// round 10
// speedup vs baseline: 1.8757x; 1.1282x over previous
#include <cuda_runtime.h>
#include <cuda_bf16.h>
#include <cstdint>

// ---------------- problem constants ----------------
#define TT 10
#define DD 64
#define LL 3
#define FF 256
#define NSEQ 8
#define MROWS 80
#define NTH 320

// ---------------- SMEM layout (bytes) ----------------
#define OUT_OFF 0        // fp32 [80][68]
#define OUT_STR 68
#define A0H_OFF 21760    // bf16 [80][64] xor-swizzled, 128B rows
#define A0L_OFF 32000
#define KF_OFF  42240    // fp32 [80][68]  (aliases A1 tiles; never live together)
#define A1H_OFF 42240
#define A1L_OFF 52480
#define W0_OFF  64000    // W double buffer: hi at +0, lo at +8192
#define W1_OFF  80384
#define S_OFF   96768    // fp32 [8][4][10][10]
#define RED_OFF 109568   // float2 [80][2]
#define SMEM_BYTES 110848

// Pre-split swizzled weight tiles: 36 stages x (8192 hi + 8192 lo)
__device__ unsigned char g_wtiles[36 * 16384];

// ---------------- helpers ----------------
__device__ __forceinline__ uint32_t smem_u32_of(const void* p) {
    uint32_t a;
    asm("{ .reg .u64 t; cvta.to.shared.u64 t, %1; cvt.u32.u64 %0, t; }" : "=r"(a) : "l"(p));
    return a;
}

__device__ __forceinline__ void ldm4(uint32_t& r0, uint32_t& r1, uint32_t& r2, uint32_t& r3,
                                     uint32_t a) {
    asm volatile("ldmatrix.sync.aligned.m8n8.x4.shared.b16 {%0,%1,%2,%3}, [%4];"
                 : "=r"(r0), "=r"(r1), "=r"(r2), "=r"(r3) : "r"(a));
}

__device__ __forceinline__ void mma16816(float* d,
                                         uint32_t a0, uint32_t a1, uint32_t a2, uint32_t a3,
                                         uint32_t b0, uint32_t b1) {
    asm volatile("mma.sync.aligned.m16n8k16.row.col.f32.bf16.bf16.f32 "
                 "{%0,%1,%2,%3}, {%4,%5,%6,%7}, {%8,%9}, {%0,%1,%2,%3};"
                 : "+f"(d[0]), "+f"(d[1]), "+f"(d[2]), "+f"(d[3])
                 : "r"(a0), "r"(a1), "r"(a2), "r"(a3), "r"(b0), "r"(b1));
}

__device__ __forceinline__ void cp16(uint32_t dst, const void* src) {
    asm volatile("cp.async.cg.shared.global [%0], [%1], 16;" :: "r"(dst), "l"(src));
}
__device__ __forceinline__ void cp_commit() {
    asm volatile("cp.async.commit_group;" ::: "memory");
}
__device__ __forceinline__ void cp_wait0() {
    asm volatile("cp.async.wait_group 0;" ::: "memory");
}

__device__ __forceinline__ float gelu_fast(float v) {
    float t = fabsf(v) * 0.70710678118654752f;
    float u = __fdividef(1.0f, fmaf(0.3275911f, t, 1.0f));
    float p = fmaf(1.061405429f, u, -1.453152027f);
    p = fmaf(p, u, 1.421413741f);
    p = fmaf(p, u, -0.284496736f);
    p = fmaf(p, u, 0.254829592f);
    p *= u;
    float e = __expf(-t * t);
    float erf_abs = fmaf(-p, e, 1.0f);
    return 0.5f * v * (1.0f + copysignf(erf_abs, v));
}

__device__ __forceinline__ float sum4(float v) {
    v += __shfl_xor_sync(0xffffffffu, v, 1);
    v += __shfl_xor_sync(0xffffffffu, v, 2);
    return v;
}

__device__ __forceinline__ void pack_split(float x0, float x1, uint32_t& hw, uint32_t& lw) {
    float h0 = __bfloat162float(__float2bfloat16(x0));
    float h1 = __bfloat162float(__float2bfloat16(x1));
    __nv_bfloat162 hp = __floats2bfloat162_rn(h0, h1);
    __nv_bfloat162 lp = __floats2bfloat162_rn(x0 - h0, x1 - h1);
    hw = *reinterpret_cast<uint32_t*>(&hp);
    lw = *reinterpret_cast<uint32_t*>(&lp);
}

__device__ __forceinline__ void fst(char* hi, char* lo, int row, int col2, float x0, float x1) {
    uint32_t off = (uint32_t)row * 128
                 + ((((uint32_t)col2 >> 3) ^ ((uint32_t)row & 7)) << 4)
                 + (((uint32_t)(col2 & 7)) << 1);
    uint32_t hw, lw;
    pack_split(x0, x1, hw, lw);
    *reinterpret_cast<uint32_t*>(hi + off) = hw;
    *reinterpret_cast<uint32_t*>(lo + off) = lw;
}

__device__ __forceinline__ void st_a16(char* hi, char* lo, int row, int c0, const float* v) {
    const uint32_t sw = (uint32_t)(row & 7);
#pragma unroll
    for (int g = 0; g < 2; g++) {
        uint32_t ph[4], pl[4];
#pragma unroll
        for (int i = 0; i < 4; i++)
            pack_split(v[g*8 + 2*i], v[g*8 + 2*i + 1], ph[i], pl[i]);
        uint32_t chunk = ((uint32_t)(c0 >> 3) + g) ^ sw;
        *reinterpret_cast<uint4*>(hi + row*128 + chunk*16) = make_uint4(ph[0], ph[1], ph[2], ph[3]);
        *reinterpret_cast<uint4*>(lo + row*128 + chunk*16) = make_uint4(pl[0], pl[1], pl[2], pl[3]);
    }
}

__device__ __forceinline__ const float* wptr_for(int st, int& ldg,
    const float* qkv_w, const float* proj_w, const float* w1, const float* w2)
{
    int li = st / 12, k = st % 12;
    switch (k) {
        case 0:  ldg = 192; return qkv_w + li * 64 * 192;
        case 1:  ldg = 192; return qkv_w + li * 64 * 192 + 64;
        case 2:  ldg = 192; return qkv_w + li * 64 * 192 + 128;
        case 3:  ldg = 64;  return proj_w + li * 64 * 64;
        case 4: case 6: case 8: case 10: {
            int ft = (k - 4) >> 1; ldg = 256; return w1 + li * 64 * 256 + ft * 64;
        }
        default: {
            int ft = (k - 5) >> 1; ldg = 64;  return w2 + li * 256 * 64 + ft * 64 * 64;
        }
    }
}

// ---------------- prologue: split+swizzle all weight tiles once ----------------
__global__ void prep_wtiles(const float* __restrict__ qkv_w, const float* __restrict__ proj_w,
                            const float* __restrict__ ffn_w1, const float* __restrict__ ffn_w2)
{
    int st = blockIdx.x;
    int ldg;
    const float* g = wptr_for(st, ldg, qkv_w, proj_w, ffn_w1, ffn_w2);
    unsigned char* hi = g_wtiles + st * 16384;
    unsigned char* lo = hi + 8192;

    int t = threadIdx.x;          // 256 threads
    int n = t & 63, kb = t >> 6;
    const uint32_t sw = (uint32_t)(n & 7);
#pragma unroll
    for (int gg = 0; gg < 2; gg++) {
        uint32_t ph[4], pl[4];
#pragma unroll
        for (int i = 0; i < 4; i++) {
            int k0 = kb * 16 + gg * 8 + 2 * i;
            float x0 = g[k0 * ldg + n];
            float x1 = g[(k0 + 1) * ldg + n];
            pack_split(x0, x1, ph[i], pl[i]);
        }
        uint32_t chunk = ((uint32_t)(2*kb + gg)) ^ sw;
        *reinterpret_cast<uint4*>(hi + n*128 + chunk*16) = make_uint4(ph[0], ph[1], ph[2], ph[3]);
        *reinterpret_cast<uint4*>(lo + n*128 + chunk*16) = make_uint4(pl[0], pl[1], pl[2], pl[3]);
    }
}

// ---------------- MMA mainloop ----------------
__device__ __forceinline__ void mma_compute(uint32_t su, uint32_t aHoff, uint32_t aLoff,
                                            uint32_t wHoff, float d[2][2][4])
{
    const int w    = threadIdx.x >> 5;
    const int lane = threadIdx.x & 31;
    const int mt = w >> 1;
    const int hf = w & 1;
    const int rl = (lane & 7) | (((lane >> 3) & 1) << 3);
    const int klane = lane >> 4;
    const int l7 = lane & 7;

    const uint32_t aH = su + aHoff + (uint32_t)(mt*16 + rl) * 128;
    const uint32_t aL = su + aLoff + (uint32_t)(mt*16 + rl) * 128;
    const uint32_t bH = su + wHoff + (uint32_t)(hf*32 + rl) * 128;
    const uint32_t bL = bH + 8192;

#pragma unroll
    for (int c = 0; c < 2; c++)
#pragma unroll
        for (int t = 0; t < 2; t++)
#pragma unroll
            for (int j = 0; j < 4; j++) d[c][t][j] = 0.f;

#pragma unroll
    for (int ks = 0; ks < 4; ks++) {
        const uint32_t coff = (uint32_t)(((ks*2 + klane) ^ l7) << 4);
        uint32_t ah0, ah1, ah2, ah3, al0, al1, al2, al3;
        ldm4(ah0, ah1, ah2, ah3, aH + coff);
        ldm4(al0, al1, al2, al3, aL + coff);
#pragma unroll
        for (int c = 0; c < 2; c++) {
            uint32_t bh0, bh1, bh2, bh3, bl0, bl1, bl2, bl3;
            ldm4(bh0, bh1, bh2, bh3, bH + (uint32_t)c*2048 + coff);
            ldm4(bl0, bl1, bl2, bl3, bL + (uint32_t)c*2048 + coff);
            mma16816(d[c][0], ah0, ah1, ah2, ah3, bh0, bh2);
            mma16816(d[c][1], ah0, ah1, ah2, ah3, bh1, bh3);
            mma16816(d[c][0], ah0, ah1, ah2, ah3, bl0, bl2);
            mma16816(d[c][1], ah0, ah1, ah2, ah3, bl1, bl3);
            mma16816(d[c][0], al0, al1, al2, al3, bh0, bh2);
            mma16816(d[c][1], al0, al1, al2, al3, bh1, bh3);
        }
    }
}

__device__ __forceinline__ void frag_to_f32(const float d[2][2][4], float* dstF) {
    const int w    = threadIdx.x >> 5;
    const int lane = threadIdx.x & 31;
    const int mt = w >> 1, hf = w & 1;
    const int r0 = mt*16 + (lane >> 2);
    const int cb = (lane & 3) * 2;
#pragma unroll
    for (int c = 0; c < 2; c++) {
        int cg = hf*2 + c;
#pragma unroll
        for (int t = 0; t < 2; t++) {
            *reinterpret_cast<float2*>(dstF + r0 * OUT_STR + cg*16 + cb + t*8) =
                make_float2(d[c][t][0], d[c][t][1]);
            *reinterpret_cast<float2*>(dstF + (r0 + 8) * OUT_STR + cg*16 + cb + t*8) =
                make_float2(d[c][t][2], d[c][t][3]);
        }
    }
}

__device__ __forceinline__ void frag_ln(const float v[2][8], int rA, int hf, int mt, int lane,
                                        float2* red2, float m[2], float iv[2])
{
    float s0 = 0.f, q0 = 0.f, s1 = 0.f, q1 = 0.f;
#pragma unroll
    for (int j = 0; j < 8; j++) {
        s0 += v[0][j]; q0 += v[0][j]*v[0][j];
        s1 += v[1][j]; q1 += v[1][j]*v[1][j];
    }
    s0 = sum4(s0); q0 = sum4(q0); s1 = sum4(s1); q1 = sum4(q1);
    if ((lane & 3) == 0) {
        red2[rA*2 + hf]     = make_float2(s0, q0);
        red2[(rA+8)*2 + hf] = make_float2(s1, q1);
    }
    asm volatile("bar.sync %0, %1;" :: "r"(mt + 1), "r"(64) : "memory");
    float2 o0 = red2[rA*2 + (hf^1)];
    float2 o1 = red2[(rA+8)*2 + (hf^1)];
    float S0 = s0 + o0.x, Q0 = q0 + o0.y;
    float S1 = s1 + o1.x, Q1 = q1 + o1.y;
    m[0] = S0 * (1.f/64.f);
    iv[0] = rsqrtf(Q0 * (1.f/64.f) - m[0]*m[0] + 1e-5f);
    m[1] = S1 * (1.f/64.f);
    iv[1] = rsqrtf(Q1 * (1.f/64.f) - m[1]*m[1] + 1e-5f);
}

// =====================================================================
__global__ __launch_bounds__(NTH, 2)
void waypoint_mma_kernel(
    const float* __restrict__ x,
    const float* __restrict__ embed_w, const float* __restrict__ embed_b,
    const float* __restrict__ ln1_g,   const float* __restrict__ ln1_b,
    const float* __restrict__ ln2_g,   const float* __restrict__ ln2_b,
    const float* __restrict__ ffn_b1,  const float* __restrict__ ffn_b2,
    const float* __restrict__ lnf_g,   const float* __restrict__ lnf_b,
    const float* __restrict__ head_w,  const float* __restrict__ head_b,
    float* __restrict__ out)
{
    extern __shared__ char smc[];
    const uint32_t su = smem_u32_of(smc);
    float*  outF = reinterpret_cast<float*>(smc + OUT_OFF);
    float*  kF   = reinterpret_cast<float*>(smc + KF_OFF);
    float*  SB   = reinterpret_cast<float*>(smc + S_OFF);
    float2* red2 = reinterpret_cast<float2*>(smc + RED_OFF);

    const int tid  = threadIdx.x;
    const int w    = tid >> 5;
    const int lane = tid & 31;
    const int mt   = w >> 1;
    const int hf   = w & 1;
    const int rA   = mt*16 + (lane >> 2);
    const int cb   = (lane & 3) * 2;
    const int rowBase = blockIdx.x * MROWS;

    int colv[8];
#pragma unroll
    for (int j = 0; j < 8; j++)
        colv[j] = hf*32 + (j>>2)*16 + ((j>>1)&1)*8 + cb + (j&1);

    float hreg[2][8];   // residual stream, fragment layout

    // stage-0 W preload via cp.async (overlaps embed)
    if (tid < 256) {
        uint32_t dst = su + W0_OFF + (uint32_t)tid * 64;
        const unsigned char* src = g_wtiles + tid * 64;
#pragma unroll
        for (int i = 0; i < 4; i++) cp16(dst + i*16, src + i*16);
    }
    cp_commit();

    // -------- embed + ln1(layer0) -> A0, fragment layout --------
    {
        float v[2][8];
#pragma unroll
        for (int r = 0; r < 2; r++) {
            int row = rA + 8*r;
            float4 xv = reinterpret_cast<const float4*>(x)[rowBase + row];
#pragma unroll
            for (int j = 0; j < 8; j++) {
                int col = colv[j];
                float a = embed_b[col];
                a = fmaf(xv.x, embed_w[col],       a);
                a = fmaf(xv.y, embed_w[64 + col],  a);
                a = fmaf(xv.z, embed_w[128 + col], a);
                a = fmaf(xv.w, embed_w[192 + col], a);
                v[r][j] = a; hreg[r][j] = a;
            }
        }
        float s0=0,q0=0,s1=0,q1=0;
#pragma unroll
        for (int j = 0; j < 8; j++) {
            s0 += v[0][j]; q0 += v[0][j]*v[0][j];
            s1 += v[1][j]; q1 += v[1][j]*v[1][j];
        }
        s0=sum4(s0); q0=sum4(q0); s1=sum4(s1); q1=sum4(q1);
        if ((lane & 3) == 0) {
            red2[rA*2 + hf]     = make_float2(s0, q0);
            red2[(rA+8)*2 + hf] = make_float2(s1, q1);
        }
        __syncthreads();
        float2 o0 = red2[rA*2 + (hf^1)];
        float2 o1 = red2[(rA+8)*2 + (hf^1)];
        float m0 = (s0+o0.x)*(1.f/64.f), i0 = rsqrtf((q0+o0.y)*(1.f/64.f)-m0*m0+1e-5f);
        float m1 = (s1+o1.x)*(1.f/64.f), i1 = rsqrtf((q1+o1.y)*(1.f/64.f)-m1*m1+1e-5f);
#pragma unroll
        for (int j = 0; j < 8; j += 2) {
            int col2 = colv[j];
            fst(smc+A0H_OFF, smc+A0L_OFF, rA,
                col2, (v[0][j]-m0)*i0*ln1_g[col2]+ln1_b[col2],
                      (v[0][j+1]-m0)*i0*ln1_g[col2+1]+ln1_b[col2+1]);
            fst(smc+A0H_OFF, smc+A0L_OFF, rA+8,
                col2, (v[1][j]-m1)*i1*ln1_g[col2]+ln1_b[col2],
                      (v[1][j+1]-m1)*i1*ln1_g[col2+1]+ln1_b[col2+1]);
        }
    }
    cp_wait0();
    __syncthreads();

    for (int st = 0; st < 36; st++) {
        const int kind = st % 12;
        const int li   = st / 12;
        const bool fromA1 = (kind == 3) || (kind >= 5 && (kind & 1));
        const uint32_t wB = (st & 1) ? W1_OFF : W0_OFF;

        // prefetch next stage's W tile into the other buffer
        if (tid < 256) {
            int nst = (st + 1 < 36) ? st + 1 : 0;
            uint32_t dst = su + ((st & 1) ? W0_OFF : W1_OFF) + (uint32_t)tid * 64;
            const unsigned char* src = g_wtiles + (size_t)nst * 16384 + tid * 64;
#pragma unroll
            for (int i = 0; i < 4; i++) cp16(dst + i*16, src + i*16);
        }
        cp_commit();

        float d[2][2][4];
        mma_compute(su, fromA1 ? A1H_OFF : A0H_OFF, fromA1 ? A1L_OFF : A0L_OFF, wB, d);

        if (kind == 0 || kind == 2) frag_to_f32(d, outF);
        else if (kind == 1)         frag_to_f32(d, kF);
        if (kind == 1 || kind == 2) __syncthreads();

        // ---------------- epilogue ----------------
        if (kind == 1) {
            int s   = tid / 40;
            int rem = tid % 40;
            int h   = rem / 10;
            int q   = rem % 10;
            const float4* qp = reinterpret_cast<const float4*>(outF + (s*TT + q) * OUT_STR + h * 16);
            float4 qv[4];
#pragma unroll
            for (int dd = 0; dd < 4; dd++) qv[dd] = qp[dd];
            float sc[TT];
            float mx = -1e30f;
            for (int kk = 0; kk <= q; kk++) {
                const float4* kp = reinterpret_cast<const float4*>(kF + (s*TT + kk) * OUT_STR + h * 16);
                float a = 0.f;
#pragma unroll
                for (int dd = 0; dd < 4; dd++) {
                    float4 kv = kp[dd];
                    a = fmaf(qv[dd].x, kv.x, a);
                    a = fmaf(qv[dd].y, kv.y, a);
                    a = fmaf(qv[dd].z, kv.z, a);
                    a = fmaf(qv[dd].w, kv.w, a);
                }
                a *= 0.25f;
                sc[kk] = a;
                mx = fmaxf(mx, a);
            }
            float ss = 0.f;
            for (int kk = 0; kk <= q; kk++) { sc[kk] = __expf(sc[kk] - mx); ss += sc[kk]; }
            float inv = __fdividef(1.f, ss);
            float* sp = SB + ((s * 4 + h) * TT + q) * TT;
#pragma unroll
            for (int kk = 0; kk < TT; kk++) sp[kk] = (kk <= q) ? sc[kk] * inv : 0.f;
        } else if (kind == 2) {
            int er = tid >> 2;
            int s = er / TT, q = er % TT;
            int h = tid & 3;
            const float* sp = SB + ((s * 4 + h) * TT + q) * TT;
            float y[16];
#pragma unroll
            for (int i = 0; i < 16; i++) y[i] = 0.f;
            for (int kk = 0; kk < TT; kk++) {
                float wgt = sp[kk];
                const float4* vp = reinterpret_cast<const float4*>(outF + (s*TT + kk) * OUT_STR + h * 16);
#pragma unroll
                for (int dd = 0; dd < 4; dd++) {
                    float4 vv = vp[dd];
                    y[dd*4+0] = fmaf(wgt, vv.x, y[dd*4+0]);
                    y[dd*4+1] = fmaf(wgt, vv.y, y[dd*4+1]);
                    y[dd*4+2] = fmaf(wgt, vv.z, y[dd*4+2]);
                    y[dd*4+3] = fmaf(wgt, vv.w, y[dd*4+3]);
                }
            }
            st_a16(smc + A1H_OFF, smc + A1L_OFF, er, h * 16, y);
        } else if (kind == 3) {
            float v[2][8];
#pragma unroll
            for (int j = 0; j < 8; j++) {
                int c = j>>2, t = (j>>1)&1, e = j&1;
                v[0][j] = d[c][t][e]   + hreg[0][j]; hreg[0][j] = v[0][j];
                v[1][j] = d[c][t][2+e] + hreg[1][j]; hreg[1][j] = v[1][j];
            }
            float m[2], iv[2];
            frag_ln(v, rA, hf, mt, lane, red2, m, iv);
            const float* g = ln2_g + li*DD;
            const float* b = ln2_b + li*DD;
#pragma unroll
            for (int j = 0; j < 8; j += 2) {
                int col2 = colv[j];
                fst(smc+A0H_OFF, smc+A0L_OFF, rA, col2,
                    (v[0][j]-m[0])*iv[0]*g[col2]+b[col2],
                    (v[0][j+1]-m[0])*iv[0]*g[col2+1]+b[col2+1]);
                fst(smc+A0H_OFF, smc+A0L_OFF, rA+8, col2,
                    (v[1][j]-m[1])*iv[1]*g[col2]+b[col2],
                    (v[1][j+1]-m[1])*iv[1]*g[col2+1]+b[col2+1]);
            }
        } else if (kind >= 4 && !(kind & 1)) {
            int ft = (kind - 4) >> 1;
            const float* b1 = ffn_b1 + li*FF + ft*64;
#pragma unroll
            for (int j = 0; j < 8; j += 2) {
                int c = j>>2, t = (j>>1)&1;
                int col2 = colv[j];
                fst(smc+A1H_OFF, smc+A1L_OFF, rA, col2,
                    gelu_fast(d[c][t][0] + b1[col2]),
                    gelu_fast(d[c][t][1] + b1[col2+1]));
                fst(smc+A1H_OFF, smc+A1L_OFF, rA+8, col2,
                    gelu_fast(d[c][t][2] + b1[col2]),
                    gelu_fast(d[c][t][3] + b1[col2+1]));
            }
        } else if (kind >= 5) {
            int ft = (kind - 5) >> 1;
#pragma unroll
            for (int j = 0; j < 8; j++) {
                int c = j>>2, t = (j>>1)&1, e = j&1;
                float add0 = d[c][t][e], add1 = d[c][t][2+e];
                if (ft == 0) {
                    float bb = ffn_b2[li*DD + colv[j]];
                    add0 += bb; add1 += bb;
                }
                hreg[0][j] += add0;
                hreg[1][j] += add1;
            }
            if (ft == 3) {
                float m[2], iv[2];
                frag_ln(hreg, rA, hf, mt, lane, red2, m, iv);
                if (li < 2) {
                    const float* g = ln1_g + (li+1)*DD;
                    const float* b = ln1_b + (li+1)*DD;
#pragma unroll
                    for (int j = 0; j < 8; j += 2) {
                        int col2 = colv[j];
                        fst(smc+A0H_OFF, smc+A0L_OFF, rA, col2,
                            (hreg[0][j]-m[0])*iv[0]*g[col2]+b[col2],
                            (hreg[0][j+1]-m[0])*iv[0]*g[col2+1]+b[col2+1]);
                        fst(smc+A0H_OFF, smc+A0L_OFF, rA+8, col2,
                            (hreg[1][j]-m[1])*iv[1]*g[col2]+b[col2],
                            (hreg[1][j+1]-m[1])*iv[1]*g[col2+1]+b[col2+1]);
                    }
                } else {
#pragma unroll
                    for (int j = 0; j < 8; j += 2) {
                        int col2 = colv[j];
                        *reinterpret_cast<float2*>(outF + rA*OUT_STR + col2) =
                            make_float2((hreg[0][j]-m[0])*iv[0]*lnf_g[col2]+lnf_b[col2],
                                        (hreg[0][j+1]-m[0])*iv[0]*lnf_g[col2+1]+lnf_b[col2+1]);
                        *reinterpret_cast<float2*>(outF + (rA+8)*OUT_STR + col2) =
                            make_float2((hreg[1][j]-m[1])*iv[1]*lnf_g[col2]+lnf_b[col2],
                                        (hreg[1][j+1]-m[1])*iv[1]*lnf_g[col2+1]+lnf_b[col2+1]);
                    }
                }
            }
        }
        // (kind == 0: q stays in outF)

        cp_wait0();
        __syncthreads();
    }

    // -------- head --------
    if (tid < NSEQ * TT) {
        int s = tid / TT;
        int j = tid % TT;
        const float* r = outF + (s * TT + TT - 1) * OUT_STR;
        float a = head_b[j];
#pragma unroll 16
        for (int dd = 0; dd < DD; dd++) a = fmaf(r[dd], head_w[dd * 10 + j], a);
        out[(blockIdx.x * NSEQ + s) * 10 + j] = a;
    }
}

extern "C" void kernel_launch(void* const* d_in, const int* in_sizes, int n_in,
                              void* d_out, int out_size)
{
    const float* x       = (const float*)d_in[0];
    const float* embed_w = (const float*)d_in[1];
    const float* embed_b = (const float*)d_in[2];
    const float* ln1_g   = (const float*)d_in[3];
    const float* ln1_b   = (const float*)d_in[4];
    const float* qkv_w   = (const float*)d_in[5];
    const float* proj_w  = (const float*)d_in[6];
    const float* ln2_g   = (const float*)d_in[7];
    const float* ln2_b   = (const float*)d_in[8];
    const float* ffn_w1  = (const float*)d_in[9];
    const float* ffn_b1  = (const float*)d_in[10];
    const float* ffn_w2  = (const float*)d_in[11];
    const float* ffn_b2  = (const float*)d_in[12];
    const float* lnf_g   = (const float*)d_in[13];
    const float* lnf_b   = (const float*)d_in[14];
    const float* head_w  = (const float*)d_in[15];
    const float* head_b  = (const float*)d_in[16];
    float* out = (float*)d_out;

    int nTokens = in_sizes[0] / 4;       // B*T
    int grid = nTokens / MROWS;          // 2048

    // prologue: split+swizzle weights into g_wtiles (deterministic, capture-safe)
    prep_wtiles<<<36, 256>>>(qkv_w, proj_w, ffn_w1, ffn_w2);

    cudaFuncSetAttribute(waypoint_mma_kernel,
                         cudaFuncAttributeMaxDynamicSharedMemorySize, SMEM_BYTES);

    waypoint_mma_kernel<<<grid, NTH, SMEM_BYTES>>>(
        x, embed_w, embed_b, ln1_g, ln1_b,
        ln2_g, ln2_b, ffn_b1, ffn_b2,
        lnf_g, lnf_b, head_w, head_b, out);
}

// round 12
// speedup vs baseline: 2.4106x; 1.2851x over previous
#include <cuda_runtime.h>
#include <cuda_fp16.h>
#include <cstdint>

// ---------------- problem constants ----------------
#define TT 10
#define DD 64
#define LL 3
#define FF 256
#define NSEQ 8
#define MROWS 80
#define NTH 320

// ---------------- SMEM layout (bytes) ----------------
#define OUT_OFF 0        // fp32 [80][68] = 21760
#define OUT_STR 68
#define A0H_OFF 21760    // fp16 [80][64] xor-swizzled, 128B rows (10240)
#define A0L_OFF 32000    // (10240)
#define KF_OFF  42240    // fp32 [80][68] = 21760 -> ends 64000 (aliases A1 tiles)
#define A1H_OFF 42240    // (10240)
#define A1L_OFF 52480    // (10240) -> ends 62720, inside KF region
#define W0_OFF  64000    // fp16 W tile, 8192
#define W1_OFF  72192    // 8192 -> ends 80384
#define S_OFF   80384    // fp32 [8][4][10][10] = 12800 -> ends 93184
#define RED_OFF 93184    // float2 [80][2] = 1280 -> ends 94464
#define SMEM_BYTES 94464

// Pre-converted swizzled fp16 weight tiles: 36 stages x 8192 B
__device__ unsigned char g_wtiles[36 * 8192];

// ---------------- helpers ----------------
__device__ __forceinline__ uint32_t smem_u32_of(const void* p) {
    uint32_t a;
    asm("{ .reg .u64 t; cvta.to.shared.u64 t, %1; cvt.u32.u64 %0, t; }" : "=r"(a) : "l"(p));
    return a;
}

__device__ __forceinline__ void ldm4(uint32_t& r0, uint32_t& r1, uint32_t& r2, uint32_t& r3,
                                     uint32_t a) {
    asm volatile("ldmatrix.sync.aligned.m8n8.x4.shared.b16 {%0,%1,%2,%3}, [%4];"
                 : "=r"(r0), "=r"(r1), "=r"(r2), "=r"(r3) : "r"(a));
}

__device__ __forceinline__ void mma16816(float* d,
                                         uint32_t a0, uint32_t a1, uint32_t a2, uint32_t a3,
                                         uint32_t b0, uint32_t b1) {
    asm volatile("mma.sync.aligned.m16n8k16.row.col.f32.f16.f16.f32 "
                 "{%0,%1,%2,%3}, {%4,%5,%6,%7}, {%8,%9}, {%0,%1,%2,%3};"
                 : "+f"(d[0]), "+f"(d[1]), "+f"(d[2]), "+f"(d[3])
                 : "r"(a0), "r"(a1), "r"(a2), "r"(a3), "r"(b0), "r"(b1));
}

__device__ __forceinline__ void cp16(uint32_t dst, const void* src) {
    asm volatile("cp.async.cg.shared.global [%0], [%1], 16;" :: "r"(dst), "l"(src));
}
__device__ __forceinline__ void cp_commit() {
    asm volatile("cp.async.commit_group;" ::: "memory");
}
__device__ __forceinline__ void cp_wait0() {
    asm volatile("cp.async.wait_group 0;" ::: "memory");
}

__device__ __forceinline__ float gelu_fast(float v) {
    float t = fabsf(v) * 0.70710678118654752f;
    float u = __fdividef(1.0f, fmaf(0.3275911f, t, 1.0f));
    float p = fmaf(1.061405429f, u, -1.453152027f);
    p = fmaf(p, u, 1.421413741f);
    p = fmaf(p, u, -0.284496736f);
    p = fmaf(p, u, 0.254829592f);
    p *= u;
    float e = __expf(-t * t);
    float erf_abs = fmaf(-p, e, 1.0f);
    return 0.5f * v * (1.0f + copysignf(erf_abs, v));
}

__device__ __forceinline__ float sum4(float v) {
    v += __shfl_xor_sync(0xffffffffu, v, 1);
    v += __shfl_xor_sync(0xffffffffu, v, 2);
    return v;
}

// split fp32 pair into fp16 hi/lo packed words
__device__ __forceinline__ void pack_split(float x0, float x1, uint32_t& hw, uint32_t& lw) {
    __half h0 = __float2half_rn(x0);
    __half h1 = __float2half_rn(x1);
    __half l0 = __float2half_rn(x0 - __half2float(h0));
    __half l1 = __float2half_rn(x1 - __half2float(h1));
    __half2 hp = __halves2half2(h0, h1);
    __half2 lp = __halves2half2(l0, l1);
    hw = *reinterpret_cast<uint32_t*>(&hp);
    lw = *reinterpret_cast<uint32_t*>(&lp);
}

__device__ __forceinline__ void fst(char* hi, char* lo, int row, int col2, float x0, float x1) {
    uint32_t off = (uint32_t)row * 128
                 + ((((uint32_t)col2 >> 3) ^ ((uint32_t)row & 7)) << 4)
                 + (((uint32_t)(col2 & 7)) << 1);
    uint32_t hw, lw;
    pack_split(x0, x1, hw, lw);
    *reinterpret_cast<uint32_t*>(hi + off) = hw;
    *reinterpret_cast<uint32_t*>(lo + off) = lw;
}

__device__ __forceinline__ void st_a16(char* hi, char* lo, int row, int c0, const float* v) {
    const uint32_t sw = (uint32_t)(row & 7);
#pragma unroll
    for (int g = 0; g < 2; g++) {
        uint32_t ph[4], pl[4];
#pragma unroll
        for (int i = 0; i < 4; i++)
            pack_split(v[g*8 + 2*i], v[g*8 + 2*i + 1], ph[i], pl[i]);
        uint32_t chunk = ((uint32_t)(c0 >> 3) + g) ^ sw;
        *reinterpret_cast<uint4*>(hi + row*128 + chunk*16) = make_uint4(ph[0], ph[1], ph[2], ph[3]);
        *reinterpret_cast<uint4*>(lo + row*128 + chunk*16) = make_uint4(pl[0], pl[1], pl[2], pl[3]);
    }
}

__device__ __forceinline__ const float* wptr_for(int st, int& ldg,
    const float* qkv_w, const float* proj_w, const float* w1, const float* w2)
{
    int li = st / 12, k = st % 12;
    switch (k) {
        case 0:  ldg = 192; return qkv_w + li * 64 * 192;
        case 1:  ldg = 192; return qkv_w + li * 64 * 192 + 64;
        case 2:  ldg = 192; return qkv_w + li * 64 * 192 + 128;
        case 3:  ldg = 64;  return proj_w + li * 64 * 64;
        case 4: case 6: case 8: case 10: {
            int ft = (k - 4) >> 1; ldg = 256; return w1 + li * 64 * 256 + ft * 64;
        }
        default: {
            int ft = (k - 5) >> 1; ldg = 64;  return w2 + li * 256 * 64 + ft * 64 * 64;
        }
    }
}

// ---------------- prologue: convert all weight tiles to swizzled fp16 once ----
__global__ void prep_wtiles(const float* __restrict__ qkv_w, const float* __restrict__ proj_w,
                            const float* __restrict__ ffn_w1, const float* __restrict__ ffn_w2)
{
    int st = blockIdx.x;
    int ldg;
    const float* g = wptr_for(st, ldg, qkv_w, proj_w, ffn_w1, ffn_w2);
    unsigned char* hi = g_wtiles + st * 8192;

    int t = threadIdx.x;          // 256 threads
    int n = t & 63, kb = t >> 6;
    const uint32_t sw = (uint32_t)(n & 7);
#pragma unroll
    for (int gg = 0; gg < 2; gg++) {
        uint32_t ph[4];
#pragma unroll
        for (int i = 0; i < 4; i++) {
            int k0 = kb * 16 + gg * 8 + 2 * i;
            __half2 hp = __floats2half2_rn(g[k0 * ldg + n], g[(k0 + 1) * ldg + n]);
            ph[i] = *reinterpret_cast<uint32_t*>(&hp);
        }
        uint32_t chunk = ((uint32_t)(2*kb + gg)) ^ sw;
        *reinterpret_cast<uint4*>(hi + n*128 + chunk*16) = make_uint4(ph[0], ph[1], ph[2], ph[3]);
    }
}

// ---------------- MMA mainloop: 2-pass split-A fp16 x single-B fp16 ----------
__device__ __forceinline__ void mma_compute(uint32_t su, uint32_t aHoff, uint32_t aLoff,
                                            uint32_t wHoff, float d[2][2][4])
{
    const int w    = threadIdx.x >> 5;
    const int lane = threadIdx.x & 31;
    const int mt = w >> 1;
    const int hf = w & 1;
    const int rl = (lane & 7) | (((lane >> 3) & 1) << 3);
    const int klane = lane >> 4;
    const int l7 = lane & 7;

    const uint32_t aH = su + aHoff + (uint32_t)(mt*16 + rl) * 128;
    const uint32_t aL = su + aLoff + (uint32_t)(mt*16 + rl) * 128;
    const uint32_t bB = su + wHoff + (uint32_t)(hf*32 + rl) * 128;

#pragma unroll
    for (int c = 0; c < 2; c++)
#pragma unroll
        for (int t = 0; t < 2; t++)
#pragma unroll
            for (int j = 0; j < 4; j++) d[c][t][j] = 0.f;

#pragma unroll
    for (int ks = 0; ks < 4; ks++) {
        const uint32_t coff = (uint32_t)(((ks*2 + klane) ^ l7) << 4);
        uint32_t ah0, ah1, ah2, ah3, al0, al1, al2, al3;
        uint32_t b00, b01, b02, b03, b10, b11, b12, b13;
        ldm4(ah0, ah1, ah2, ah3, aH + coff);
        ldm4(al0, al1, al2, al3, aL + coff);
        ldm4(b00, b01, b02, b03, bB + coff);
        ldm4(b10, b11, b12, b13, bB + 2048u + coff);
        // hi pass: 4 independent accumulator chains
        mma16816(d[0][0], ah0, ah1, ah2, ah3, b00, b02);
        mma16816(d[0][1], ah0, ah1, ah2, ah3, b01, b03);
        mma16816(d[1][0], ah0, ah1, ah2, ah3, b10, b12);
        mma16816(d[1][1], ah0, ah1, ah2, ah3, b11, b13);
        // lo pass
        mma16816(d[0][0], al0, al1, al2, al3, b00, b02);
        mma16816(d[0][1], al0, al1, al2, al3, b01, b03);
        mma16816(d[1][0], al0, al1, al2, al3, b10, b12);
        mma16816(d[1][1], al0, al1, al2, al3, b11, b13);
    }
}

__device__ __forceinline__ void frag_to_f32(const float d[2][2][4], float* dstF) {
    const int w    = threadIdx.x >> 5;
    const int lane = threadIdx.x & 31;
    const int mt = w >> 1, hf = w & 1;
    const int r0 = mt*16 + (lane >> 2);
    const int cb = (lane & 3) * 2;
#pragma unroll
    for (int c = 0; c < 2; c++) {
        int cg = hf*2 + c;
#pragma unroll
        for (int t = 0; t < 2; t++) {
            *reinterpret_cast<float2*>(dstF + r0 * OUT_STR + cg*16 + cb + t*8) =
                make_float2(d[c][t][0], d[c][t][1]);
            *reinterpret_cast<float2*>(dstF + (r0 + 8) * OUT_STR + cg*16 + cb + t*8) =
                make_float2(d[c][t][2], d[c][t][3]);
        }
    }
}

__device__ __forceinline__ void frag_ln(const float v[2][8], int rA, int hf, int mt, int lane,
                                        float2* red2, float m[2], float iv[2])
{
    float s0 = 0.f, q0 = 0.f, s1 = 0.f, q1 = 0.f;
#pragma unroll
    for (int j = 0; j < 8; j++) {
        s0 += v[0][j]; q0 += v[0][j]*v[0][j];
        s1 += v[1][j]; q1 += v[1][j]*v[1][j];
    }
    s0 = sum4(s0); q0 = sum4(q0); s1 = sum4(s1); q1 = sum4(q1);
    if ((lane & 3) == 0) {
        red2[rA*2 + hf]     = make_float2(s0, q0);
        red2[(rA+8)*2 + hf] = make_float2(s1, q1);
    }
    asm volatile("bar.sync %0, %1;" :: "r"(mt + 1), "r"(64) : "memory");
    float2 o0 = red2[rA*2 + (hf^1)];
    float2 o1 = red2[(rA+8)*2 + (hf^1)];
    float S0 = s0 + o0.x, Q0 = q0 + o0.y;
    float S1 = s1 + o1.x, Q1 = q1 + o1.y;
    m[0] = S0 * (1.f/64.f);
    iv[0] = rsqrtf(Q0 * (1.f/64.f) - m[0]*m[0] + 1e-5f);
    m[1] = S1 * (1.f/64.f);
    iv[1] = rsqrtf(Q1 * (1.f/64.f) - m[1]*m[1] + 1e-5f);
}

// =====================================================================
__global__ __launch_bounds__(NTH, 2)
void waypoint_mma_kernel(
    const float* __restrict__ x,
    const float* __restrict__ embed_w, const float* __restrict__ embed_b,
    const float* __restrict__ ln1_g,   const float* __restrict__ ln1_b,
    const float* __restrict__ ln2_g,   const float* __restrict__ ln2_b,
    const float* __restrict__ ffn_b1,  const float* __restrict__ ffn_b2,
    const float* __restrict__ lnf_g,   const float* __restrict__ lnf_b,
    const float* __restrict__ head_w,  const float* __restrict__ head_b,
    float* __restrict__ out)
{
    extern __shared__ char smc[];
    const uint32_t su = smem_u32_of(smc);
    float*  outF = reinterpret_cast<float*>(smc + OUT_OFF);
    float*  kF   = reinterpret_cast<float*>(smc + KF_OFF);
    float*  SB   = reinterpret_cast<float*>(smc + S_OFF);
    float2* red2 = reinterpret_cast<float2*>(smc + RED_OFF);

    const int tid  = threadIdx.x;
    const int w    = tid >> 5;
    const int lane = tid & 31;
    const int mt   = w >> 1;
    const int hf   = w & 1;
    const int rA   = mt*16 + (lane >> 2);
    const int cb   = (lane & 3) * 2;
    const int rowBase = blockIdx.x * MROWS;

    int colv[8];
#pragma unroll
    for (int j = 0; j < 8; j++)
        colv[j] = hf*32 + (j>>2)*16 + ((j>>1)&1)*8 + cb + (j&1);

    float hreg[2][8];   // residual stream, fragment layout

    // stage-0 W preload via cp.async (overlaps embed)
    if (tid < 256) {
        uint32_t dst = su + W0_OFF + (uint32_t)tid * 32;
        const unsigned char* src = g_wtiles + tid * 32;
        cp16(dst, src);
        cp16(dst + 16, src + 16);
    }
    cp_commit();

    // -------- embed + ln1(layer0) -> A0, fragment layout --------
    {
        float v[2][8];
#pragma unroll
        for (int r = 0; r < 2; r++) {
            int row = rA + 8*r;
            float4 xv = reinterpret_cast<const float4*>(x)[rowBase + row];
#pragma unroll
            for (int j = 0; j < 8; j++) {
                int col = colv[j];
                float a = embed_b[col];
                a = fmaf(xv.x, embed_w[col],       a);
                a = fmaf(xv.y, embed_w[64 + col],  a);
                a = fmaf(xv.z, embed_w[128 + col], a);
                a = fmaf(xv.w, embed_w[192 + col], a);
                v[r][j] = a; hreg[r][j] = a;
            }
        }
        float s0=0,q0=0,s1=0,q1=0;
#pragma unroll
        for (int j = 0; j < 8; j++) {
            s0 += v[0][j]; q0 += v[0][j]*v[0][j];
            s1 += v[1][j]; q1 += v[1][j]*v[1][j];
        }
        s0=sum4(s0); q0=sum4(q0); s1=sum4(s1); q1=sum4(q1);
        if ((lane & 3) == 0) {
            red2[rA*2 + hf]     = make_float2(s0, q0);
            red2[(rA+8)*2 + hf] = make_float2(s1, q1);
        }
        __syncthreads();
        float2 o0 = red2[rA*2 + (hf^1)];
        float2 o1 = red2[(rA+8)*2 + (hf^1)];
        float m0 = (s0+o0.x)*(1.f/64.f), i0 = rsqrtf((q0+o0.y)*(1.f/64.f)-m0*m0+1e-5f);
        float m1 = (s1+o1.x)*(1.f/64.f), i1 = rsqrtf((q1+o1.y)*(1.f/64.f)-m1*m1+1e-5f);
#pragma unroll
        for (int j = 0; j < 8; j += 2) {
            int col2 = colv[j];
            fst(smc+A0H_OFF, smc+A0L_OFF, rA,
                col2, (v[0][j]-m0)*i0*ln1_g[col2]+ln1_b[col2],
                      (v[0][j+1]-m0)*i0*ln1_g[col2+1]+ln1_b[col2+1]);
            fst(smc+A0H_OFF, smc+A0L_OFF, rA+8,
                col2, (v[1][j]-m1)*i1*ln1_g[col2]+ln1_b[col2],
                      (v[1][j+1]-m1)*i1*ln1_g[col2+1]+ln1_b[col2+1]);
        }
    }
    cp_wait0();
    __syncthreads();

    for (int st = 0; st < 36; st++) {
        const int kind = st % 12;
        const int li   = st / 12;
        const bool fromA1 = (kind == 3) || (kind >= 5 && (kind & 1));
        const uint32_t wB = (st & 1) ? W1_OFF : W0_OFF;

        // prefetch next stage's W tile into the other buffer
        if (tid < 256) {
            int nst = (st + 1 < 36) ? st + 1 : 0;
            uint32_t dst = su + ((st & 1) ? W0_OFF : W1_OFF) + (uint32_t)tid * 32;
            const unsigned char* src = g_wtiles + (size_t)nst * 8192 + tid * 32;
            cp16(dst, src);
            cp16(dst + 16, src + 16);
        }
        cp_commit();

        float d[2][2][4];
        mma_compute(su, fromA1 ? A1H_OFF : A0H_OFF, fromA1 ? A1L_OFF : A0L_OFF, wB, d);

        if (kind == 0 || kind == 2) frag_to_f32(d, outF);
        else if (kind == 1)         frag_to_f32(d, kF);
        if (kind == 1 || kind == 2) __syncthreads();

        // ---------------- epilogue ----------------
        if (kind == 1) {
            int s   = tid / 40;
            int rem = tid % 40;
            int h   = rem / 10;
            int q   = rem % 10;
            const float4* qp = reinterpret_cast<const float4*>(outF + (s*TT + q) * OUT_STR + h * 16);
            float4 qv[4];
#pragma unroll
            for (int dd = 0; dd < 4; dd++) qv[dd] = qp[dd];
            float sc[TT];
            float mx = -1e30f;
            for (int kk = 0; kk <= q; kk++) {
                const float4* kp = reinterpret_cast<const float4*>(kF + (s*TT + kk) * OUT_STR + h * 16);
                float a = 0.f;
#pragma unroll
                for (int dd = 0; dd < 4; dd++) {
                    float4 kv = kp[dd];
                    a = fmaf(qv[dd].x, kv.x, a);
                    a = fmaf(qv[dd].y, kv.y, a);
                    a = fmaf(qv[dd].z, kv.z, a);
                    a = fmaf(qv[dd].w, kv.w, a);
                }
                a *= 0.25f;
                sc[kk] = a;
                mx = fmaxf(mx, a);
            }
            float ss = 0.f;
            for (int kk = 0; kk <= q; kk++) { sc[kk] = __expf(sc[kk] - mx); ss += sc[kk]; }
            float inv = __fdividef(1.f, ss);
            float* sp = SB + ((s * 4 + h) * TT + q) * TT;
#pragma unroll
            for (int kk = 0; kk < TT; kk++) sp[kk] = (kk <= q) ? sc[kk] * inv : 0.f;
        } else if (kind == 2) {
            int er = tid >> 2;
            int s = er / TT, q = er % TT;
            int h = tid & 3;
            const float* sp = SB + ((s * 4 + h) * TT + q) * TT;
            float y[16];
#pragma unroll
            for (int i = 0; i < 16; i++) y[i] = 0.f;
            for (int kk = 0; kk < TT; kk++) {
                float wgt = sp[kk];
                const float4* vp = reinterpret_cast<const float4*>(outF + (s*TT + kk) * OUT_STR + h * 16);
#pragma unroll
                for (int dd = 0; dd < 4; dd++) {
                    float4 vv = vp[dd];
                    y[dd*4+0] = fmaf(wgt, vv.x, y[dd*4+0]);
                    y[dd*4+1] = fmaf(wgt, vv.y, y[dd*4+1]);
                    y[dd*4+2] = fmaf(wgt, vv.z, y[dd*4+2]);
                    y[dd*4+3] = fmaf(wgt, vv.w, y[dd*4+3]);
                }
            }
            st_a16(smc + A1H_OFF, smc + A1L_OFF, er, h * 16, y);
        } else if (kind == 3) {
            float v[2][8];
#pragma unroll
            for (int j = 0; j < 8; j++) {
                int c = j>>2, t = (j>>1)&1, e = j&1;
                v[0][j] = d[c][t][e]   + hreg[0][j]; hreg[0][j] = v[0][j];
                v[1][j] = d[c][t][2+e] + hreg[1][j]; hreg[1][j] = v[1][j];
            }
            float m[2], iv[2];
            frag_ln(v, rA, hf, mt, lane, red2, m, iv);
            const float* g = ln2_g + li*DD;
            const float* b = ln2_b + li*DD;
#pragma unroll
            for (int j = 0; j < 8; j += 2) {
                int col2 = colv[j];
                fst(smc+A0H_OFF, smc+A0L_OFF, rA, col2,
                    (v[0][j]-m[0])*iv[0]*g[col2]+b[col2],
                    (v[0][j+1]-m[0])*iv[0]*g[col2+1]+b[col2+1]);
                fst(smc+A0H_OFF, smc+A0L_OFF, rA+8, col2,
                    (v[1][j]-m[1])*iv[1]*g[col2]+b[col2],
                    (v[1][j+1]-m[1])*iv[1]*g[col2+1]+b[col2+1]);
            }
        } else if (kind >= 4 && !(kind & 1)) {
            int ft = (kind - 4) >> 1;
            const float* b1 = ffn_b1 + li*FF + ft*64;
#pragma unroll
            for (int j = 0; j < 8; j += 2) {
                int c = j>>2, t = (j>>1)&1;
                int col2 = colv[j];
                fst(smc+A1H_OFF, smc+A1L_OFF, rA, col2,
                    gelu_fast(d[c][t][0] + b1[col2]),
                    gelu_fast(d[c][t][1] + b1[col2+1]));
                fst(smc+A1H_OFF, smc+A1L_OFF, rA+8, col2,
                    gelu_fast(d[c][t][2] + b1[col2]),
                    gelu_fast(d[c][t][3] + b1[col2+1]));
            }
        } else if (kind >= 5) {
            int ft = (kind - 5) >> 1;
#pragma unroll
            for (int j = 0; j < 8; j++) {
                int c = j>>2, t = (j>>1)&1, e = j&1;
                float add0 = d[c][t][e], add1 = d[c][t][2+e];
                if (ft == 0) {
                    float bb = ffn_b2[li*DD + colv[j]];
                    add0 += bb; add1 += bb;
                }
                hreg[0][j] += add0;
                hreg[1][j] += add1;
            }
            if (ft == 3) {
                float m[2], iv[2];
                frag_ln(hreg, rA, hf, mt, lane, red2, m, iv);
                if (li < 2) {
                    const float* g = ln1_g + (li+1)*DD;
                    const float* b = ln1_b + (li+1)*DD;
#pragma unroll
                    for (int j = 0; j < 8; j += 2) {
                        int col2 = colv[j];
                        fst(smc+A0H_OFF, smc+A0L_OFF, rA, col2,
                            (hreg[0][j]-m[0])*iv[0]*g[col2]+b[col2],
                            (hreg[0][j+1]-m[0])*iv[0]*g[col2+1]+b[col2+1]);
                        fst(smc+A0H_OFF, smc+A0L_OFF, rA+8, col2,
                            (hreg[1][j]-m[1])*iv[1]*g[col2]+b[col2],
                            (hreg[1][j+1]-m[1])*iv[1]*g[col2+1]+b[col2+1]);
                    }
                } else {
#pragma unroll
                    for (int j = 0; j < 8; j += 2) {
                        int col2 = colv[j];
                        *reinterpret_cast<float2*>(outF + rA*OUT_STR + col2) =
                            make_float2((hreg[0][j]-m[0])*iv[0]*lnf_g[col2]+lnf_b[col2],
                                        (hreg[0][j+1]-m[0])*iv[0]*lnf_g[col2+1]+lnf_b[col2+1]);
                        *reinterpret_cast<float2*>(outF + (rA+8)*OUT_STR + col2) =
                            make_float2((hreg[1][j]-m[1])*iv[1]*lnf_g[col2]+lnf_b[col2],
                                        (hreg[1][j+1]-m[1])*iv[1]*lnf_g[col2+1]+lnf_b[col2+1]);
                    }
                }
            }
        }
        // (kind == 0: q stays in outF)

        cp_wait0();
        __syncthreads();
    }

    // -------- head --------
    if (tid < NSEQ * TT) {
        int s = tid / TT;
        int j = tid % TT;
        const float* r = outF + (s * TT + TT - 1) * OUT_STR;
        float a = head_b[j];
#pragma unroll 16
        for (int dd = 0; dd < DD; dd++) a = fmaf(r[dd], head_w[dd * 10 + j], a);
        out[(blockIdx.x * NSEQ + s) * 10 + j] = a;
    }
}

extern "C" void kernel_launch(void* const* d_in, const int* in_sizes, int n_in,
                              void* d_out, int out_size)
{
    const float* x       = (const float*)d_in[0];
    const float* embed_w = (const float*)d_in[1];
    const float* embed_b = (const float*)d_in[2];
    const float* ln1_g   = (const float*)d_in[3];
    const float* ln1_b   = (const float*)d_in[4];
    const float* qkv_w   = (const float*)d_in[5];
    const float* proj_w  = (const float*)d_in[6];
    const float* ln2_g   = (const float*)d_in[7];
    const float* ln2_b   = (const float*)d_in[8];
    const float* ffn_w1  = (const float*)d_in[9];
    const float* ffn_b1  = (const float*)d_in[10];
    const float* ffn_w2  = (const float*)d_in[11];
    const float* ffn_b2  = (const float*)d_in[12];
    const float* lnf_g   = (const float*)d_in[13];
    const float* lnf_b   = (const float*)d_in[14];
    const float* head_w  = (const float*)d_in[15];
    const float* head_b  = (const float*)d_in[16];
    float* out = (float*)d_out;

    int nTokens = in_sizes[0] / 4;       // B*T
    int grid = nTokens / MROWS;          // 2048

    // prologue: convert weights into fp16 swizzled tiles (deterministic, capture-safe)
    prep_wtiles<<<36, 256>>>(qkv_w, proj_w, ffn_w1, ffn_w2);

    cudaFuncSetAttribute(waypoint_mma_kernel,
                         cudaFuncAttributeMaxDynamicSharedMemorySize, SMEM_BYTES);

    waypoint_mma_kernel<<<grid, NTH, SMEM_BYTES>>>(
        x, embed_w, embed_b, ln1_g, ln1_b,
        ln2_g, ln2_b, ffn_b1, ffn_b2,
        lnf_g, lnf_b, head_w, head_b, out);
}

// round 13
// speedup vs baseline: 2.5279x; 1.0487x over previous
#include <cuda_runtime.h>
#include <cuda_fp16.h>
#include <cstdint>

// ---------------- problem constants ----------------
#define TT 10
#define DD 64
#define LL 3
#define FF 256
#define NSEQ 8
#define MROWS 80
#define NTH 320

// ---------------- SMEM layout (bytes) ----------------
#define OUT_OFF 0        // fp32 [80][68] = 21760
#define OUT_STR 68
#define A0H_OFF 21760    // fp16 [80][64] xor-swizzled, 128B rows (10240)
#define A0L_OFF 32000    // (10240)
#define KF_OFF  42240    // fp32 [80][68] = 21760 -> ends 64000 (aliases A1 tiles)
#define A1H_OFF 42240    // (10240)
#define A1L_OFF 52480    // (10240) -> ends 62720, inside KF region
#define W0_OFF  64000    // W slot 0: up to 2 fp16 tiles (16384)
#define W1_OFF  80384    // W slot 1: 16384 -> ends 96768
#define S_OFF   96768    // fp32 [8][4][10][10] = 12800 -> ends 109568
#define RED_OFF 109568   // float2 [80][2] = 1280 -> ends 110848
#define SMEM_BYTES 110848

// Pre-converted swizzled fp16 weight tiles: 36 tiles x 8192 B
// layer li: 12li+{0:q,1:k,2:v,3:proj,4:w1_0,5:w2_0,6:w1_1,7:w2_1,8:w1_2,9:w2_2,10:w1_3,11:w2_3}
__device__ unsigned char g_wtiles[36 * 8192];

// ---------------- helpers ----------------
__device__ __forceinline__ uint32_t smem_u32_of(const void* p) {
    uint32_t a;
    asm("{ .reg .u64 t; cvta.to.shared.u64 t, %1; cvt.u32.u64 %0, t; }" : "=r"(a) : "l"(p));
    return a;
}

__device__ __forceinline__ void ldm4(uint32_t& r0, uint32_t& r1, uint32_t& r2, uint32_t& r3,
                                     uint32_t a) {
    asm volatile("ldmatrix.sync.aligned.m8n8.x4.shared.b16 {%0,%1,%2,%3}, [%4];"
                 : "=r"(r0), "=r"(r1), "=r"(r2), "=r"(r3) : "r"(a));
}

__device__ __forceinline__ void mma16816(float* d,
                                         uint32_t a0, uint32_t a1, uint32_t a2, uint32_t a3,
                                         uint32_t b0, uint32_t b1) {
    asm volatile("mma.sync.aligned.m16n8k16.row.col.f32.f16.f16.f32 "
                 "{%0,%1,%2,%3}, {%4,%5,%6,%7}, {%8,%9}, {%0,%1,%2,%3};"
                 : "+f"(d[0]), "+f"(d[1]), "+f"(d[2]), "+f"(d[3])
                 : "r"(a0), "r"(a1), "r"(a2), "r"(a3), "r"(b0), "r"(b1));
}

__device__ __forceinline__ void cp16(uint32_t dst, const void* src) {
    asm volatile("cp.async.cg.shared.global [%0], [%1], 16;" :: "r"(dst), "l"(src));
}
__device__ __forceinline__ void cp_commit() {
    asm volatile("cp.async.commit_group;" ::: "memory");
}
__device__ __forceinline__ void cp_wait0() {
    asm volatile("cp.async.wait_group 0;" ::: "memory");
}

__device__ __forceinline__ float gelu_fast(float v) {
    float t = fabsf(v) * 0.70710678118654752f;
    float u = __fdividef(1.0f, fmaf(0.3275911f, t, 1.0f));
    float p = fmaf(1.061405429f, u, -1.453152027f);
    p = fmaf(p, u, 1.421413741f);
    p = fmaf(p, u, -0.284496736f);
    p = fmaf(p, u, 0.254829592f);
    p *= u;
    float e = __expf(-t * t);
    float erf_abs = fmaf(-p, e, 1.0f);
    return 0.5f * v * (1.0f + copysignf(erf_abs, v));
}

__device__ __forceinline__ float sum4(float v) {
    v += __shfl_xor_sync(0xffffffffu, v, 1);
    v += __shfl_xor_sync(0xffffffffu, v, 2);
    return v;
}

__device__ __forceinline__ void pack_split(float x0, float x1, uint32_t& hw, uint32_t& lw) {
    __half h0 = __float2half_rn(x0);
    __half h1 = __float2half_rn(x1);
    __half l0 = __float2half_rn(x0 - __half2float(h0));
    __half l1 = __float2half_rn(x1 - __half2float(h1));
    __half2 hp = __halves2half2(h0, h1);
    __half2 lp = __halves2half2(l0, l1);
    hw = *reinterpret_cast<uint32_t*>(&hp);
    lw = *reinterpret_cast<uint32_t*>(&lp);
}

__device__ __forceinline__ void fst(char* hi, char* lo, int row, int col2, float x0, float x1) {
    uint32_t off = (uint32_t)row * 128
                 + ((((uint32_t)col2 >> 3) ^ ((uint32_t)row & 7)) << 4)
                 + (((uint32_t)(col2 & 7)) << 1);
    uint32_t hw, lw;
    pack_split(x0, x1, hw, lw);
    *reinterpret_cast<uint32_t*>(hi + off) = hw;
    *reinterpret_cast<uint32_t*>(lo + off) = lw;
}

__device__ __forceinline__ void st_a16(char* hi, char* lo, int row, int c0, const float* v) {
    const uint32_t sw = (uint32_t)(row & 7);
#pragma unroll
    for (int g = 0; g < 2; g++) {
        uint32_t ph[4], pl[4];
#pragma unroll
        for (int i = 0; i < 4; i++)
            pack_split(v[g*8 + 2*i], v[g*8 + 2*i + 1], ph[i], pl[i]);
        uint32_t chunk = ((uint32_t)(c0 >> 3) + g) ^ sw;
        *reinterpret_cast<uint4*>(hi + row*128 + chunk*16) = make_uint4(ph[0], ph[1], ph[2], ph[3]);
        *reinterpret_cast<uint4*>(lo + row*128 + chunk*16) = make_uint4(pl[0], pl[1], pl[2], pl[3]);
    }
}

__device__ __forceinline__ const float* wptr_for(int st, int& ldg,
    const float* qkv_w, const float* proj_w, const float* w1, const float* w2)
{
    int li = st / 12, k = st % 12;
    switch (k) {
        case 0:  ldg = 192; return qkv_w + li * 64 * 192;
        case 1:  ldg = 192; return qkv_w + li * 64 * 192 + 64;
        case 2:  ldg = 192; return qkv_w + li * 64 * 192 + 128;
        case 3:  ldg = 64;  return proj_w + li * 64 * 64;
        case 4: case 6: case 8: case 10: {
            int ft = (k - 4) >> 1; ldg = 256; return w1 + li * 64 * 256 + ft * 64;
        }
        default: {
            int ft = (k - 5) >> 1; ldg = 64;  return w2 + li * 256 * 64 + ft * 64 * 64;
        }
    }
}

// ---------------- prologue: convert all weight tiles to swizzled fp16 once ----
__global__ void prep_wtiles(const float* __restrict__ qkv_w, const float* __restrict__ proj_w,
                            const float* __restrict__ ffn_w1, const float* __restrict__ ffn_w2)
{
    int st = blockIdx.x;
    int ldg;
    const float* g = wptr_for(st, ldg, qkv_w, proj_w, ffn_w1, ffn_w2);
    unsigned char* hi = g_wtiles + st * 8192;

    int t = threadIdx.x;          // 256 threads
    int n = t & 63, kb = t >> 6;
    const uint32_t sw = (uint32_t)(n & 7);
#pragma unroll
    for (int gg = 0; gg < 2; gg++) {
        uint32_t ph[4];
#pragma unroll
        for (int i = 0; i < 4; i++) {
            int k0 = kb * 16 + gg * 8 + 2 * i;
            __half2 hp = __floats2half2_rn(g[k0 * ldg + n], g[(k0 + 1) * ldg + n]);
            ph[i] = *reinterpret_cast<uint32_t*>(&hp);
        }
        uint32_t chunk = ((uint32_t)(2*kb + gg)) ^ sw;
        *reinterpret_cast<uint4*>(hi + n*128 + chunk*16) = make_uint4(ph[0], ph[1], ph[2], ph[3]);
    }
}

// prefetch cnt (1 or 2) contiguous tiles starting at t0 into slot
__device__ __forceinline__ void prefetch_w(uint32_t su, uint32_t slot, int t0, int cnt) {
    if (threadIdx.x < 256) {
        uint32_t dst = su + slot + (uint32_t)threadIdx.x * 32;
        const unsigned char* s0 = g_wtiles + (size_t)t0 * 8192 + threadIdx.x * 32;
        cp16(dst, s0);
        cp16(dst + 16, s0 + 16);
        if (cnt == 2) {
            cp16(dst + 8192, s0 + 8192);
            cp16(dst + 8192 + 16, s0 + 8192 + 16);
        }
    }
    cp_commit();
}

// ---------------- MMA mainloop: 2-pass split-A fp16 x single-B fp16 ----------
__device__ __forceinline__ void mma_compute(uint32_t su, uint32_t aHoff, uint32_t aLoff,
                                            uint32_t wHoff, float d[2][2][4])
{
    const int w    = threadIdx.x >> 5;
    const int lane = threadIdx.x & 31;
    const int mt = w >> 1;
    const int hf = w & 1;
    const int rl = (lane & 7) | (((lane >> 3) & 1) << 3);
    const int klane = lane >> 4;
    const int l7 = lane & 7;

    const uint32_t aH = su + aHoff + (uint32_t)(mt*16 + rl) * 128;
    const uint32_t aL = su + aLoff + (uint32_t)(mt*16 + rl) * 128;
    const uint32_t bB = su + wHoff + (uint32_t)(hf*32 + rl) * 128;

#pragma unroll
    for (int c = 0; c < 2; c++)
#pragma unroll
        for (int t = 0; t < 2; t++)
#pragma unroll
            for (int j = 0; j < 4; j++) d[c][t][j] = 0.f;

#pragma unroll
    for (int ks = 0; ks < 4; ks++) {
        const uint32_t coff = (uint32_t)(((ks*2 + klane) ^ l7) << 4);
        uint32_t ah0, ah1, ah2, ah3, al0, al1, al2, al3;
        uint32_t b00, b01, b02, b03, b10, b11, b12, b13;
        ldm4(ah0, ah1, ah2, ah3, aH + coff);
        ldm4(al0, al1, al2, al3, aL + coff);
        ldm4(b00, b01, b02, b03, bB + coff);
        ldm4(b10, b11, b12, b13, bB + 2048u + coff);
        mma16816(d[0][0], ah0, ah1, ah2, ah3, b00, b02);
        mma16816(d[0][1], ah0, ah1, ah2, ah3, b01, b03);
        mma16816(d[1][0], ah0, ah1, ah2, ah3, b10, b12);
        mma16816(d[1][1], ah0, ah1, ah2, ah3, b11, b13);
        mma16816(d[0][0], al0, al1, al2, al3, b00, b02);
        mma16816(d[0][1], al0, al1, al2, al3, b01, b03);
        mma16816(d[1][0], al0, al1, al2, al3, b10, b12);
        mma16816(d[1][1], al0, al1, al2, al3, b11, b13);
    }
}

__device__ __forceinline__ void frag_to_f32(const float d[2][2][4], float* dstF) {
    const int w    = threadIdx.x >> 5;
    const int lane = threadIdx.x & 31;
    const int mt = w >> 1, hf = w & 1;
    const int r0 = mt*16 + (lane >> 2);
    const int cb = (lane & 3) * 2;
#pragma unroll
    for (int c = 0; c < 2; c++) {
        int cg = hf*2 + c;
#pragma unroll
        for (int t = 0; t < 2; t++) {
            *reinterpret_cast<float2*>(dstF + r0 * OUT_STR + cg*16 + cb + t*8) =
                make_float2(d[c][t][0], d[c][t][1]);
            *reinterpret_cast<float2*>(dstF + (r0 + 8) * OUT_STR + cg*16 + cb + t*8) =
                make_float2(d[c][t][2], d[c][t][3]);
        }
    }
}

__device__ __forceinline__ void frag_ln(const float v[2][8], int rA, int hf, int mt, int lane,
                                        float2* red2, float m[2], float iv[2])
{
    float s0 = 0.f, q0 = 0.f, s1 = 0.f, q1 = 0.f;
#pragma unroll
    for (int j = 0; j < 8; j++) {
        s0 += v[0][j]; q0 += v[0][j]*v[0][j];
        s1 += v[1][j]; q1 += v[1][j]*v[1][j];
    }
    s0 = sum4(s0); q0 = sum4(q0); s1 = sum4(s1); q1 = sum4(q1);
    if ((lane & 3) == 0) {
        red2[rA*2 + hf]     = make_float2(s0, q0);
        red2[(rA+8)*2 + hf] = make_float2(s1, q1);
    }
    asm volatile("bar.sync %0, %1;" :: "r"(mt + 1), "r"(64) : "memory");
    float2 o0 = red2[rA*2 + (hf^1)];
    float2 o1 = red2[(rA+8)*2 + (hf^1)];
    float S0 = s0 + o0.x, Q0 = q0 + o0.y;
    float S1 = s1 + o1.x, Q1 = q1 + o1.y;
    m[0] = S0 * (1.f/64.f);
    iv[0] = rsqrtf(Q0 * (1.f/64.f) - m[0]*m[0] + 1e-5f);
    m[1] = S1 * (1.f/64.f);
    iv[1] = rsqrtf(Q1 * (1.f/64.f) - m[1]*m[1] + 1e-5f);
}

// =====================================================================
__global__ __launch_bounds__(NTH, 2)
void waypoint_mma_kernel(
    const float* __restrict__ x,
    const float* __restrict__ embed_w, const float* __restrict__ embed_b,
    const float* __restrict__ ln1_g,   const float* __restrict__ ln1_b,
    const float* __restrict__ ln2_g,   const float* __restrict__ ln2_b,
    const float* __restrict__ ffn_b1,  const float* __restrict__ ffn_b2,
    const float* __restrict__ lnf_g,   const float* __restrict__ lnf_b,
    const float* __restrict__ head_w,  const float* __restrict__ head_b,
    float* __restrict__ out)
{
    extern __shared__ char smc[];
    const uint32_t su = smem_u32_of(smc);
    float*  outF = reinterpret_cast<float*>(smc + OUT_OFF);
    float*  kF   = reinterpret_cast<float*>(smc + KF_OFF);
    float*  SB   = reinterpret_cast<float*>(smc + S_OFF);
    float2* red2 = reinterpret_cast<float2*>(smc + RED_OFF);

    const int tid  = threadIdx.x;
    const int w    = tid >> 5;
    const int lane = tid & 31;
    const int mt   = w >> 1;
    const int hf   = w & 1;
    const int rA   = mt*16 + (lane >> 2);
    const int cb   = (lane & 3) * 2;
    const int rowBase = blockIdx.x * MROWS;

    int colv[8];
#pragma unroll
    for (int j = 0; j < 8; j++)
        colv[j] = hf*32 + (j>>2)*16 + ((j>>1)&1)*8 + cb + (j&1);

    float hreg[2][8];   // residual stream, fragment layout

    // preload layer-0 q tile into slot 0 (overlaps embed)
    prefetch_w(su, W0_OFF, 0, 1);

    // -------- embed + ln1(layer0) -> A0, fragment layout --------
    {
        float v[2][8];
#pragma unroll
        for (int r = 0; r < 2; r++) {
            int row = rA + 8*r;
            float4 xv = reinterpret_cast<const float4*>(x)[rowBase + row];
#pragma unroll
            for (int j = 0; j < 8; j++) {
                int col = colv[j];
                float a = embed_b[col];
                a = fmaf(xv.x, embed_w[col],       a);
                a = fmaf(xv.y, embed_w[64 + col],  a);
                a = fmaf(xv.z, embed_w[128 + col], a);
                a = fmaf(xv.w, embed_w[192 + col], a);
                v[r][j] = a; hreg[r][j] = a;
            }
        }
        float s0=0,q0=0,s1=0,q1=0;
#pragma unroll
        for (int j = 0; j < 8; j++) {
            s0 += v[0][j]; q0 += v[0][j]*v[0][j];
            s1 += v[1][j]; q1 += v[1][j]*v[1][j];
        }
        s0=sum4(s0); q0=sum4(q0); s1=sum4(s1); q1=sum4(q1);
        if ((lane & 3) == 0) {
            red2[rA*2 + hf]     = make_float2(s0, q0);
            red2[(rA+8)*2 + hf] = make_float2(s1, q1);
        }
        __syncthreads();
        float2 o0 = red2[rA*2 + (hf^1)];
        float2 o1 = red2[(rA+8)*2 + (hf^1)];
        float m0 = (s0+o0.x)*(1.f/64.f), i0 = rsqrtf((q0+o0.y)*(1.f/64.f)-m0*m0+1e-5f);
        float m1 = (s1+o1.x)*(1.f/64.f), i1 = rsqrtf((q1+o1.y)*(1.f/64.f)-m1*m1+1e-5f);
#pragma unroll
        for (int j = 0; j < 8; j += 2) {
            int col2 = colv[j];
            fst(smc+A0H_OFF, smc+A0L_OFF, rA,
                col2, (v[0][j]-m0)*i0*ln1_g[col2]+ln1_b[col2],
                      (v[0][j+1]-m0)*i0*ln1_g[col2+1]+ln1_b[col2+1]);
            fst(smc+A0H_OFF, smc+A0L_OFF, rA+8,
                col2, (v[1][j]-m1)*i1*ln1_g[col2]+ln1_b[col2],
                      (v[1][j+1]-m1)*i1*ln1_g[col2+1]+ln1_b[col2+1]);
        }
    }
    cp_wait0();
    __syncthreads();

    for (int li = 0; li < LL; li++) {
        const int tb = li * 12;

        // ================= stage q (slot 0) =================
        prefetch_w(su, W1_OFF, tb + 1, 1);
        {
            float d[2][2][4];
            mma_compute(su, A0H_OFF, A0L_OFF, W0_OFF, d);
            frag_to_f32(d, outF);
        }
        cp_wait0(); __syncthreads();

        // ================= stage k (slot 1) =================
        prefetch_w(su, W0_OFF, tb + 2, 1);
        {
            float d[2][2][4];
            mma_compute(su, A0H_OFF, A0L_OFF, W1_OFF, d);
            frag_to_f32(d, kF);
        }
        cp_wait0(); __syncthreads();

        // ================= stage v + attention (slot 0) =================
        prefetch_w(su, W1_OFF, tb + 3, 1);
        {
            float d[2][2][4];
            mma_compute(su, A0H_OFF, A0L_OFF, W0_OFF, d);   // v in regs

            // ---- S phase (overlaps v-MMA completion) ----
            {
                int s   = tid / 40;
                int rem = tid % 40;
                int h   = rem / 10;
                int q   = rem % 10;
                const float4* qp = reinterpret_cast<const float4*>(outF + (s*TT + q) * OUT_STR + h * 16);
                float4 qv[4];
#pragma unroll
                for (int dd = 0; dd < 4; dd++) qv[dd] = qp[dd];
                float sc[TT];
                float mx = -1e30f;
                for (int kk = 0; kk <= q; kk++) {
                    const float4* kp = reinterpret_cast<const float4*>(kF + (s*TT + kk) * OUT_STR + h * 16);
                    float a = 0.f;
#pragma unroll
                    for (int dd = 0; dd < 4; dd++) {
                        float4 kv = kp[dd];
                        a = fmaf(qv[dd].x, kv.x, a);
                        a = fmaf(qv[dd].y, kv.y, a);
                        a = fmaf(qv[dd].z, kv.z, a);
                        a = fmaf(qv[dd].w, kv.w, a);
                    }
                    a *= 0.25f;
                    sc[kk] = a;
                    mx = fmaxf(mx, a);
                }
                float ss = 0.f;
                for (int kk = 0; kk <= q; kk++) { sc[kk] = __expf(sc[kk] - mx); ss += sc[kk]; }
                float inv = __fdividef(1.f, ss);
                float* sp = SB + ((s * 4 + h) * TT + q) * TT;
#pragma unroll
                for (int kk = 0; kk < TT; kk++) sp[kk] = (kk <= q) ? sc[kk] * inv : 0.f;
            }
            __syncthreads();           // S done; q reads done -> safe to overwrite outF

            frag_to_f32(d, outF);      // v -> outF
        }
        cp_wait0(); __syncthreads();   // v visible; proj W visible

        // ---- y phase ----
        {
            int er = tid >> 2;
            int s = er / TT, q = er % TT;
            int h = tid & 3;
            const float* sp = SB + ((s * 4 + h) * TT + q) * TT;
            float y[16];
#pragma unroll
            for (int i = 0; i < 16; i++) y[i] = 0.f;
            for (int kk = 0; kk < TT; kk++) {
                float wgt = sp[kk];
                const float4* vp = reinterpret_cast<const float4*>(outF + (s*TT + kk) * OUT_STR + h * 16);
#pragma unroll
                for (int dd = 0; dd < 4; dd++) {
                    float4 vv = vp[dd];
                    y[dd*4+0] = fmaf(wgt, vv.x, y[dd*4+0]);
                    y[dd*4+1] = fmaf(wgt, vv.y, y[dd*4+1]);
                    y[dd*4+2] = fmaf(wgt, vv.z, y[dd*4+2]);
                    y[dd*4+3] = fmaf(wgt, vv.w, y[dd*4+3]);
                }
            }
            st_a16(smc + A1H_OFF, smc + A1L_OFF, er, h * 16, y);
        }
        __syncthreads();               // A1 (y) visible

        // ================= stage proj (slot 1) =================
        prefetch_w(su, W0_OFF, tb + 4, 2);    // (w1_0, w2_0)
        {
            float d[2][2][4];
            mma_compute(su, A1H_OFF, A1L_OFF, W1_OFF, d);
            float v[2][8];
#pragma unroll
            for (int j = 0; j < 8; j++) {
                int c = j>>2, t = (j>>1)&1, e = j&1;
                v[0][j] = d[c][t][e]   + hreg[0][j]; hreg[0][j] = v[0][j];
                v[1][j] = d[c][t][2+e] + hreg[1][j]; hreg[1][j] = v[1][j];
            }
            float m[2], iv[2];
            frag_ln(v, rA, hf, mt, lane, red2, m, iv);
            const float* g = ln2_g + li*DD;
            const float* b = ln2_b + li*DD;
#pragma unroll
            for (int j = 0; j < 8; j += 2) {
                int col2 = colv[j];
                fst(smc+A0H_OFF, smc+A0L_OFF, rA, col2,
                    (v[0][j]-m[0])*iv[0]*g[col2]+b[col2],
                    (v[0][j+1]-m[0])*iv[0]*g[col2+1]+b[col2+1]);
                fst(smc+A0H_OFF, smc+A0L_OFF, rA+8, col2,
                    (v[1][j]-m[1])*iv[1]*g[col2]+b[col2],
                    (v[1][j+1]-m[1])*iv[1]*g[col2+1]+b[col2+1]);
            }
        }
        cp_wait0(); __syncthreads();

        // ================= merged FFN stages (4) =================
        for (int ft = 0; ft < 4; ft++) {
            const uint32_t sc_ = (ft & 1) ? W1_OFF : W0_OFF;
            const uint32_t sn_ = (ft & 1) ? W0_OFF : W1_OFF;
            if (ft < 3)      prefetch_w(su, sn_, tb + 6 + 2*ft, 2);
            else if (li < 2) prefetch_w(su, sn_, tb + 12, 1);
            else             prefetch_w(su, sn_, 0, 1);

            // ffn1 chunk: z = gelu(A0 @ w1_ft + b1) -> A1 (pair-local rows)
            {
                float d[2][2][4];
                mma_compute(su, A0H_OFF, A0L_OFF, sc_, d);
                const float* b1 = ffn_b1 + li*FF + ft*64;
#pragma unroll
                for (int j = 0; j < 8; j += 2) {
                    int c = j>>2, t = (j>>1)&1;
                    int col2 = colv[j];
                    fst(smc+A1H_OFF, smc+A1L_OFF, rA, col2,
                        gelu_fast(d[c][t][0] + b1[col2]),
                        gelu_fast(d[c][t][1] + b1[col2+1]));
                    fst(smc+A1H_OFF, smc+A1L_OFF, rA+8, col2,
                        gelu_fast(d[c][t][2] + b1[col2]),
                        gelu_fast(d[c][t][3] + b1[col2+1]));
                }
            }
            // pair-local sync: both warps of mt wrote their z columns
            asm volatile("bar.sync %0, 64;" :: "r"(mt + 1) : "memory");

            // ffn2 chunk: hreg += z @ w2_ft (+b2 at ft0); LN at ft3
            {
                float d[2][2][4];
                mma_compute(su, A1H_OFF, A1L_OFF, sc_ + 8192, d);
#pragma unroll
                for (int j = 0; j < 8; j++) {
                    int c = j>>2, t = (j>>1)&1, e = j&1;
                    float add0 = d[c][t][e], add1 = d[c][t][2+e];
                    if (ft == 0) {
                        float bb = ffn_b2[li*DD + colv[j]];
                        add0 += bb; add1 += bb;
                    }
                    hreg[0][j] += add0;
                    hreg[1][j] += add1;
                }
                if (ft == 3) {
                    float m[2], iv[2];
                    frag_ln(hreg, rA, hf, mt, lane, red2, m, iv);
                    if (li < 2) {
                        const float* g = ln1_g + (li+1)*DD;
                        const float* b = ln1_b + (li+1)*DD;
#pragma unroll
                        for (int j = 0; j < 8; j += 2) {
                            int col2 = colv[j];
                            fst(smc+A0H_OFF, smc+A0L_OFF, rA, col2,
                                (hreg[0][j]-m[0])*iv[0]*g[col2]+b[col2],
                                (hreg[0][j+1]-m[0])*iv[0]*g[col2+1]+b[col2+1]);
                            fst(smc+A0H_OFF, smc+A0L_OFF, rA+8, col2,
                                (hreg[1][j]-m[1])*iv[1]*g[col2]+b[col2],
                                (hreg[1][j+1]-m[1])*iv[1]*g[col2+1]+b[col2+1]);
                        }
                    } else {
#pragma unroll
                        for (int j = 0; j < 8; j += 2) {
                            int col2 = colv[j];
                            *reinterpret_cast<float2*>(outF + rA*OUT_STR + col2) =
                                make_float2((hreg[0][j]-m[0])*iv[0]*lnf_g[col2]+lnf_b[col2],
                                            (hreg[0][j+1]-m[0])*iv[0]*lnf_g[col2+1]+lnf_b[col2+1]);
                            *reinterpret_cast<float2*>(outF + (rA+8)*OUT_STR + col2) =
                                make_float2((hreg[1][j]-m[1])*iv[1]*lnf_g[col2]+lnf_b[col2],
                                            (hreg[1][j+1]-m[1])*iv[1]*lnf_g[col2+1]+lnf_b[col2+1]);
                        }
                    }
                }
            }
            cp_wait0(); __syncthreads();
        }
    }

    // -------- head --------
    if (tid < NSEQ * TT) {
        int s = tid / TT;
        int j = tid % TT;
        const float* r = outF + (s * TT + TT - 1) * OUT_STR;
        float a = head_b[j];
#pragma unroll 16
        for (int dd = 0; dd < DD; dd++) a = fmaf(r[dd], head_w[dd * 10 + j], a);
        out[(blockIdx.x * NSEQ + s) * 10 + j] = a;
    }
}

extern "C" void kernel_launch(void* const* d_in, const int* in_sizes, int n_in,
                              void* d_out, int out_size)
{
    const float* x       = (const float*)d_in[0];
    const float* embed_w = (const float*)d_in[1];
    const float* embed_b = (const float*)d_in[2];
    const float* ln1_g   = (const float*)d_in[3];
    const float* ln1_b   = (const float*)d_in[4];
    const float* qkv_w   = (const float*)d_in[5];
    const float* proj_w  = (const float*)d_in[6];
    const float* ln2_g   = (const float*)d_in[7];
    const float* ln2_b   = (const float*)d_in[8];
    const float* ffn_w1  = (const float*)d_in[9];
    const float* ffn_b1  = (const float*)d_in[10];
    const float* ffn_w2  = (const float*)d_in[11];
    const float* ffn_b2  = (const float*)d_in[12];
    const float* lnf_g   = (const float*)d_in[13];
    const float* lnf_b   = (const float*)d_in[14];
    const float* head_w  = (const float*)d_in[15];
    const float* head_b  = (const float*)d_in[16];
    float* out = (float*)d_out;

    int nTokens = in_sizes[0] / 4;       // B*T
    int grid = nTokens / MROWS;          // 2048

    // prologue: convert weights into fp16 swizzled tiles (deterministic, capture-safe)
    prep_wtiles<<<36, 256>>>(qkv_w, proj_w, ffn_w1, ffn_w2);

    cudaFuncSetAttribute(waypoint_mma_kernel,
                         cudaFuncAttributeMaxDynamicSharedMemorySize, SMEM_BYTES);

    waypoint_mma_kernel<<<grid, NTH, SMEM_BYTES>>>(
        x, embed_w, embed_b, ln1_g, ln1_b,
        ln2_g, ln2_b, ffn_b1, ffn_b2,
        lnf_g, lnf_b, head_w, head_b, out);
}

// round 14
// speedup vs baseline: 3.0180x; 1.1939x over previous
#include <cuda_runtime.h>
#include <cuda_fp16.h>
#include <cstdint>

// ---------------- problem constants ----------------
#define TT 10
#define DD 64
#define LL 3
#define FF 256
#define NSEQ 8
#define MROWS 80
#define NTH 320

// ---------------- SMEM layout (bytes) ----------------
#define OUT_OFF 0        // fp32 [80][68] = 21760
#define OUT_STR 68
#define A0_OFF  21760    // fp16 [80][64] xor-swizzled, 128B rows (10240) -> 32000
#define KF_OFF  32000    // fp32 [80][68] = 21760 -> 53760 (aliases A1)
#define A1_OFF  32000    // fp16 tile 10240 -> 42240, inside KF region
#define W0_OFF  53760    // W slot 0: 2 fp16 tiles (16384) -> 70144
#define W1_OFF  70144    // W slot 1: 16384 -> 86528
#define S_OFF   86528    // fp32 [8][4][10][10] = 12800 -> 99328
#define RED_OFF 99328    // float2 [80][2] = 1280 -> 100608
#define SMEM_BYTES 100608

// Pre-converted swizzled fp16 weight tiles: 36 tiles x 8192 B
// layer li: 12li+{0:q,1:k,2:v,3:proj,4:w1_0,5:w2_0,6:w1_1,7:w2_1,8:w1_2,9:w2_2,10:w1_3,11:w2_3}
__device__ unsigned char g_wtiles[36 * 8192];

// ---------------- helpers ----------------
__device__ __forceinline__ uint32_t smem_u32_of(const void* p) {
    uint32_t a;
    asm("{ .reg .u64 t; cvta.to.shared.u64 t, %1; cvt.u32.u64 %0, t; }" : "=r"(a) : "l"(p));
    return a;
}

__device__ __forceinline__ void ldm4(uint32_t& r0, uint32_t& r1, uint32_t& r2, uint32_t& r3,
                                     uint32_t a) {
    asm volatile("ldmatrix.sync.aligned.m8n8.x4.shared.b16 {%0,%1,%2,%3}, [%4];"
                 : "=r"(r0), "=r"(r1), "=r"(r2), "=r"(r3) : "r"(a));
}

__device__ __forceinline__ void mma16816(float* d,
                                         uint32_t a0, uint32_t a1, uint32_t a2, uint32_t a3,
                                         uint32_t b0, uint32_t b1) {
    asm volatile("mma.sync.aligned.m16n8k16.row.col.f32.f16.f16.f32 "
                 "{%0,%1,%2,%3}, {%4,%5,%6,%7}, {%8,%9}, {%0,%1,%2,%3};"
                 : "+f"(d[0]), "+f"(d[1]), "+f"(d[2]), "+f"(d[3])
                 : "r"(a0), "r"(a1), "r"(a2), "r"(a3), "r"(b0), "r"(b1));
}

__device__ __forceinline__ void cp16(uint32_t dst, const void* src) {
    asm volatile("cp.async.cg.shared.global [%0], [%1], 16;" :: "r"(dst), "l"(src));
}
__device__ __forceinline__ void cp_commit() {
    asm volatile("cp.async.commit_group;" ::: "memory");
}
__device__ __forceinline__ void cp_wait0() {
    asm volatile("cp.async.wait_group 0;" ::: "memory");
}

__device__ __forceinline__ float gelu_fast(float v) {
    float t = fabsf(v) * 0.70710678118654752f;
    float u = __fdividef(1.0f, fmaf(0.3275911f, t, 1.0f));
    float p = fmaf(1.061405429f, u, -1.453152027f);
    p = fmaf(p, u, 1.421413741f);
    p = fmaf(p, u, -0.284496736f);
    p = fmaf(p, u, 0.254829592f);
    p *= u;
    float e = __expf(-t * t);
    float erf_abs = fmaf(-p, e, 1.0f);
    return 0.5f * v * (1.0f + copysignf(erf_abs, v));
}

__device__ __forceinline__ float sum4(float v) {
    v += __shfl_xor_sync(0xffffffffu, v, 1);
    v += __shfl_xor_sync(0xffffffffu, v, 2);
    return v;
}

// pack fp32 pair to fp16x2 word
__device__ __forceinline__ uint32_t pack1(float x0, float x1) {
    __half2 hp = __floats2half2_rn(x0, x1);
    return *reinterpret_cast<uint32_t*>(&hp);
}

// fragment store of an adjacent column pair into a swizzled fp16 tile
__device__ __forceinline__ void fst(char* t, int row, int col2, float x0, float x1) {
    uint32_t off = (uint32_t)row * 128
                 + ((((uint32_t)col2 >> 3) ^ ((uint32_t)row & 7)) << 4)
                 + (((uint32_t)(col2 & 7)) << 1);
    *reinterpret_cast<uint32_t*>(t + off) = pack1(x0, x1);
}

// row-major 16-value store (er-layout) used by the attention y-phase
__device__ __forceinline__ void st_a16(char* t, int row, int c0, const float* v) {
    const uint32_t sw = (uint32_t)(row & 7);
#pragma unroll
    for (int g = 0; g < 2; g++) {
        uint32_t ph[4];
#pragma unroll
        for (int i = 0; i < 4; i++)
            ph[i] = pack1(v[g*8 + 2*i], v[g*8 + 2*i + 1]);
        uint32_t chunk = ((uint32_t)(c0 >> 3) + g) ^ sw;
        *reinterpret_cast<uint4*>(t + row*128 + chunk*16) = make_uint4(ph[0], ph[1], ph[2], ph[3]);
    }
}

__device__ __forceinline__ const float* wptr_for(int st, int& ldg,
    const float* qkv_w, const float* proj_w, const float* w1, const float* w2)
{
    int li = st / 12, k = st % 12;
    switch (k) {
        case 0:  ldg = 192; return qkv_w + li * 64 * 192;
        case 1:  ldg = 192; return qkv_w + li * 64 * 192 + 64;
        case 2:  ldg = 192; return qkv_w + li * 64 * 192 + 128;
        case 3:  ldg = 64;  return proj_w + li * 64 * 64;
        case 4: case 6: case 8: case 10: {
            int ft = (k - 4) >> 1; ldg = 256; return w1 + li * 64 * 256 + ft * 64;
        }
        default: {
            int ft = (k - 5) >> 1; ldg = 64;  return w2 + li * 256 * 64 + ft * 64 * 64;
        }
    }
}

// ---------------- prologue: convert all weight tiles to swizzled fp16 once ----
__global__ void prep_wtiles(const float* __restrict__ qkv_w, const float* __restrict__ proj_w,
                            const float* __restrict__ ffn_w1, const float* __restrict__ ffn_w2)
{
    int st = blockIdx.x;
    int ldg;
    const float* g = wptr_for(st, ldg, qkv_w, proj_w, ffn_w1, ffn_w2);
    unsigned char* hi = g_wtiles + st * 8192;

    int t = threadIdx.x;          // 256 threads
    int n = t & 63, kb = t >> 6;
    const uint32_t sw = (uint32_t)(n & 7);
#pragma unroll
    for (int gg = 0; gg < 2; gg++) {
        uint32_t ph[4];
#pragma unroll
        for (int i = 0; i < 4; i++) {
            int k0 = kb * 16 + gg * 8 + 2 * i;
            ph[i] = pack1(g[k0 * ldg + n], g[(k0 + 1) * ldg + n]);
        }
        uint32_t chunk = ((uint32_t)(2*kb + gg)) ^ sw;
        *reinterpret_cast<uint4*>(hi + n*128 + chunk*16) = make_uint4(ph[0], ph[1], ph[2], ph[3]);
    }
}

// prefetch cnt (1 or 2) contiguous tiles starting at t0 into slot
__device__ __forceinline__ void prefetch_w(uint32_t su, uint32_t slot, int t0, int cnt) {
    if (threadIdx.x < 256) {
        uint32_t dst = su + slot + (uint32_t)threadIdx.x * 32;
        const unsigned char* s0 = g_wtiles + (size_t)t0 * 8192 + threadIdx.x * 32;
        cp16(dst, s0);
        cp16(dst + 16, s0 + 16);
        if (cnt == 2) {
            cp16(dst + 8192, s0 + 8192);
            cp16(dst + 8192 + 16, s0 + 8192 + 16);
        }
    }
    cp_commit();
}

// ---------------- MMA mainloop: single-pass fp16 x fp16 ----------
__device__ __forceinline__ void mma_compute(uint32_t su, uint32_t aoff,
                                            uint32_t woff, float d[2][2][4])
{
    const int w    = threadIdx.x >> 5;
    const int lane = threadIdx.x & 31;
    const int mt = w >> 1;
    const int hf = w & 1;
    const int rl = (lane & 7) | (((lane >> 3) & 1) << 3);
    const int klane = lane >> 4;
    const int l7 = lane & 7;

    const uint32_t aB = su + aoff + (uint32_t)(mt*16 + rl) * 128;
    const uint32_t bB = su + woff + (uint32_t)(hf*32 + rl) * 128;

#pragma unroll
    for (int c = 0; c < 2; c++)
#pragma unroll
        for (int t = 0; t < 2; t++)
#pragma unroll
            for (int j = 0; j < 4; j++) d[c][t][j] = 0.f;

#pragma unroll
    for (int ks = 0; ks < 4; ks++) {
        const uint32_t coff = (uint32_t)(((ks*2 + klane) ^ l7) << 4);
        uint32_t a0, a1, a2, a3;
        uint32_t b00, b01, b02, b03, b10, b11, b12, b13;
        ldm4(a0, a1, a2, a3, aB + coff);
        ldm4(b00, b01, b02, b03, bB + coff);
        ldm4(b10, b11, b12, b13, bB + 2048u + coff);
        mma16816(d[0][0], a0, a1, a2, a3, b00, b02);
        mma16816(d[0][1], a0, a1, a2, a3, b01, b03);
        mma16816(d[1][0], a0, a1, a2, a3, b10, b12);
        mma16816(d[1][1], a0, a1, a2, a3, b11, b13);
    }
}

__device__ __forceinline__ void frag_to_f32(const float d[2][2][4], float* dstF) {
    const int w    = threadIdx.x >> 5;
    const int lane = threadIdx.x & 31;
    const int mt = w >> 1, hf = w & 1;
    const int r0 = mt*16 + (lane >> 2);
    const int cb = (lane & 3) * 2;
#pragma unroll
    for (int c = 0; c < 2; c++) {
        int cg = hf*2 + c;
#pragma unroll
        for (int t = 0; t < 2; t++) {
            *reinterpret_cast<float2*>(dstF + r0 * OUT_STR + cg*16 + cb + t*8) =
                make_float2(d[c][t][0], d[c][t][1]);
            *reinterpret_cast<float2*>(dstF + (r0 + 8) * OUT_STR + cg*16 + cb + t*8) =
                make_float2(d[c][t][2], d[c][t][3]);
        }
    }
}

__device__ __forceinline__ void frag_ln(const float v[2][8], int rA, int hf, int mt, int lane,
                                        float2* red2, float m[2], float iv[2])
{
    float s0 = 0.f, q0 = 0.f, s1 = 0.f, q1 = 0.f;
#pragma unroll
    for (int j = 0; j < 8; j++) {
        s0 += v[0][j]; q0 += v[0][j]*v[0][j];
        s1 += v[1][j]; q1 += v[1][j]*v[1][j];
    }
    s0 = sum4(s0); q0 = sum4(q0); s1 = sum4(s1); q1 = sum4(q1);
    if ((lane & 3) == 0) {
        red2[rA*2 + hf]     = make_float2(s0, q0);
        red2[(rA+8)*2 + hf] = make_float2(s1, q1);
    }
    asm volatile("bar.sync %0, %1;" :: "r"(mt + 1), "r"(64) : "memory");
    float2 o0 = red2[rA*2 + (hf^1)];
    float2 o1 = red2[(rA+8)*2 + (hf^1)];
    float S0 = s0 + o0.x, Q0 = q0 + o0.y;
    float S1 = s1 + o1.x, Q1 = q1 + o1.y;
    m[0] = S0 * (1.f/64.f);
    iv[0] = rsqrtf(Q0 * (1.f/64.f) - m[0]*m[0] + 1e-5f);
    m[1] = S1 * (1.f/64.f);
    iv[1] = rsqrtf(Q1 * (1.f/64.f) - m[1]*m[1] + 1e-5f);
}

// =====================================================================
__global__ __launch_bounds__(NTH, 2)
void waypoint_mma_kernel(
    const float* __restrict__ x,
    const float* __restrict__ embed_w, const float* __restrict__ embed_b,
    const float* __restrict__ ln1_g,   const float* __restrict__ ln1_b,
    const float* __restrict__ ln2_g,   const float* __restrict__ ln2_b,
    const float* __restrict__ ffn_b1,  const float* __restrict__ ffn_b2,
    const float* __restrict__ lnf_g,   const float* __restrict__ lnf_b,
    const float* __restrict__ head_w,  const float* __restrict__ head_b,
    float* __restrict__ out)
{
    extern __shared__ char smc[];
    const uint32_t su = smem_u32_of(smc);
    float*  outF = reinterpret_cast<float*>(smc + OUT_OFF);
    float*  kF   = reinterpret_cast<float*>(smc + KF_OFF);
    float*  SB   = reinterpret_cast<float*>(smc + S_OFF);
    float2* red2 = reinterpret_cast<float2*>(smc + RED_OFF);

    const int tid  = threadIdx.x;
    const int w    = tid >> 5;
    const int lane = tid & 31;
    const int mt   = w >> 1;
    const int hf   = w & 1;
    const int rA   = mt*16 + (lane >> 2);
    const int cb   = (lane & 3) * 2;
    const int rowBase = blockIdx.x * MROWS;

    int colv[8];
#pragma unroll
    for (int j = 0; j < 8; j++)
        colv[j] = hf*32 + (j>>2)*16 + ((j>>1)&1)*8 + cb + (j&1);

    float hreg[2][8];   // residual stream, fragment layout

    // preload layer-0 (q,k) into slot 0 (overlaps embed)
    prefetch_w(su, W0_OFF, 0, 2);

    // -------- embed + ln1(layer0) -> A0, fragment layout --------
    {
        float v[2][8];
#pragma unroll
        for (int r = 0; r < 2; r++) {
            int row = rA + 8*r;
            float4 xv = reinterpret_cast<const float4*>(x)[rowBase + row];
#pragma unroll
            for (int j = 0; j < 8; j++) {
                int col = colv[j];
                float a = embed_b[col];
                a = fmaf(xv.x, embed_w[col],       a);
                a = fmaf(xv.y, embed_w[64 + col],  a);
                a = fmaf(xv.z, embed_w[128 + col], a);
                a = fmaf(xv.w, embed_w[192 + col], a);
                v[r][j] = a; hreg[r][j] = a;
            }
        }
        float s0=0,q0=0,s1=0,q1=0;
#pragma unroll
        for (int j = 0; j < 8; j++) {
            s0 += v[0][j]; q0 += v[0][j]*v[0][j];
            s1 += v[1][j]; q1 += v[1][j]*v[1][j];
        }
        s0=sum4(s0); q0=sum4(q0); s1=sum4(s1); q1=sum4(q1);
        if ((lane & 3) == 0) {
            red2[rA*2 + hf]     = make_float2(s0, q0);
            red2[(rA+8)*2 + hf] = make_float2(s1, q1);
        }
        __syncthreads();
        float2 o0 = red2[rA*2 + (hf^1)];
        float2 o1 = red2[(rA+8)*2 + (hf^1)];
        float m0 = (s0+o0.x)*(1.f/64.f), i0 = rsqrtf((q0+o0.y)*(1.f/64.f)-m0*m0+1e-5f);
        float m1 = (s1+o1.x)*(1.f/64.f), i1 = rsqrtf((q1+o1.y)*(1.f/64.f)-m1*m1+1e-5f);
#pragma unroll
        for (int j = 0; j < 8; j += 2) {
            int col2 = colv[j];
            fst(smc+A0_OFF, rA, col2,
                (v[0][j]-m0)*i0*ln1_g[col2]+ln1_b[col2],
                (v[0][j+1]-m0)*i0*ln1_g[col2+1]+ln1_b[col2+1]);
            fst(smc+A0_OFF, rA+8, col2,
                (v[1][j]-m1)*i1*ln1_g[col2]+ln1_b[col2],
                (v[1][j+1]-m1)*i1*ln1_g[col2+1]+ln1_b[col2+1]);
        }
    }
    cp_wait0();
    __syncthreads();

    for (int li = 0; li < LL; li++) {
        const int tb = li * 12;

        // ================= stage qk (slot 0 holds q,k) =================
        prefetch_w(su, W1_OFF, tb + 2, 2);          // v, proj
        {
            float d[2][2][4];
            mma_compute(su, A0_OFF, W0_OFF, d);
            frag_to_f32(d, outF);                   // q
            mma_compute(su, A0_OFF, W0_OFF + 8192, d);
            frag_to_f32(d, kF);                     // k
        }
        cp_wait0(); __syncthreads();

        // ================= stage v + attention + proj =================
        prefetch_w(su, W0_OFF, tb + 4, 2);          // w1_0, w2_0
        {
            float d[2][2][4];
            mma_compute(su, A0_OFF, W1_OFF, d);     // v in regs

            // ---- S phase (overlaps v-MMA completion) ----
            {
                int s   = tid / 40;
                int rem = tid % 40;
                int h   = rem / 10;
                int q   = rem % 10;
                const float4* qp = reinterpret_cast<const float4*>(outF + (s*TT + q) * OUT_STR + h * 16);
                float4 qv[4];
#pragma unroll
                for (int dd = 0; dd < 4; dd++) qv[dd] = qp[dd];
                float sc[TT];
                float mx = -1e30f;
                for (int kk = 0; kk <= q; kk++) {
                    const float4* kp = reinterpret_cast<const float4*>(kF + (s*TT + kk) * OUT_STR + h * 16);
                    float a = 0.f;
#pragma unroll
                    for (int dd = 0; dd < 4; dd++) {
                        float4 kv = kp[dd];
                        a = fmaf(qv[dd].x, kv.x, a);
                        a = fmaf(qv[dd].y, kv.y, a);
                        a = fmaf(qv[dd].z, kv.z, a);
                        a = fmaf(qv[dd].w, kv.w, a);
                    }
                    a *= 0.25f;
                    sc[kk] = a;
                    mx = fmaxf(mx, a);
                }
                float ss = 0.f;
                for (int kk = 0; kk <= q; kk++) { sc[kk] = __expf(sc[kk] - mx); ss += sc[kk]; }
                float inv = __fdividef(1.f, ss);
                float* sp = SB + ((s * 4 + h) * TT + q) * TT;
#pragma unroll
                for (int kk = 0; kk < TT; kk++) sp[kk] = (kk <= q) ? sc[kk] * inv : 0.f;
            }
            __syncthreads();           // S done; q reads done -> safe to overwrite outF

            frag_to_f32(d, outF);      // v -> outF
        }
        __syncthreads();               // v visible

        // ---- y phase ----
        {
            int er = tid >> 2;
            int s = er / TT, q = er % TT;
            int h = tid & 3;
            const float* sp = SB + ((s * 4 + h) * TT + q) * TT;
            float y[16];
#pragma unroll
            for (int i = 0; i < 16; i++) y[i] = 0.f;
            for (int kk = 0; kk < TT; kk++) {
                float wgt = sp[kk];
                const float4* vp = reinterpret_cast<const float4*>(outF + (s*TT + kk) * OUT_STR + h * 16);
#pragma unroll
                for (int dd = 0; dd < 4; dd++) {
                    float4 vv = vp[dd];
                    y[dd*4+0] = fmaf(wgt, vv.x, y[dd*4+0]);
                    y[dd*4+1] = fmaf(wgt, vv.y, y[dd*4+1]);
                    y[dd*4+2] = fmaf(wgt, vv.z, y[dd*4+2]);
                    y[dd*4+3] = fmaf(wgt, vv.w, y[dd*4+3]);
                }
            }
            st_a16(smc + A1_OFF, er, h * 16, y);
        }
        __syncthreads();               // A1 (y) visible

        // ---- proj (slot 1, tile +8192) ----
        {
            float d[2][2][4];
            mma_compute(su, A1_OFF, W1_OFF + 8192, d);
            float v[2][8];
#pragma unroll
            for (int j = 0; j < 8; j++) {
                int c = j>>2, t = (j>>1)&1, e = j&1;
                v[0][j] = d[c][t][e]   + hreg[0][j]; hreg[0][j] = v[0][j];
                v[1][j] = d[c][t][2+e] + hreg[1][j]; hreg[1][j] = v[1][j];
            }
            float m[2], iv[2];
            frag_ln(v, rA, hf, mt, lane, red2, m, iv);
            const float* g = ln2_g + li*DD;
            const float* b = ln2_b + li*DD;
#pragma unroll
            for (int j = 0; j < 8; j += 2) {
                int col2 = colv[j];
                fst(smc+A0_OFF, rA, col2,
                    (v[0][j]-m[0])*iv[0]*g[col2]+b[col2],
                    (v[0][j+1]-m[0])*iv[0]*g[col2+1]+b[col2+1]);
                fst(smc+A0_OFF, rA+8, col2,
                    (v[1][j]-m[1])*iv[1]*g[col2]+b[col2],
                    (v[1][j+1]-m[1])*iv[1]*g[col2+1]+b[col2+1]);
            }
        }
        cp_wait0(); __syncthreads();

        // ================= merged FFN stages (4) =================
        for (int ft = 0; ft < 4; ft++) {
            const uint32_t cur = (ft & 1) ? W1_OFF : W0_OFF;
            const uint32_t nxt = (ft & 1) ? W0_OFF : W1_OFF;
            if (ft < 3)      prefetch_w(su, nxt, tb + 6 + 2*ft, 2);
            else if (li < 2) prefetch_w(su, nxt, tb + 12, 2);   // next layer (q,k)

            // ffn1 chunk: z = gelu(A0 @ w1_ft + b1) -> A1 (pair-local rows)
            {
                float d[2][2][4];
                mma_compute(su, A0_OFF, cur, d);
                const float* b1 = ffn_b1 + li*FF + ft*64;
#pragma unroll
                for (int j = 0; j < 8; j += 2) {
                    int c = j>>2, t = (j>>1)&1;
                    int col2 = colv[j];
                    fst(smc+A1_OFF, rA, col2,
                        gelu_fast(d[c][t][0] + b1[col2]),
                        gelu_fast(d[c][t][1] + b1[col2+1]));
                    fst(smc+A1_OFF, rA+8, col2,
                        gelu_fast(d[c][t][2] + b1[col2]),
                        gelu_fast(d[c][t][3] + b1[col2+1]));
                }
            }
            // pair-local sync: both warps of mt wrote their z columns
            asm volatile("bar.sync %0, 64;" :: "r"(mt + 1) : "memory");

            // ffn2 chunk: hreg += z @ w2_ft (+b2 at ft0); LN at ft3
            {
                float d[2][2][4];
                mma_compute(su, A1_OFF, cur + 8192, d);
#pragma unroll
                for (int j = 0; j < 8; j++) {
                    int c = j>>2, t = (j>>1)&1, e = j&1;
                    float add0 = d[c][t][e], add1 = d[c][t][2+e];
                    if (ft == 0) {
                        float bb = ffn_b2[li*DD + colv[j]];
                        add0 += bb; add1 += bb;
                    }
                    hreg[0][j] += add0;
                    hreg[1][j] += add1;
                }
                if (ft == 3) {
                    float m[2], iv[2];
                    frag_ln(hreg, rA, hf, mt, lane, red2, m, iv);
                    if (li < 2) {
                        const float* g = ln1_g + (li+1)*DD;
                        const float* b = ln1_b + (li+1)*DD;
#pragma unroll
                        for (int j = 0; j < 8; j += 2) {
                            int col2 = colv[j];
                            fst(smc+A0_OFF, rA, col2,
                                (hreg[0][j]-m[0])*iv[0]*g[col2]+b[col2],
                                (hreg[0][j+1]-m[0])*iv[0]*g[col2+1]+b[col2+1]);
                            fst(smc+A0_OFF, rA+8, col2,
                                (hreg[1][j]-m[1])*iv[1]*g[col2]+b[col2],
                                (hreg[1][j+1]-m[1])*iv[1]*g[col2+1]+b[col2+1]);
                        }
                    } else {
#pragma unroll
                        for (int j = 0; j < 8; j += 2) {
                            int col2 = colv[j];
                            *reinterpret_cast<float2*>(outF + rA*OUT_STR + col2) =
                                make_float2((hreg[0][j]-m[0])*iv[0]*lnf_g[col2]+lnf_b[col2],
                                            (hreg[0][j+1]-m[0])*iv[0]*lnf_g[col2+1]+lnf_b[col2+1]);
                            *reinterpret_cast<float2*>(outF + (rA+8)*OUT_STR + col2) =
                                make_float2((hreg[1][j]-m[1])*iv[1]*lnf_g[col2]+lnf_b[col2],
                                            (hreg[1][j+1]-m[1])*iv[1]*lnf_g[col2+1]+lnf_b[col2+1]);
                        }
                    }
                }
            }
            cp_wait0(); __syncthreads();
        }
    }

    // -------- head --------
    if (tid < NSEQ * TT) {
        int s = tid / TT;
        int j = tid % TT;
        const float* r = outF + (s * TT + TT - 1) * OUT_STR;
        float a = head_b[j];
#pragma unroll 16
        for (int dd = 0; dd < DD; dd++) a = fmaf(r[dd], head_w[dd * 10 + j], a);
        out[(blockIdx.x * NSEQ + s) * 10 + j] = a;
    }
}

extern "C" void kernel_launch(void* const* d_in, const int* in_sizes, int n_in,
                              void* d_out, int out_size)
{
    const float* x       = (const float*)d_in[0];
    const float* embed_w = (const float*)d_in[1];
    const float* embed_b = (const float*)d_in[2];
    const float* ln1_g   = (const float*)d_in[3];
    const float* ln1_b   = (const float*)d_in[4];
    const float* qkv_w   = (const float*)d_in[5];
    const float* proj_w  = (const float*)d_in[6];
    const float* ln2_g   = (const float*)d_in[7];
    const float* ln2_b   = (const float*)d_in[8];
    const float* ffn_w1  = (const float*)d_in[9];
    const float* ffn_b1  = (const float*)d_in[10];
    const float* ffn_w2  = (const float*)d_in[11];
    const float* ffn_b2  = (const float*)d_in[12];
    const float* lnf_g   = (const float*)d_in[13];
    const float* lnf_b   = (const float*)d_in[14];
    const float* head_w  = (const float*)d_in[15];
    const float* head_b  = (const float*)d_in[16];
    float* out = (float*)d_out;

    int nTokens = in_sizes[0] / 4;       // B*T
    int grid = nTokens / MROWS;          // 2048

    // prologue: convert weights into fp16 swizzled tiles (deterministic, capture-safe)
    prep_wtiles<<<36, 256>>>(qkv_w, proj_w, ffn_w1, ffn_w2);

    cudaFuncSetAttribute(waypoint_mma_kernel,
                         cudaFuncAttributeMaxDynamicSharedMemorySize, SMEM_BYTES);

    waypoint_mma_kernel<<<grid, NTH, SMEM_BYTES>>>(
        x, embed_w, embed_b, ln1_g, ln1_b,
        ln2_g, ln2_b, ffn_b1, ffn_b2,
        lnf_g, lnf_b, head_w, head_b, out);
}

// round 15
// speedup vs baseline: 3.5062x; 1.1618x over previous
#include <cuda_runtime.h>
#include <cuda_fp16.h>
#include <cstdint>

// ---------------- problem constants ----------------
#define TT 10
#define DD 64
#define LL 3
#define FF 256
#define NSEQ 8
#define MROWS 80
#define NTH 320

// ---------------- SMEM layout (bytes) ----------------
#define OUT_OFF 0        // fp32 [80][68] = 21760 (q / final lnf)
#define OUT_STR 68
#define A0_OFF  21760    // fp16 [80][64] xor-swizzled, 128B rows (10240) -> 32000
#define KF_OFF  32000    // fp32 [80][68] = 21760 -> 53760 (aliases A1)
#define A1_OFF  32000    // fp16 tile 10240 -> 42240, inside KF region
#define VH_OFF  53760    // fp16 v tile 10240 -> 64000
#define W0_OFF  64000    // W slot 0: 2 fp16 tiles (16384) -> 80384
#define W1_OFF  80384    // W slot 1: 16384 -> 96768
#define S_OFF   96768    // fp32 [8][4][10][10] = 12800 -> 109568
#define RED_OFF 109568   // float2 [80][2] = 1280 -> 110848
#define SMEM_BYTES 110848

// Pre-converted swizzled fp16 weight tiles: 36 tiles x 8192 B
// layer li: 12li+{0:q,1:k,2:v,3:proj,4:w1_0,5:w2_0,6:w1_1,7:w2_1,8:w1_2,9:w2_2,10:w1_3,11:w2_3}
__device__ unsigned char g_wtiles[36 * 8192];

// ---------------- helpers ----------------
__device__ __forceinline__ uint32_t smem_u32_of(const void* p) {
    uint32_t a;
    asm("{ .reg .u64 t; cvta.to.shared.u64 t, %1; cvt.u32.u64 %0, t; }" : "=r"(a) : "l"(p));
    return a;
}

__device__ __forceinline__ void ldm4(uint32_t& r0, uint32_t& r1, uint32_t& r2, uint32_t& r3,
                                     uint32_t a) {
    asm volatile("ldmatrix.sync.aligned.m8n8.x4.shared.b16 {%0,%1,%2,%3}, [%4];"
                 : "=r"(r0), "=r"(r1), "=r"(r2), "=r"(r3) : "r"(a));
}

__device__ __forceinline__ void stm4(uint32_t a, uint32_t r0, uint32_t r1,
                                     uint32_t r2, uint32_t r3) {
    asm volatile("stmatrix.sync.aligned.m8n8.x4.shared.b16 [%0], {%1,%2,%3,%4};"
                 :: "r"(a), "r"(r0), "r"(r1), "r"(r2), "r"(r3) : "memory");
}

__device__ __forceinline__ void mma16816(float* d,
                                         uint32_t a0, uint32_t a1, uint32_t a2, uint32_t a3,
                                         uint32_t b0, uint32_t b1) {
    asm volatile("mma.sync.aligned.m16n8k16.row.col.f32.f16.f16.f32 "
                 "{%0,%1,%2,%3}, {%4,%5,%6,%7}, {%8,%9}, {%0,%1,%2,%3};"
                 : "+f"(d[0]), "+f"(d[1]), "+f"(d[2]), "+f"(d[3])
                 : "r"(a0), "r"(a1), "r"(a2), "r"(a3), "r"(b0), "r"(b1));
}

__device__ __forceinline__ void cp16(uint32_t dst, const void* src) {
    asm volatile("cp.async.cg.shared.global [%0], [%1], 16;" :: "r"(dst), "l"(src));
}
__device__ __forceinline__ void cp_commit() {
    asm volatile("cp.async.commit_group;" ::: "memory");
}
__device__ __forceinline__ void cp_wait0() {
    asm volatile("cp.async.wait_group 0;" ::: "memory");
}

__device__ __forceinline__ float gelu_fast(float v) {
    float t = fabsf(v) * 0.70710678118654752f;
    float u = __fdividef(1.0f, fmaf(0.3275911f, t, 1.0f));
    float p = fmaf(1.061405429f, u, -1.453152027f);
    p = fmaf(p, u, 1.421413741f);
    p = fmaf(p, u, -0.284496736f);
    p = fmaf(p, u, 0.254829592f);
    p *= u;
    float e = __expf(-t * t);
    float erf_abs = fmaf(-p, e, 1.0f);
    return 0.5f * v * (1.0f + copysignf(erf_abs, v));
}

__device__ __forceinline__ float sum4(float v) {
    v += __shfl_xor_sync(0xffffffffu, v, 1);
    v += __shfl_xor_sync(0xffffffffu, v, 2);
    return v;
}

__device__ __forceinline__ uint32_t pack1(float x0, float x1) {
    __half2 hp = __floats2half2_rn(x0, x1);
    return *reinterpret_cast<uint32_t*>(&hp);
}

// Store a fragment-layout value array v[2][8] (rows rA, rA+8; j = c*4+t*2+e)
// into the xor-swizzled fp16 tile at tile_su via 2x stmatrix.x4.
// Matrix k = lane>>3 maps to (t = k>>1, rh = k&1); lane&7 = row-in-matrix.
__device__ __forceinline__ void frag_store_tile(uint32_t tile_su, int mt, int hf, int lane,
                                                const float v[2][8])
{
    const int t_ = (lane >> 4) & 1;
    const int rh = (lane >> 3) & 1;
    const int jj = lane & 7;
    const int row = mt * 16 + rh * 8 + jj;
#pragma unroll
    for (int cg = 0; cg < 2; cg++) {
        int col8 = hf * 4 + cg * 2 + t_;
        uint32_t addr = tile_su + (uint32_t)row * 128
                      + ((uint32_t)(col8 ^ (row & 7)) << 4);
        uint32_t r0 = pack1(v[0][cg*4 + 0], v[0][cg*4 + 1]);   // (t0, rh0)
        uint32_t r1 = pack1(v[1][cg*4 + 0], v[1][cg*4 + 1]);   // (t0, rh1)
        uint32_t r2 = pack1(v[0][cg*4 + 2], v[0][cg*4 + 3]);   // (t1, rh0)
        uint32_t r3 = pack1(v[1][cg*4 + 2], v[1][cg*4 + 3]);   // (t1, rh1)
        stm4(addr, r0, r1, r2, r3);
    }
}

// row-major 16-value store (er-layout) used by the attention y-phase
__device__ __forceinline__ void st_a16(char* t, int row, int c0, const float* v) {
    const uint32_t sw = (uint32_t)(row & 7);
#pragma unroll
    for (int g = 0; g < 2; g++) {
        uint32_t ph[4];
#pragma unroll
        for (int i = 0; i < 4; i++)
            ph[i] = pack1(v[g*8 + 2*i], v[g*8 + 2*i + 1]);
        uint32_t chunk = ((uint32_t)(c0 >> 3) + g) ^ sw;
        *reinterpret_cast<uint4*>(t + row*128 + chunk*16) = make_uint4(ph[0], ph[1], ph[2], ph[3]);
    }
}

__device__ __forceinline__ const float* wptr_for(int st, int& ldg,
    const float* qkv_w, const float* proj_w, const float* w1, const float* w2)
{
    int li = st / 12, k = st % 12;
    switch (k) {
        case 0:  ldg = 192; return qkv_w + li * 64 * 192;
        case 1:  ldg = 192; return qkv_w + li * 64 * 192 + 64;
        case 2:  ldg = 192; return qkv_w + li * 64 * 192 + 128;
        case 3:  ldg = 64;  return proj_w + li * 64 * 64;
        case 4: case 6: case 8: case 10: {
            int ft = (k - 4) >> 1; ldg = 256; return w1 + li * 64 * 256 + ft * 64;
        }
        default: {
            int ft = (k - 5) >> 1; ldg = 64;  return w2 + li * 256 * 64 + ft * 64 * 64;
        }
    }
}

// ---------------- prologue: convert all weight tiles to swizzled fp16 once ----
__global__ void prep_wtiles(const float* __restrict__ qkv_w, const float* __restrict__ proj_w,
                            const float* __restrict__ ffn_w1, const float* __restrict__ ffn_w2)
{
    int st = blockIdx.x;
    int ldg;
    const float* g = wptr_for(st, ldg, qkv_w, proj_w, ffn_w1, ffn_w2);
    unsigned char* hi = g_wtiles + st * 8192;

    int t = threadIdx.x;          // 256 threads
    int n = t & 63, kb = t >> 6;
    const uint32_t sw = (uint32_t)(n & 7);
#pragma unroll
    for (int gg = 0; gg < 2; gg++) {
        uint32_t ph[4];
#pragma unroll
        for (int i = 0; i < 4; i++) {
            int k0 = kb * 16 + gg * 8 + 2 * i;
            ph[i] = pack1(g[k0 * ldg + n], g[(k0 + 1) * ldg + n]);
        }
        uint32_t chunk = ((uint32_t)(2*kb + gg)) ^ sw;
        *reinterpret_cast<uint4*>(hi + n*128 + chunk*16) = make_uint4(ph[0], ph[1], ph[2], ph[3]);
    }
}

// prefetch cnt (1 or 2) contiguous tiles starting at t0 into slot
__device__ __forceinline__ void prefetch_w(uint32_t su, uint32_t slot, int t0, int cnt) {
    if (threadIdx.x < 256) {
        uint32_t dst = su + slot + (uint32_t)threadIdx.x * 32;
        const unsigned char* s0 = g_wtiles + (size_t)t0 * 8192 + threadIdx.x * 32;
        cp16(dst, s0);
        cp16(dst + 16, s0 + 16);
        if (cnt == 2) {
            cp16(dst + 8192, s0 + 8192);
            cp16(dst + 8192 + 16, s0 + 8192 + 16);
        }
    }
    cp_commit();
}

// ---------------- MMA mainloop: single-pass fp16 x fp16 ----------
__device__ __forceinline__ void mma_compute(uint32_t su, uint32_t aoff,
                                            uint32_t woff, float d[2][2][4])
{
    const int w    = threadIdx.x >> 5;
    const int lane = threadIdx.x & 31;
    const int mt = w >> 1;
    const int hf = w & 1;
    const int rl = (lane & 7) | (((lane >> 3) & 1) << 3);
    const int klane = lane >> 4;
    const int l7 = lane & 7;

    const uint32_t aB = su + aoff + (uint32_t)(mt*16 + rl) * 128;
    const uint32_t bB = su + woff + (uint32_t)(hf*32 + rl) * 128;

#pragma unroll
    for (int c = 0; c < 2; c++)
#pragma unroll
        for (int t = 0; t < 2; t++)
#pragma unroll
            for (int j = 0; j < 4; j++) d[c][t][j] = 0.f;

#pragma unroll
    for (int ks = 0; ks < 4; ks++) {
        const uint32_t coff = (uint32_t)(((ks*2 + klane) ^ l7) << 4);
        uint32_t a0, a1, a2, a3;
        uint32_t b00, b01, b02, b03, b10, b11, b12, b13;
        ldm4(a0, a1, a2, a3, aB + coff);
        ldm4(b00, b01, b02, b03, bB + coff);
        ldm4(b10, b11, b12, b13, bB + 2048u + coff);
        mma16816(d[0][0], a0, a1, a2, a3, b00, b02);
        mma16816(d[0][1], a0, a1, a2, a3, b01, b03);
        mma16816(d[1][0], a0, a1, a2, a3, b10, b12);
        mma16816(d[1][1], a0, a1, a2, a3, b11, b13);
    }
}

__device__ __forceinline__ void frag_to_f32(const float d[2][2][4], float* dstF) {
    const int w    = threadIdx.x >> 5;
    const int lane = threadIdx.x & 31;
    const int mt = w >> 1, hf = w & 1;
    const int r0 = mt*16 + (lane >> 2);
    const int cb = (lane & 3) * 2;
#pragma unroll
    for (int c = 0; c < 2; c++) {
        int cg = hf*2 + c;
#pragma unroll
        for (int t = 0; t < 2; t++) {
            *reinterpret_cast<float2*>(dstF + r0 * OUT_STR + cg*16 + cb + t*8) =
                make_float2(d[c][t][0], d[c][t][1]);
            *reinterpret_cast<float2*>(dstF + (r0 + 8) * OUT_STR + cg*16 + cb + t*8) =
                make_float2(d[c][t][2], d[c][t][3]);
        }
    }
}

__device__ __forceinline__ void frag_ln(const float v[2][8], int rA, int hf, int mt, int lane,
                                        float2* red2, float m[2], float iv[2])
{
    float s0 = 0.f, q0 = 0.f, s1 = 0.f, q1 = 0.f;
#pragma unroll
    for (int j = 0; j < 8; j++) {
        s0 += v[0][j]; q0 += v[0][j]*v[0][j];
        s1 += v[1][j]; q1 += v[1][j]*v[1][j];
    }
    s0 = sum4(s0); q0 = sum4(q0); s1 = sum4(s1); q1 = sum4(q1);
    if ((lane & 3) == 0) {
        red2[rA*2 + hf]     = make_float2(s0, q0);
        red2[(rA+8)*2 + hf] = make_float2(s1, q1);
    }
    asm volatile("bar.sync %0, %1;" :: "r"(mt + 1), "r"(64) : "memory");
    float2 o0 = red2[rA*2 + (hf^1)];
    float2 o1 = red2[(rA+8)*2 + (hf^1)];
    float S0 = s0 + o0.x, Q0 = q0 + o0.y;
    float S1 = s1 + o1.x, Q1 = q1 + o1.y;
    m[0] = S0 * (1.f/64.f);
    iv[0] = rsqrtf(Q0 * (1.f/64.f) - m[0]*m[0] + 1e-5f);
    m[1] = S1 * (1.f/64.f);
    iv[1] = rsqrtf(Q1 * (1.f/64.f) - m[1]*m[1] + 1e-5f);
}

// =====================================================================
__global__ __launch_bounds__(NTH, 2)
void waypoint_mma_kernel(
    const float* __restrict__ x,
    const float* __restrict__ embed_w, const float* __restrict__ embed_b,
    const float* __restrict__ ln1_g,   const float* __restrict__ ln1_b,
    const float* __restrict__ ln2_g,   const float* __restrict__ ln2_b,
    const float* __restrict__ ffn_b1,  const float* __restrict__ ffn_b2,
    const float* __restrict__ lnf_g,   const float* __restrict__ lnf_b,
    const float* __restrict__ head_w,  const float* __restrict__ head_b,
    float* __restrict__ out)
{
    extern __shared__ char smc[];
    const uint32_t su = smem_u32_of(smc);
    float*  outF = reinterpret_cast<float*>(smc + OUT_OFF);
    float*  kF   = reinterpret_cast<float*>(smc + KF_OFF);
    float*  SB   = reinterpret_cast<float*>(smc + S_OFF);
    float2* red2 = reinterpret_cast<float2*>(smc + RED_OFF);

    const int tid  = threadIdx.x;
    const int w    = tid >> 5;
    const int lane = tid & 31;
    const int mt   = w >> 1;
    const int hf   = w & 1;
    const int rA   = mt*16 + (lane >> 2);
    const int cb   = (lane & 3) * 2;
    const int rowBase = blockIdx.x * MROWS;

    int colv[8];
#pragma unroll
    for (int j = 0; j < 8; j++)
        colv[j] = hf*32 + (j>>2)*16 + ((j>>1)&1)*8 + cb + (j&1);

    float hreg[2][8];   // residual stream, fragment layout

    // preload layer-0 (q,k) into slot 0 (overlaps embed)
    prefetch_w(su, W0_OFF, 0, 2);

    // -------- embed + ln1(layer0) -> A0, fragment layout --------
    {
        float v[2][8];
#pragma unroll
        for (int r = 0; r < 2; r++) {
            int row = rA + 8*r;
            float4 xv = reinterpret_cast<const float4*>(x)[rowBase + row];
#pragma unroll
            for (int j = 0; j < 8; j++) {
                int col = colv[j];
                float a = embed_b[col];
                a = fmaf(xv.x, embed_w[col],       a);
                a = fmaf(xv.y, embed_w[64 + col],  a);
                a = fmaf(xv.z, embed_w[128 + col], a);
                a = fmaf(xv.w, embed_w[192 + col], a);
                v[r][j] = a; hreg[r][j] = a;
            }
        }
        float s0=0,q0=0,s1=0,q1=0;
#pragma unroll
        for (int j = 0; j < 8; j++) {
            s0 += v[0][j]; q0 += v[0][j]*v[0][j];
            s1 += v[1][j]; q1 += v[1][j]*v[1][j];
        }
        s0=sum4(s0); q0=sum4(q0); s1=sum4(s1); q1=sum4(q1);
        if ((lane & 3) == 0) {
            red2[rA*2 + hf]     = make_float2(s0, q0);
            red2[(rA+8)*2 + hf] = make_float2(s1, q1);
        }
        __syncthreads();
        float2 o0 = red2[rA*2 + (hf^1)];
        float2 o1 = red2[(rA+8)*2 + (hf^1)];
        float m0 = (s0+o0.x)*(1.f/64.f), i0 = rsqrtf((q0+o0.y)*(1.f/64.f)-m0*m0+1e-5f);
        float m1 = (s1+o1.x)*(1.f/64.f), i1 = rsqrtf((q1+o1.y)*(1.f/64.f)-m1*m1+1e-5f);
        float o[2][8];
#pragma unroll
        for (int j = 0; j < 8; j++) {
            int col = colv[j];
            o[0][j] = (v[0][j]-m0)*i0*ln1_g[col]+ln1_b[col];
            o[1][j] = (v[1][j]-m1)*i1*ln1_g[col]+ln1_b[col];
        }
        frag_store_tile(su + A0_OFF, mt, hf, lane, o);
    }
    cp_wait0();
    __syncthreads();

    for (int li = 0; li < LL; li++) {
        const int tb = li * 12;

        // ================= stage qk (slot 0 holds q,k) =================
        prefetch_w(su, W1_OFF, tb + 2, 2);          // v, proj
        {
            float d[2][2][4];
            mma_compute(su, A0_OFF, W0_OFF, d);
            frag_to_f32(d, outF);                   // q
            mma_compute(su, A0_OFF, W0_OFF + 8192, d);
            frag_to_f32(d, kF);                     // k
        }
        cp_wait0(); __syncthreads();

        // ================= stage v + attention + proj =================
        prefetch_w(su, W0_OFF, tb + 4, 2);          // w1_0, w2_0
        {
            float d[2][2][4];
            mma_compute(su, A0_OFF, W1_OFF, d);     // v
            // v -> VH (fp16, stmatrix) immediately
            float vv[2][8];
#pragma unroll
            for (int j = 0; j < 8; j++) {
                int c = j>>2, t = (j>>1)&1, e = j&1;
                vv[0][j] = d[c][t][e];
                vv[1][j] = d[c][t][2+e];
            }
            frag_store_tile(su + VH_OFF, mt, hf, lane, vv);

            // ---- S phase ----
            {
                int s   = tid / 40;
                int rem = tid % 40;
                int h   = rem / 10;
                int q   = rem % 10;
                const float4* qp = reinterpret_cast<const float4*>(outF + (s*TT + q) * OUT_STR + h * 16);
                float4 qv[4];
#pragma unroll
                for (int dd = 0; dd < 4; dd++) qv[dd] = qp[dd];
                float sc[TT];
                float mx = -1e30f;
                for (int kk = 0; kk <= q; kk++) {
                    const float4* kp = reinterpret_cast<const float4*>(kF + (s*TT + kk) * OUT_STR + h * 16);
                    float a = 0.f;
#pragma unroll
                    for (int dd = 0; dd < 4; dd++) {
                        float4 kv = kp[dd];
                        a = fmaf(qv[dd].x, kv.x, a);
                        a = fmaf(qv[dd].y, kv.y, a);
                        a = fmaf(qv[dd].z, kv.z, a);
                        a = fmaf(qv[dd].w, kv.w, a);
                    }
                    a *= 0.25f;
                    sc[kk] = a;
                    mx = fmaxf(mx, a);
                }
                float ss = 0.f;
                for (int kk = 0; kk <= q; kk++) { sc[kk] = __expf(sc[kk] - mx); ss += sc[kk]; }
                float inv = __fdividef(1.f, ss);
                float* sp = SB + ((s * 4 + h) * TT + q) * TT;
#pragma unroll
                for (int kk = 0; kk < TT; kk++) sp[kk] = (kk <= q) ? sc[kk] * inv : 0.f;
            }
        }
        __syncthreads();               // S + VH visible; kF reads done

        // ---- y phase (reads VH fp16) ----
        {
            int er = tid >> 2;
            int s = er / TT, q = er % TT;
            int h = tid & 3;
            const float* sp = SB + ((s * 4 + h) * TT + q) * TT;
            float y[16];
#pragma unroll
            for (int i = 0; i < 16; i++) y[i] = 0.f;
            for (int kk = 0; kk < TT; kk++) {
                float wgt = sp[kk];
                int r = s*TT + kk;
                const char* base = smc + VH_OFF + r * 128;
                uint4 u0 = *reinterpret_cast<const uint4*>(base + (((h*2)     ^ (r & 7)) << 4));
                uint4 u1 = *reinterpret_cast<const uint4*>(base + (((h*2 + 1) ^ (r & 7)) << 4));
                uint32_t uw[8] = {u0.x, u0.y, u0.z, u0.w, u1.x, u1.y, u1.z, u1.w};
#pragma unroll
                for (int p = 0; p < 8; p++) {
                    float2 f = __half22float2(*reinterpret_cast<const __half2*>(&uw[p]));
                    y[p*2+0] = fmaf(wgt, f.x, y[p*2+0]);
                    y[p*2+1] = fmaf(wgt, f.y, y[p*2+1]);
                }
            }
            st_a16(smc + A1_OFF, er, h * 16, y);
        }
        __syncthreads();               // A1 (y) visible

        // ---- proj (slot 1, tile +8192) ----
        {
            float d[2][2][4];
            mma_compute(su, A1_OFF, W1_OFF + 8192, d);
            float v[2][8];
#pragma unroll
            for (int j = 0; j < 8; j++) {
                int c = j>>2, t = (j>>1)&1, e = j&1;
                v[0][j] = d[c][t][e]   + hreg[0][j]; hreg[0][j] = v[0][j];
                v[1][j] = d[c][t][2+e] + hreg[1][j]; hreg[1][j] = v[1][j];
            }
            float m[2], iv[2];
            frag_ln(v, rA, hf, mt, lane, red2, m, iv);
            const float* g = ln2_g + li*DD;
            const float* b = ln2_b + li*DD;
            float o[2][8];
#pragma unroll
            for (int j = 0; j < 8; j++) {
                int col = colv[j];
                o[0][j] = (v[0][j]-m[0])*iv[0]*g[col]+b[col];
                o[1][j] = (v[1][j]-m[1])*iv[1]*g[col]+b[col];
            }
            frag_store_tile(su + A0_OFF, mt, hf, lane, o);
        }
        cp_wait0(); __syncthreads();

        // ================= merged FFN stages (4) =================
        for (int ft = 0; ft < 4; ft++) {
            const uint32_t cur = (ft & 1) ? W1_OFF : W0_OFF;
            const uint32_t nxt = (ft & 1) ? W0_OFF : W1_OFF;
            if (ft < 3)      prefetch_w(su, nxt, tb + 6 + 2*ft, 2);
            else if (li < 2) prefetch_w(su, nxt, tb + 12, 2);   // next layer (q,k)

            // ffn1 chunk: z = gelu(A0 @ w1_ft + b1) -> A1 (pair-local rows)
            {
                float d[2][2][4];
                mma_compute(su, A0_OFF, cur, d);
                const float* b1 = ffn_b1 + li*FF + ft*64;
                float o[2][8];
#pragma unroll
                for (int j = 0; j < 8; j++) {
                    int c = j>>2, t = (j>>1)&1, e = j&1;
                    int col = colv[j];
                    o[0][j] = gelu_fast(d[c][t][e]   + b1[col]);
                    o[1][j] = gelu_fast(d[c][t][2+e] + b1[col]);
                }
                frag_store_tile(su + A1_OFF, mt, hf, lane, o);
            }
            // pair-local sync: both warps of mt wrote their z columns
            asm volatile("bar.sync %0, 64;" :: "r"(mt + 1) : "memory");

            // ffn2 chunk: hreg += z @ w2_ft (+b2 at ft0); LN at ft3
            {
                float d[2][2][4];
                mma_compute(su, A1_OFF, cur + 8192, d);
#pragma unroll
                for (int j = 0; j < 8; j++) {
                    int c = j>>2, t = (j>>1)&1, e = j&1;
                    float add0 = d[c][t][e], add1 = d[c][t][2+e];
                    if (ft == 0) {
                        float bb = ffn_b2[li*DD + colv[j]];
                        add0 += bb; add1 += bb;
                    }
                    hreg[0][j] += add0;
                    hreg[1][j] += add1;
                }
                if (ft == 3) {
                    float m[2], iv[2];
                    frag_ln(hreg, rA, hf, mt, lane, red2, m, iv);
                    if (li < 2) {
                        const float* g = ln1_g + (li+1)*DD;
                        const float* b = ln1_b + (li+1)*DD;
                        float o[2][8];
#pragma unroll
                        for (int j = 0; j < 8; j++) {
                            int col = colv[j];
                            o[0][j] = (hreg[0][j]-m[0])*iv[0]*g[col]+b[col];
                            o[1][j] = (hreg[1][j]-m[1])*iv[1]*g[col]+b[col];
                        }
                        frag_store_tile(su + A0_OFF, mt, hf, lane, o);
                    } else {
#pragma unroll
                        for (int j = 0; j < 8; j += 2) {
                            int col2 = colv[j];
                            *reinterpret_cast<float2*>(outF + rA*OUT_STR + col2) =
                                make_float2((hreg[0][j]-m[0])*iv[0]*lnf_g[col2]+lnf_b[col2],
                                            (hreg[0][j+1]-m[0])*iv[0]*lnf_g[col2+1]+lnf_b[col2+1]);
                            *reinterpret_cast<float2*>(outF + (rA+8)*OUT_STR + col2) =
                                make_float2((hreg[1][j]-m[1])*iv[1]*lnf_g[col2]+lnf_b[col2],
                                            (hreg[1][j+1]-m[1])*iv[1]*lnf_g[col2+1]+lnf_b[col2+1]);
                        }
                    }
                }
            }
            cp_wait0(); __syncthreads();
        }
    }

    // -------- head --------
    if (tid < NSEQ * TT) {
        int s = tid / TT;
        int j = tid % TT;
        const float* r = outF + (s * TT + TT - 1) * OUT_STR;
        float a = head_b[j];
#pragma unroll 16
        for (int dd = 0; dd < DD; dd++) a = fmaf(r[dd], head_w[dd * 10 + j], a);
        out[(blockIdx.x * NSEQ + s) * 10 + j] = a;
    }
}

extern "C" void kernel_launch(void* const* d_in, const int* in_sizes, int n_in,
                              void* d_out, int out_size)
{
    const float* x       = (const float*)d_in[0];
    const float* embed_w = (const float*)d_in[1];
    const float* embed_b = (const float*)d_in[2];
    const float* ln1_g   = (const float*)d_in[3];
    const float* ln1_b   = (const float*)d_in[4];
    const float* qkv_w   = (const float*)d_in[5];
    const float* proj_w  = (const float*)d_in[6];
    const float* ln2_g   = (const float*)d_in[7];
    const float* ln2_b   = (const float*)d_in[8];
    const float* ffn_w1  = (const float*)d_in[9];
    const float* ffn_b1  = (const float*)d_in[10];
    const float* ffn_w2  = (const float*)d_in[11];
    const float* ffn_b2  = (const float*)d_in[12];
    const float* lnf_g   = (const float*)d_in[13];
    const float* lnf_b   = (const float*)d_in[14];
    const float* head_w  = (const float*)d_in[15];
    const float* head_b  = (const float*)d_in[16];
    float* out = (float*)d_out;

    int nTokens = in_sizes[0] / 4;       // B*T
    int grid = nTokens / MROWS;          // 2048

    // prologue: convert weights into fp16 swizzled tiles (deterministic, capture-safe)
    prep_wtiles<<<36, 256>>>(qkv_w, proj_w, ffn_w1, ffn_w2);

    cudaFuncSetAttribute(waypoint_mma_kernel,
                         cudaFuncAttributeMaxDynamicSharedMemorySize, SMEM_BYTES);

    waypoint_mma_kernel<<<grid, NTH, SMEM_BYTES>>>(
        x, embed_w, embed_b, ln1_g, ln1_b,
        ln2_g, ln2_b, ffn_b1, ffn_b2,
        lnf_g, lnf_b, head_w, head_b, out);
}

// round 16
// speedup vs baseline: 3.6146x; 1.0309x over previous
#include <cuda_runtime.h>
#include <cuda_fp16.h>
#include <cstdint>

// ---------------- problem constants ----------------
#define TT 10
#define DD 64
#define LL 3
#define FF 256
#define NSEQ 8
#define MROWS 80
#define NTH 320

// ---------------- SMEM layout (bytes) ----------------
#define OUT_OFF 0        // fp32 [80][68] = 21760 (q / final lnf)
#define OUT_STR 68
#define A0_OFF  21760    // fp16 [80][64] xor-swizzled, 128B rows (10240) -> 32000
#define KF_OFF  32000    // fp32 [80][68] = 21760 -> 53760 (aliases A1)
#define A1_OFF  32000    // fp16 tile 10240 -> 42240, inside KF region
#define VH_OFF  53760    // fp16 v tile 10240 -> 64000
#define W0_OFF  64000    // W slot 0: 2 fp16 tiles (16384) -> 80384
#define W1_OFF  80384    // W slot 1: 16384 -> 96768
#define S_OFF   96768    // fp32 [8][4][10][10] = 12800 -> 109568
#define RED_OFF 109568   // float2 [80][2] = 1280 -> 110848
#define SMEM_BYTES 110848

// Pre-converted swizzled fp16 weight tiles: 36 tiles x 8192 B
__device__ unsigned char g_wtiles[36 * 8192];

// ---------------- helpers ----------------
__device__ __forceinline__ uint32_t smem_u32_of(const void* p) {
    uint32_t a;
    asm("{ .reg .u64 t; cvta.to.shared.u64 t, %1; cvt.u32.u64 %0, t; }" : "=r"(a) : "l"(p));
    return a;
}

__device__ __forceinline__ void ldm4(uint32_t& r0, uint32_t& r1, uint32_t& r2, uint32_t& r3,
                                     uint32_t a) {
    asm volatile("ldmatrix.sync.aligned.m8n8.x4.shared.b16 {%0,%1,%2,%3}, [%4];"
                 : "=r"(r0), "=r"(r1), "=r"(r2), "=r"(r3) : "r"(a));
}

__device__ __forceinline__ void stm4(uint32_t a, uint32_t r0, uint32_t r1,
                                     uint32_t r2, uint32_t r3) {
    asm volatile("stmatrix.sync.aligned.m8n8.x4.shared.b16 [%0], {%1,%2,%3,%4};"
                 :: "r"(a), "r"(r0), "r"(r1), "r"(r2), "r"(r3) : "memory");
}

__device__ __forceinline__ void mma16816(float* d,
                                         uint32_t a0, uint32_t a1, uint32_t a2, uint32_t a3,
                                         uint32_t b0, uint32_t b1) {
    asm volatile("mma.sync.aligned.m16n8k16.row.col.f32.f16.f16.f32 "
                 "{%0,%1,%2,%3}, {%4,%5,%6,%7}, {%8,%9}, {%0,%1,%2,%3};"
                 : "+f"(d[0]), "+f"(d[1]), "+f"(d[2]), "+f"(d[3])
                 : "r"(a0), "r"(a1), "r"(a2), "r"(a3), "r"(b0), "r"(b1));
}

__device__ __forceinline__ void cp16(uint32_t dst, const void* src) {
    asm volatile("cp.async.cg.shared.global [%0], [%1], 16;" :: "r"(dst), "l"(src));
}
__device__ __forceinline__ void cp_commit() {
    asm volatile("cp.async.commit_group;" ::: "memory");
}
__device__ __forceinline__ void cp_wait0() {
    asm volatile("cp.async.wait_group 0;" ::: "memory");
}

__device__ __forceinline__ float gelu_fast(float v) {
    float t = fabsf(v) * 0.70710678118654752f;
    float u = __fdividef(1.0f, fmaf(0.3275911f, t, 1.0f));
    float p = fmaf(1.061405429f, u, -1.453152027f);
    p = fmaf(p, u, 1.421413741f);
    p = fmaf(p, u, -0.284496736f);
    p = fmaf(p, u, 0.254829592f);
    p *= u;
    float e = __expf(-t * t);
    float erf_abs = fmaf(-p, e, 1.0f);
    return 0.5f * v * (1.0f + copysignf(erf_abs, v));
}

__device__ __forceinline__ float sum4(float v) {
    v += __shfl_xor_sync(0xffffffffu, v, 1);
    v += __shfl_xor_sync(0xffffffffu, v, 2);
    return v;
}

__device__ __forceinline__ uint32_t pack1(float x0, float x1) {
    __half2 hp = __floats2half2_rn(x0, x1);
    return *reinterpret_cast<uint32_t*>(&hp);
}

// Store a fragment-layout value array v[2][8] into the xor-swizzled fp16 tile
// via 2x stmatrix.x4.
__device__ __forceinline__ void frag_store_tile(uint32_t tile_su, int mt, int hf, int lane,
                                                const float v[2][8])
{
    const int t_ = (lane >> 4) & 1;
    const int rh = (lane >> 3) & 1;
    const int jj = lane & 7;
    const int row = mt * 16 + rh * 8 + jj;
#pragma unroll
    for (int cg = 0; cg < 2; cg++) {
        int col8 = hf * 4 + cg * 2 + t_;
        uint32_t addr = tile_su + (uint32_t)row * 128
                      + ((uint32_t)(col8 ^ (row & 7)) << 4);
        uint32_t r0 = pack1(v[0][cg*4 + 0], v[0][cg*4 + 1]);
        uint32_t r1 = pack1(v[1][cg*4 + 0], v[1][cg*4 + 1]);
        uint32_t r2 = pack1(v[0][cg*4 + 2], v[0][cg*4 + 3]);
        uint32_t r3 = pack1(v[1][cg*4 + 2], v[1][cg*4 + 3]);
        stm4(addr, r0, r1, r2, r3);
    }
}

// row-major 16-value store used by the attention y-phase
__device__ __forceinline__ void st_a16(char* t, int row, int c0, const float* v) {
    const uint32_t sw = (uint32_t)(row & 7);
#pragma unroll
    for (int g = 0; g < 2; g++) {
        uint32_t ph[4];
#pragma unroll
        for (int i = 0; i < 4; i++)
            ph[i] = pack1(v[g*8 + 2*i], v[g*8 + 2*i + 1]);
        uint32_t chunk = ((uint32_t)(c0 >> 3) + g) ^ sw;
        *reinterpret_cast<uint4*>(t + row*128 + chunk*16) = make_uint4(ph[0], ph[1], ph[2], ph[3]);
    }
}

__device__ __forceinline__ const float* wptr_for(int st, int& ldg,
    const float* qkv_w, const float* proj_w, const float* w1, const float* w2)
{
    int li = st / 12, k = st % 12;
    switch (k) {
        case 0:  ldg = 192; return qkv_w + li * 64 * 192;
        case 1:  ldg = 192; return qkv_w + li * 64 * 192 + 64;
        case 2:  ldg = 192; return qkv_w + li * 64 * 192 + 128;
        case 3:  ldg = 64;  return proj_w + li * 64 * 64;
        case 4: case 6: case 8: case 10: {
            int ft = (k - 4) >> 1; ldg = 256; return w1 + li * 64 * 256 + ft * 64;
        }
        default: {
            int ft = (k - 5) >> 1; ldg = 64;  return w2 + li * 256 * 64 + ft * 64 * 64;
        }
    }
}

// ---------------- prologue: convert all weight tiles to swizzled fp16 once ----
__global__ void prep_wtiles(const float* __restrict__ qkv_w, const float* __restrict__ proj_w,
                            const float* __restrict__ ffn_w1, const float* __restrict__ ffn_w2)
{
    int st = blockIdx.x;
    int ldg;
    const float* g = wptr_for(st, ldg, qkv_w, proj_w, ffn_w1, ffn_w2);
    unsigned char* hi = g_wtiles + st * 8192;

    int t = threadIdx.x;          // 256 threads
    int n = t & 63, kb = t >> 6;
    const uint32_t sw = (uint32_t)(n & 7);
#pragma unroll
    for (int gg = 0; gg < 2; gg++) {
        uint32_t ph[4];
#pragma unroll
        for (int i = 0; i < 4; i++) {
            int k0 = kb * 16 + gg * 8 + 2 * i;
            ph[i] = pack1(g[k0 * ldg + n], g[(k0 + 1) * ldg + n]);
        }
        uint32_t chunk = ((uint32_t)(2*kb + gg)) ^ sw;
        *reinterpret_cast<uint4*>(hi + n*128 + chunk*16) = make_uint4(ph[0], ph[1], ph[2], ph[3]);
    }
}

// prefetch cnt (1 or 2) contiguous tiles starting at t0 into slot
__device__ __forceinline__ void prefetch_w(uint32_t su, uint32_t slot, int t0, int cnt) {
    if (threadIdx.x < 256) {
        uint32_t dst = su + slot + (uint32_t)threadIdx.x * 32;
        const unsigned char* s0 = g_wtiles + (size_t)t0 * 8192 + threadIdx.x * 32;
        cp16(dst, s0);
        cp16(dst + 16, s0 + 16);
        if (cnt == 2) {
            cp16(dst + 8192, s0 + 8192);
            cp16(dst + 8192 + 16, s0 + 8192 + 16);
        }
    }
    cp_commit();
}

// ---------------- MMA mainloop: single-pass fp16 x fp16 ----------
__device__ __forceinline__ void mma_compute(uint32_t su, uint32_t aoff,
                                            uint32_t woff, float d[2][2][4])
{
    const int w    = threadIdx.x >> 5;
    const int lane = threadIdx.x & 31;
    const int mt = w >> 1;
    const int hf = w & 1;
    const int rl = (lane & 7) | (((lane >> 3) & 1) << 3);
    const int klane = lane >> 4;
    const int l7 = lane & 7;

    const uint32_t aB = su + aoff + (uint32_t)(mt*16 + rl) * 128;
    const uint32_t bB = su + woff + (uint32_t)(hf*32 + rl) * 128;

#pragma unroll
    for (int c = 0; c < 2; c++)
#pragma unroll
        for (int t = 0; t < 2; t++)
#pragma unroll
            for (int j = 0; j < 4; j++) d[c][t][j] = 0.f;

#pragma unroll
    for (int ks = 0; ks < 4; ks++) {
        const uint32_t coff = (uint32_t)(((ks*2 + klane) ^ l7) << 4);
        uint32_t a0, a1, a2, a3;
        uint32_t b00, b01, b02, b03, b10, b11, b12, b13;
        ldm4(a0, a1, a2, a3, aB + coff);
        ldm4(b00, b01, b02, b03, bB + coff);
        ldm4(b10, b11, b12, b13, bB + 2048u + coff);
        mma16816(d[0][0], a0, a1, a2, a3, b00, b02);
        mma16816(d[0][1], a0, a1, a2, a3, b01, b03);
        mma16816(d[1][0], a0, a1, a2, a3, b10, b12);
        mma16816(d[1][1], a0, a1, a2, a3, b11, b13);
    }
}

__device__ __forceinline__ void frag_to_f32(const float d[2][2][4], float* dstF) {
    const int w    = threadIdx.x >> 5;
    const int lane = threadIdx.x & 31;
    const int mt = w >> 1, hf = w & 1;
    const int r0 = mt*16 + (lane >> 2);
    const int cb = (lane & 3) * 2;
#pragma unroll
    for (int c = 0; c < 2; c++) {
        int cg = hf*2 + c;
#pragma unroll
        for (int t = 0; t < 2; t++) {
            *reinterpret_cast<float2*>(dstF + r0 * OUT_STR + cg*16 + cb + t*8) =
                make_float2(d[c][t][0], d[c][t][1]);
            *reinterpret_cast<float2*>(dstF + (r0 + 8) * OUT_STR + cg*16 + cb + t*8) =
                make_float2(d[c][t][2], d[c][t][3]);
        }
    }
}

__device__ __forceinline__ void frag_ln(const float v[2][8], int rA, int hf, int mt, int lane,
                                        float2* red2, float m[2], float iv[2])
{
    float s0 = 0.f, q0 = 0.f, s1 = 0.f, q1 = 0.f;
#pragma unroll
    for (int j = 0; j < 8; j++) {
        s0 += v[0][j]; q0 += v[0][j]*v[0][j];
        s1 += v[1][j]; q1 += v[1][j]*v[1][j];
    }
    s0 = sum4(s0); q0 = sum4(q0); s1 = sum4(s1); q1 = sum4(q1);
    if ((lane & 3) == 0) {
        red2[rA*2 + hf]     = make_float2(s0, q0);
        red2[(rA+8)*2 + hf] = make_float2(s1, q1);
    }
    asm volatile("bar.sync %0, %1;" :: "r"(mt + 1), "r"(64) : "memory");
    float2 o0 = red2[rA*2 + (hf^1)];
    float2 o1 = red2[(rA+8)*2 + (hf^1)];
    float S0 = s0 + o0.x, Q0 = q0 + o0.y;
    float S1 = s1 + o1.x, Q1 = q1 + o1.y;
    m[0] = S0 * (1.f/64.f);
    iv[0] = rsqrtf(Q0 * (1.f/64.f) - m[0]*m[0] + 1e-5f);
    m[1] = S1 * (1.f/64.f);
    iv[1] = rsqrtf(Q1 * (1.f/64.f) - m[1]*m[1] + 1e-5f);
}

// =====================================================================
__global__ __launch_bounds__(NTH, 2)
void waypoint_mma_kernel(
    const float* __restrict__ x,
    const float* __restrict__ embed_w, const float* __restrict__ embed_b,
    const float* __restrict__ ln1_g,   const float* __restrict__ ln1_b,
    const float* __restrict__ ln2_g,   const float* __restrict__ ln2_b,
    const float* __restrict__ ffn_b1,  const float* __restrict__ ffn_b2,
    const float* __restrict__ lnf_g,   const float* __restrict__ lnf_b,
    const float* __restrict__ head_w,  const float* __restrict__ head_b,
    float* __restrict__ out)
{
    extern __shared__ char smc[];
    const uint32_t su = smem_u32_of(smc);
    float*  outF = reinterpret_cast<float*>(smc + OUT_OFF);
    float*  kF   = reinterpret_cast<float*>(smc + KF_OFF);
    float*  SB   = reinterpret_cast<float*>(smc + S_OFF);
    float2* red2 = reinterpret_cast<float2*>(smc + RED_OFF);

    const int tid  = threadIdx.x;
    const int w    = tid >> 5;
    const int lane = tid & 31;
    const int mt   = w >> 1;
    const int hf   = w & 1;
    const int rA   = mt*16 + (lane >> 2);
    const int cb   = (lane & 3) * 2;
    const int rowBase = blockIdx.x * MROWS;

    int colv[8];
#pragma unroll
    for (int j = 0; j < 8; j++)
        colv[j] = hf*32 + (j>>2)*16 + ((j>>1)&1)*8 + cb + (j&1);

    float hreg[2][8];   // residual stream, fragment layout

    // preload layer-0 (q,k) into slot 0 (overlaps embed)
    prefetch_w(su, W0_OFF, 0, 2);

    // -------- embed + ln1(layer0) -> A0, fragment layout --------
    {
        float v[2][8];
#pragma unroll
        for (int r = 0; r < 2; r++) {
            int row = rA + 8*r;
            float4 xv = reinterpret_cast<const float4*>(x)[rowBase + row];
#pragma unroll
            for (int j = 0; j < 8; j++) {
                int col = colv[j];
                float a = embed_b[col];
                a = fmaf(xv.x, embed_w[col],       a);
                a = fmaf(xv.y, embed_w[64 + col],  a);
                a = fmaf(xv.z, embed_w[128 + col], a);
                a = fmaf(xv.w, embed_w[192 + col], a);
                v[r][j] = a; hreg[r][j] = a;
            }
        }
        float s0=0,q0=0,s1=0,q1=0;
#pragma unroll
        for (int j = 0; j < 8; j++) {
            s0 += v[0][j]; q0 += v[0][j]*v[0][j];
            s1 += v[1][j]; q1 += v[1][j]*v[1][j];
        }
        s0=sum4(s0); q0=sum4(q0); s1=sum4(s1); q1=sum4(q1);
        if ((lane & 3) == 0) {
            red2[rA*2 + hf]     = make_float2(s0, q0);
            red2[(rA+8)*2 + hf] = make_float2(s1, q1);
        }
        __syncthreads();
        float2 o0 = red2[rA*2 + (hf^1)];
        float2 o1 = red2[(rA+8)*2 + (hf^1)];
        float m0 = (s0+o0.x)*(1.f/64.f), i0 = rsqrtf((q0+o0.y)*(1.f/64.f)-m0*m0+1e-5f);
        float m1 = (s1+o1.x)*(1.f/64.f), i1 = rsqrtf((q1+o1.y)*(1.f/64.f)-m1*m1+1e-5f);
        float o[2][8];
#pragma unroll
        for (int j = 0; j < 8; j++) {
            int col = colv[j];
            o[0][j] = (v[0][j]-m0)*i0*ln1_g[col]+ln1_b[col];
            o[1][j] = (v[1][j]-m1)*i1*ln1_g[col]+ln1_b[col];
        }
        frag_store_tile(su + A0_OFF, mt, hf, lane, o);
    }
    cp_wait0();
    __syncthreads();

    for (int li = 0; li < LL; li++) {
        const int tb = li * 12;

        // ================= stage qk (slot 0 holds q,k) =================
        prefetch_w(su, W1_OFF, tb + 2, 2);          // v, proj
        {
            float d[2][2][4];
            mma_compute(su, A0_OFF, W0_OFF, d);
            frag_to_f32(d, outF);                   // q
            mma_compute(su, A0_OFF, W0_OFF + 8192, d);
            frag_to_f32(d, kF);                     // k
        }
        cp_wait0(); __syncthreads();

        // ================= stage v + attention =================
        prefetch_w(su, W0_OFF, tb + 4, 2);          // w1_0, w2_0
        {
            float d[2][2][4];
            mma_compute(su, A0_OFF, W1_OFF, d);     // v
            // v -> VH (fp16, stmatrix) immediately
            float vv[2][8];
#pragma unroll
            for (int j = 0; j < 8; j++) {
                int c = j>>2, t = (j>>1)&1, e = j&1;
                vv[0][j] = d[c][t][e];
                vv[1][j] = d[c][t][2+e];
            }
            frag_store_tile(su + VH_OFF, mt, hf, lane, vv);

            // ---- S phase: warp w handles q=w, lane = (s,h) ----
            {
                const int qq = w;                   // 0..9, warp-uniform
                const int s  = lane >> 2;
                const int h  = lane & 3;
                const float4* qp = reinterpret_cast<const float4*>(outF + (s*TT + qq) * OUT_STR + h * 16);
                float4 qv[4];
#pragma unroll
                for (int dd = 0; dd < 4; dd++) qv[dd] = qp[dd];
                float sc[TT];
                float mx = -1e30f;
                for (int kk = 0; kk <= qq; kk++) {
                    const float4* kp = reinterpret_cast<const float4*>(kF + (s*TT + kk) * OUT_STR + h * 16);
                    float a = 0.f;
#pragma unroll
                    for (int dd = 0; dd < 4; dd++) {
                        float4 kv = kp[dd];
                        a = fmaf(qv[dd].x, kv.x, a);
                        a = fmaf(qv[dd].y, kv.y, a);
                        a = fmaf(qv[dd].z, kv.z, a);
                        a = fmaf(qv[dd].w, kv.w, a);
                    }
                    a *= 0.25f;
                    sc[kk] = a;
                    mx = fmaxf(mx, a);
                }
                float ss = 0.f;
                for (int kk = 0; kk <= qq; kk++) { sc[kk] = __expf(sc[kk] - mx); ss += sc[kk]; }
                float inv = __fdividef(1.f, ss);
                float* sp = SB + ((s * 4 + h) * TT + qq) * TT;
                for (int kk = 0; kk <= qq; kk++) sp[kk] = sc[kk] * inv;
            }
        }
        __syncthreads();               // S + VH visible; kF reads done

        // ---- y phase: warp w handles q=w, lane = (s,h); reads VH fp16 ----
        {
            const int qq = w;
            const int s  = lane >> 2;
            const int h  = lane & 3;
            const int rq = s * TT + qq;
            const float* sp = SB + ((s * 4 + h) * TT + qq) * TT;
            float y[16];
#pragma unroll
            for (int i = 0; i < 16; i++) y[i] = 0.f;
            for (int kk = 0; kk <= qq; kk++) {
                float wgt = sp[kk];
                int r = s*TT + kk;
                const char* base = smc + VH_OFF + r * 128;
                uint4 u0 = *reinterpret_cast<const uint4*>(base + (((h*2)     ^ (r & 7)) << 4));
                uint4 u1 = *reinterpret_cast<const uint4*>(base + (((h*2 + 1) ^ (r & 7)) << 4));
                uint32_t uw[8] = {u0.x, u0.y, u0.z, u0.w, u1.x, u1.y, u1.z, u1.w};
#pragma unroll
                for (int p = 0; p < 8; p++) {
                    float2 f = __half22float2(*reinterpret_cast<const __half2*>(&uw[p]));
                    y[p*2+0] = fmaf(wgt, f.x, y[p*2+0]);
                    y[p*2+1] = fmaf(wgt, f.y, y[p*2+1]);
                }
            }
            st_a16(smc + A1_OFF, rq, h * 16, y);
        }
        __syncthreads();               // A1 (y) visible

        // ---- proj (slot 1, tile +8192) ----
        {
            float d[2][2][4];
            mma_compute(su, A1_OFF, W1_OFF + 8192, d);
            float v[2][8];
#pragma unroll
            for (int j = 0; j < 8; j++) {
                int c = j>>2, t = (j>>1)&1, e = j&1;
                v[0][j] = d[c][t][e]   + hreg[0][j]; hreg[0][j] = v[0][j];
                v[1][j] = d[c][t][2+e] + hreg[1][j]; hreg[1][j] = v[1][j];
            }
            float m[2], iv[2];
            frag_ln(v, rA, hf, mt, lane, red2, m, iv);
            const float* g = ln2_g + li*DD;
            const float* b = ln2_b + li*DD;
            float o[2][8];
#pragma unroll
            for (int j = 0; j < 8; j++) {
                int col = colv[j];
                o[0][j] = (v[0][j]-m[0])*iv[0]*g[col]+b[col];
                o[1][j] = (v[1][j]-m[1])*iv[1]*g[col]+b[col];
            }
            frag_store_tile(su + A0_OFF, mt, hf, lane, o);
        }
        cp_wait0(); __syncthreads();

        // ================= merged FFN stages (4) =================
        for (int ft = 0; ft < 4; ft++) {
            const uint32_t cur = (ft & 1) ? W1_OFF : W0_OFF;
            const uint32_t nxt = (ft & 1) ? W0_OFF : W1_OFF;
            if (ft < 3)      prefetch_w(su, nxt, tb + 6 + 2*ft, 2);
            else if (li < 2) prefetch_w(su, nxt, tb + 12, 2);   // next layer (q,k)

            // ffn1 chunk: z = gelu(A0 @ w1_ft + b1) -> A1 (pair-local rows)
            {
                float d[2][2][4];
                mma_compute(su, A0_OFF, cur, d);
                const float* b1 = ffn_b1 + li*FF + ft*64;
                float o[2][8];
#pragma unroll
                for (int j = 0; j < 8; j++) {
                    int c = j>>2, t = (j>>1)&1, e = j&1;
                    int col = colv[j];
                    o[0][j] = gelu_fast(d[c][t][e]   + b1[col]);
                    o[1][j] = gelu_fast(d[c][t][2+e] + b1[col]);
                }
                frag_store_tile(su + A1_OFF, mt, hf, lane, o);
            }
            // pair-local sync: both warps of mt wrote their z columns
            asm volatile("bar.sync %0, 64;" :: "r"(mt + 1) : "memory");

            // ffn2 chunk: hreg += z @ w2_ft (+b2 at ft0); LN at ft3
            {
                float d[2][2][4];
                mma_compute(su, A1_OFF, cur + 8192, d);
#pragma unroll
                for (int j = 0; j < 8; j++) {
                    int c = j>>2, t = (j>>1)&1, e = j&1;
                    float add0 = d[c][t][e], add1 = d[c][t][2+e];
                    if (ft == 0) {
                        float bb = ffn_b2[li*DD + colv[j]];
                        add0 += bb; add1 += bb;
                    }
                    hreg[0][j] += add0;
                    hreg[1][j] += add1;
                }
                if (ft == 3) {
                    float m[2], iv[2];
                    frag_ln(hreg, rA, hf, mt, lane, red2, m, iv);
                    if (li < 2) {
                        const float* g = ln1_g + (li+1)*DD;
                        const float* b = ln1_b + (li+1)*DD;
                        float o[2][8];
#pragma unroll
                        for (int j = 0; j < 8; j++) {
                            int col = colv[j];
                            o[0][j] = (hreg[0][j]-m[0])*iv[0]*g[col]+b[col];
                            o[1][j] = (hreg[1][j]-m[1])*iv[1]*g[col]+b[col];
                        }
                        frag_store_tile(su + A0_OFF, mt, hf, lane, o);
                    } else {
#pragma unroll
                        for (int j = 0; j < 8; j += 2) {
                            int col2 = colv[j];
                            *reinterpret_cast<float2*>(outF + rA*OUT_STR + col2) =
                                make_float2((hreg[0][j]-m[0])*iv[0]*lnf_g[col2]+lnf_b[col2],
                                            (hreg[0][j+1]-m[0])*iv[0]*lnf_g[col2+1]+lnf_b[col2+1]);
                            *reinterpret_cast<float2*>(outF + (rA+8)*OUT_STR + col2) =
                                make_float2((hreg[1][j]-m[1])*iv[1]*lnf_g[col2]+lnf_b[col2],
                                            (hreg[1][j+1]-m[1])*iv[1]*lnf_g[col2+1]+lnf_b[col2+1]);
                        }
                    }
                }
            }
            cp_wait0(); __syncthreads();
        }
    }

    // -------- head --------
    if (tid < NSEQ * TT) {
        int s = tid / TT;
        int j = tid % TT;
        const float* r = outF + (s * TT + TT - 1) * OUT_STR;
        float a = head_b[j];
#pragma unroll 16
        for (int dd = 0; dd < DD; dd++) a = fmaf(r[dd], head_w[dd * 10 + j], a);
        out[(blockIdx.x * NSEQ + s) * 10 + j] = a;
    }
}

extern "C" void kernel_launch(void* const* d_in, const int* in_sizes, int n_in,
                              void* d_out, int out_size)
{
    const float* x       = (const float*)d_in[0];
    const float* embed_w = (const float*)d_in[1];
    const float* embed_b = (const float*)d_in[2];
    const float* ln1_g   = (const float*)d_in[3];
    const float* ln1_b   = (const float*)d_in[4];
    const float* qkv_w   = (const float*)d_in[5];
    const float* proj_w  = (const float*)d_in[6];
    const float* ln2_g   = (const float*)d_in[7];
    const float* ln2_b   = (const float*)d_in[8];
    const float* ffn_w1  = (const float*)d_in[9];
    const float* ffn_b1  = (const float*)d_in[10];
    const float* ffn_w2  = (const float*)d_in[11];
    const float* ffn_b2  = (const float*)d_in[12];
    const float* lnf_g   = (const float*)d_in[13];
    const float* lnf_b   = (const float*)d_in[14];
    const float* head_w  = (const float*)d_in[15];
    const float* head_b  = (const float*)d_in[16];
    float* out = (float*)d_out;

    int nTokens = in_sizes[0] / 4;       // B*T
    int grid = nTokens / MROWS;          // 2048

    // prologue: convert weights into fp16 swizzled tiles (deterministic, capture-safe)
    prep_wtiles<<<36, 256>>>(qkv_w, proj_w, ffn_w1, ffn_w2);

    cudaFuncSetAttribute(waypoint_mma_kernel,
                         cudaFuncAttributeMaxDynamicSharedMemorySize, SMEM_BYTES);

    waypoint_mma_kernel<<<grid, NTH, SMEM_BYTES>>>(
        x, embed_w, embed_b, ln1_g, ln1_b,
        ln2_g, ln2_b, ffn_b1, ffn_b2,
        lnf_g, lnf_b, head_w, head_b, out);
}

// round 17
// speedup vs baseline: 4.4034x; 1.2182x over previous
#include <cuda_runtime.h>
#include <cuda_fp16.h>
#include <cstdint>

// ---------------- problem constants ----------------
#define TT 10
#define DD 64
#define LL 3
#define FF 256
#define NSEQ 8
#define MROWS 80
#define NTH 320

// ---------------- SMEM layout (bytes) ----------------
#define OUT_OFF 0        // fp32 [80][68] = 21760
#define OUT_STR 68
#define A0_OFF  21760    // fp16 [80][64] xor-swizzled, 128B rows (10240)
#define KF_OFF  32000    // fp32 [80][68] = 21760 (aliases A1)
#define A1_OFF  32000    // fp16 tile 10240, inside KF region
#define VH_OFF  53760    // fp16 v tile 10240
#define W0_OFF  64000    // W slot 0: 2 fp16 tiles (16384)
#define W1_OFF  80384    // W slot 1: 16384
#define SBH_OFF 96768    // fp16 [8][4][10][10] = 6400
#define RED_OFF 103168   // float2 [80][2] = 1280
#define A0C_OFF 104448   // fp16 compact 16x64 tile (2048)
#define A1C_OFF 106496   // fp16 compact 16x64 tile (2048)
#define HL_OFF  108544   // fp32 [8][64] = 2048
#define SMEM_BYTES 110592

// Pre-converted swizzled fp16 weight tiles: 36 tiles x 8192 B
__device__ unsigned char g_wtiles[36 * 8192];

// ---------------- helpers ----------------
__device__ __forceinline__ uint32_t smem_u32_of(const void* p) {
    uint32_t a;
    asm("{ .reg .u64 t; cvta.to.shared.u64 t, %1; cvt.u32.u64 %0, t; }" : "=r"(a) : "l"(p));
    return a;
}

__device__ __forceinline__ void ldm4(uint32_t& r0, uint32_t& r1, uint32_t& r2, uint32_t& r3,
                                     uint32_t a) {
    asm volatile("ldmatrix.sync.aligned.m8n8.x4.shared.b16 {%0,%1,%2,%3}, [%4];"
                 : "=r"(r0), "=r"(r1), "=r"(r2), "=r"(r3) : "r"(a));
}

__device__ __forceinline__ void stm4(uint32_t a, uint32_t r0, uint32_t r1,
                                     uint32_t r2, uint32_t r3) {
    asm volatile("stmatrix.sync.aligned.m8n8.x4.shared.b16 [%0], {%1,%2,%3,%4};"
                 :: "r"(a), "r"(r0), "r"(r1), "r"(r2), "r"(r3) : "memory");
}

__device__ __forceinline__ void mma16816(float* d,
                                         uint32_t a0, uint32_t a1, uint32_t a2, uint32_t a3,
                                         uint32_t b0, uint32_t b1) {
    asm volatile("mma.sync.aligned.m16n8k16.row.col.f32.f16.f16.f32 "
                 "{%0,%1,%2,%3}, {%4,%5,%6,%7}, {%8,%9}, {%0,%1,%2,%3};"
                 : "+f"(d[0]), "+f"(d[1]), "+f"(d[2]), "+f"(d[3])
                 : "r"(a0), "r"(a1), "r"(a2), "r"(a3), "r"(b0), "r"(b1));
}

__device__ __forceinline__ void cp16(uint32_t dst, const void* src) {
    asm volatile("cp.async.cg.shared.global [%0], [%1], 16;" :: "r"(dst), "l"(src));
}
__device__ __forceinline__ void cp_commit() {
    asm volatile("cp.async.commit_group;" ::: "memory");
}
__device__ __forceinline__ void cp_wait0() {
    asm volatile("cp.async.wait_group 0;" ::: "memory");
}

__device__ __forceinline__ float gelu_fast(float v) {
    float t = fabsf(v) * 0.70710678118654752f;
    float u = __fdividef(1.0f, fmaf(0.3275911f, t, 1.0f));
    float p = fmaf(1.061405429f, u, -1.453152027f);
    p = fmaf(p, u, 1.421413741f);
    p = fmaf(p, u, -0.284496736f);
    p = fmaf(p, u, 0.254829592f);
    p *= u;
    float e = __expf(-t * t);
    float erf_abs = fmaf(-p, e, 1.0f);
    return 0.5f * v * (1.0f + copysignf(erf_abs, v));
}

__device__ __forceinline__ float sum4(float v) {
    v += __shfl_xor_sync(0xffffffffu, v, 1);
    v += __shfl_xor_sync(0xffffffffu, v, 2);
    return v;
}

__device__ __forceinline__ uint32_t pack1(float x0, float x1) {
    __half2 hp = __floats2half2_rn(x0, x1);
    return *reinterpret_cast<uint32_t*>(&hp);
}

// fragment-layout v[2][8] -> xor-swizzled fp16 tile via 2x stmatrix.x4
__device__ __forceinline__ void frag_store_tile(uint32_t tile_su, int mt, int hf, int lane,
                                                const float v[2][8])
{
    const int t_ = (lane >> 4) & 1;
    const int rh = (lane >> 3) & 1;
    const int jj = lane & 7;
    const int row = mt * 16 + rh * 8 + jj;
#pragma unroll
    for (int cg = 0; cg < 2; cg++) {
        int col8 = hf * 4 + cg * 2 + t_;
        uint32_t addr = tile_su + (uint32_t)row * 128
                      + ((uint32_t)(col8 ^ (row & 7)) << 4);
        uint32_t r0 = pack1(v[0][cg*4 + 0], v[0][cg*4 + 1]);
        uint32_t r1 = pack1(v[1][cg*4 + 0], v[1][cg*4 + 1]);
        uint32_t r2 = pack1(v[0][cg*4 + 2], v[0][cg*4 + 3]);
        uint32_t r3 = pack1(v[1][cg*4 + 2], v[1][cg*4 + 3]);
        stm4(addr, r0, r1, r2, r3);
    }
}

// row-major 16-value store used by the attention y-phase
__device__ __forceinline__ void st_a16(char* t, int row, int c0, const float* v) {
    const uint32_t sw = (uint32_t)(row & 7);
#pragma unroll
    for (int g = 0; g < 2; g++) {
        uint32_t ph[4];
#pragma unroll
        for (int i = 0; i < 4; i++)
            ph[i] = pack1(v[g*8 + 2*i], v[g*8 + 2*i + 1]);
        uint32_t chunk = ((uint32_t)(c0 >> 3) + g) ^ sw;
        *reinterpret_cast<uint4*>(t + row*128 + chunk*16) = make_uint4(ph[0], ph[1], ph[2], ph[3]);
    }
}

__device__ __forceinline__ const float* wptr_for(int st, int& ldg,
    const float* qkv_w, const float* proj_w, const float* w1, const float* w2)
{
    int li = st / 12, k = st % 12;
    switch (k) {
        case 0:  ldg = 192; return qkv_w + li * 64 * 192;
        case 1:  ldg = 192; return qkv_w + li * 64 * 192 + 64;
        case 2:  ldg = 192; return qkv_w + li * 64 * 192 + 128;
        case 3:  ldg = 64;  return proj_w + li * 64 * 64;
        case 4: case 6: case 8: case 10: {
            int ft = (k - 4) >> 1; ldg = 256; return w1 + li * 64 * 256 + ft * 64;
        }
        default: {
            int ft = (k - 5) >> 1; ldg = 64;  return w2 + li * 256 * 64 + ft * 64 * 64;
        }
    }
}

// ---------------- prologue: convert all weight tiles to swizzled fp16 once ----
__global__ void prep_wtiles(const float* __restrict__ qkv_w, const float* __restrict__ proj_w,
                            const float* __restrict__ ffn_w1, const float* __restrict__ ffn_w2)
{
    int st = blockIdx.x;
    int ldg;
    const float* g = wptr_for(st, ldg, qkv_w, proj_w, ffn_w1, ffn_w2);
    unsigned char* hi = g_wtiles + st * 8192;

    int t = threadIdx.x;          // 256 threads
    int n = t & 63, kb = t >> 6;
    const uint32_t sw = (uint32_t)(n & 7);
#pragma unroll
    for (int gg = 0; gg < 2; gg++) {
        uint32_t ph[4];
#pragma unroll
        for (int i = 0; i < 4; i++) {
            int k0 = kb * 16 + gg * 8 + 2 * i;
            ph[i] = pack1(g[k0 * ldg + n], g[(k0 + 1) * ldg + n]);
        }
        uint32_t chunk = ((uint32_t)(2*kb + gg)) ^ sw;
        *reinterpret_cast<uint4*>(hi + n*128 + chunk*16) = make_uint4(ph[0], ph[1], ph[2], ph[3]);
    }
}

__device__ __forceinline__ void prefetch_w(uint32_t su, uint32_t slot, int t0, int cnt) {
    if (threadIdx.x < 256) {
        uint32_t dst = su + slot + (uint32_t)threadIdx.x * 32;
        const unsigned char* s0 = g_wtiles + (size_t)t0 * 8192 + threadIdx.x * 32;
        cp16(dst, s0);
        cp16(dst + 16, s0 + 16);
        if (cnt == 2) {
            cp16(dst + 8192, s0 + 8192);
            cp16(dst + 8192 + 16, s0 + 8192 + 16);
        }
    }
    cp_commit();
}

// ---------------- MMA mainloop: single-pass fp16 x fp16 ----------
// Warp (mt, hf) computes rows mt*16..+15, cols hf*32..+31 of A(aoff) @ W(woff).
__device__ __forceinline__ void mma_compute(uint32_t su, uint32_t aoff,
                                            uint32_t woff, float d[2][2][4])
{
    const int w    = threadIdx.x >> 5;
    const int lane = threadIdx.x & 31;
    const int mt = w >> 1;
    const int hf = w & 1;
    const int rl = (lane & 7) | (((lane >> 3) & 1) << 3);
    const int klane = lane >> 4;
    const int l7 = lane & 7;

    const uint32_t aB = su + aoff + (uint32_t)(mt*16 + rl) * 128;
    const uint32_t bB = su + woff + (uint32_t)(hf*32 + rl) * 128;

#pragma unroll
    for (int c = 0; c < 2; c++)
#pragma unroll
        for (int t = 0; t < 2; t++)
#pragma unroll
            for (int j = 0; j < 4; j++) d[c][t][j] = 0.f;

#pragma unroll
    for (int ks = 0; ks < 4; ks++) {
        const uint32_t coff = (uint32_t)(((ks*2 + klane) ^ l7) << 4);
        uint32_t a0, a1, a2, a3;
        uint32_t b00, b01, b02, b03, b10, b11, b12, b13;
        ldm4(a0, a1, a2, a3, aB + coff);
        ldm4(b00, b01, b02, b03, bB + coff);
        ldm4(b10, b11, b12, b13, bB + 2048u + coff);
        mma16816(d[0][0], a0, a1, a2, a3, b00, b02);
        mma16816(d[0][1], a0, a1, a2, a3, b01, b03);
        mma16816(d[1][0], a0, a1, a2, a3, b10, b12);
        mma16816(d[1][1], a0, a1, a2, a3, b11, b13);
    }
}

__device__ __forceinline__ void frag_to_f32(const float d[2][2][4], float* dstF) {
    const int w    = threadIdx.x >> 5;
    const int lane = threadIdx.x & 31;
    const int mt = w >> 1, hf = w & 1;
    const int r0 = mt*16 + (lane >> 2);
    const int cb = (lane & 3) * 2;
#pragma unroll
    for (int c = 0; c < 2; c++) {
        int cg = hf*2 + c;
#pragma unroll
        for (int t = 0; t < 2; t++) {
            *reinterpret_cast<float2*>(dstF + r0 * OUT_STR + cg*16 + cb + t*8) =
                make_float2(d[c][t][0], d[c][t][1]);
            *reinterpret_cast<float2*>(dstF + (r0 + 8) * OUT_STR + cg*16 + cb + t*8) =
                make_float2(d[c][t][2], d[c][t][3]);
        }
    }
}

// pair-local LayerNorm stats on fragment rows (rA, rA+8)
__device__ __forceinline__ void frag_ln(const float v[2][8], int rA, int hf, int mt, int lane,
                                        float2* red2, float m[2], float iv[2])
{
    float s0 = 0.f, q0 = 0.f, s1 = 0.f, q1 = 0.f;
#pragma unroll
    for (int j = 0; j < 8; j++) {
        s0 += v[0][j]; q0 += v[0][j]*v[0][j];
        s1 += v[1][j]; q1 += v[1][j]*v[1][j];
    }
    s0 = sum4(s0); q0 = sum4(q0); s1 = sum4(s1); q1 = sum4(q1);
    if ((lane & 3) == 0) {
        red2[rA*2 + hf]     = make_float2(s0, q0);
        red2[(rA+8)*2 + hf] = make_float2(s1, q1);
    }
    asm volatile("bar.sync %0, %1;" :: "r"(mt + 1), "r"(64) : "memory");
    float2 o0 = red2[rA*2 + (hf^1)];
    float2 o1 = red2[(rA+8)*2 + (hf^1)];
    float S0 = s0 + o0.x, Q0 = q0 + o0.y;
    float S1 = s1 + o1.x, Q1 = q1 + o1.y;
    m[0] = S0 * (1.f/64.f);
    iv[0] = rsqrtf(Q0 * (1.f/64.f) - m[0]*m[0] + 1e-5f);
    m[1] = S1 * (1.f/64.f);
    iv[1] = rsqrtf(Q1 * (1.f/64.f) - m[1]*m[1] + 1e-5f);
}

// =====================================================================
__global__ __launch_bounds__(NTH, 2)
void waypoint_mma_kernel(
    const float* __restrict__ x,
    const float* __restrict__ embed_w, const float* __restrict__ embed_b,
    const float* __restrict__ ln1_g,   const float* __restrict__ ln1_b,
    const float* __restrict__ ln2_g,   const float* __restrict__ ln2_b,
    const float* __restrict__ ffn_b1,  const float* __restrict__ ffn_b2,
    const float* __restrict__ lnf_g,   const float* __restrict__ lnf_b,
    const float* __restrict__ head_w,  const float* __restrict__ head_b,
    float* __restrict__ out)
{
    extern __shared__ char smc[];
    const uint32_t su = smem_u32_of(smc);
    float*  outF = reinterpret_cast<float*>(smc + OUT_OFF);
    float*  kF   = reinterpret_cast<float*>(smc + KF_OFF);
    __half* SBH  = reinterpret_cast<__half*>(smc + SBH_OFF);
    float2* red2 = reinterpret_cast<float2*>(smc + RED_OFF);
    float*  hL   = reinterpret_cast<float*>(smc + HL_OFF);

    const int tid  = threadIdx.x;
    const int w    = tid >> 5;
    const int lane = tid & 31;
    const int mt   = w >> 1;
    const int hf   = w & 1;
    const int rA   = mt*16 + (lane >> 2);
    const int cb   = (lane & 3) * 2;
    const int rowBase = blockIdx.x * MROWS;

    int colv[8];
#pragma unroll
    for (int j = 0; j < 8; j++)
        colv[j] = hf*32 + (j>>2)*16 + ((j>>1)&1)*8 + cb + (j&1);

    float hreg[2][8];   // residual stream, fragment layout (layers 0-1; compact h in layer 2)

    // preload layer-0 (q,k) into slot 0 (overlaps embed)
    prefetch_w(su, W0_OFF, 0, 2);

    // zero compact pad regions: A0C rows 8-15 (1024B) + all A1C (2048B)
    if (tid < 192) {
        uint32_t off = (tid < 64) ? (A0C_OFF + 1024 + tid * 16)
                                  : (A1C_OFF + (tid - 64) * 16);
        *reinterpret_cast<uint4*>(smc + off) = make_uint4(0, 0, 0, 0);
    }

    // -------- embed + ln1(layer0) -> A0, fragment layout --------
    {
        float v[2][8];
#pragma unroll
        for (int r = 0; r < 2; r++) {
            int row = rA + 8*r;
            float4 xv = reinterpret_cast<const float4*>(x)[rowBase + row];
#pragma unroll
            for (int j = 0; j < 8; j++) {
                int col = colv[j];
                float a = embed_b[col];
                a = fmaf(xv.x, embed_w[col],       a);
                a = fmaf(xv.y, embed_w[64 + col],  a);
                a = fmaf(xv.z, embed_w[128 + col], a);
                a = fmaf(xv.w, embed_w[192 + col], a);
                v[r][j] = a; hreg[r][j] = a;
            }
        }
        float s0=0,q0=0,s1=0,q1=0;
#pragma unroll
        for (int j = 0; j < 8; j++) {
            s0 += v[0][j]; q0 += v[0][j]*v[0][j];
            s1 += v[1][j]; q1 += v[1][j]*v[1][j];
        }
        s0=sum4(s0); q0=sum4(q0); s1=sum4(s1); q1=sum4(q1);
        if ((lane & 3) == 0) {
            red2[rA*2 + hf]     = make_float2(s0, q0);
            red2[(rA+8)*2 + hf] = make_float2(s1, q1);
        }
        __syncthreads();
        float2 o0 = red2[rA*2 + (hf^1)];
        float2 o1 = red2[(rA+8)*2 + (hf^1)];
        float m0 = (s0+o0.x)*(1.f/64.f), i0 = rsqrtf((q0+o0.y)*(1.f/64.f)-m0*m0+1e-5f);
        float m1 = (s1+o1.x)*(1.f/64.f), i1 = rsqrtf((q1+o1.y)*(1.f/64.f)-m1*m1+1e-5f);
        float o[2][8];
#pragma unroll
        for (int j = 0; j < 8; j++) {
            int col = colv[j];
            o[0][j] = (v[0][j]-m0)*i0*ln1_g[col]+ln1_b[col];
            o[1][j] = (v[1][j]-m1)*i1*ln1_g[col]+ln1_b[col];
        }
        frag_store_tile(su + A0_OFF, mt, hf, lane, o);
    }
    cp_wait0();
    __syncthreads();

    // ================= layers 0, 1 : full-rate =================
    for (int li = 0; li < 2; li++) {
        const int tb = li * 12;

        // ----- stage qk (slot 0 holds q,k) -----
        prefetch_w(su, W1_OFF, tb + 2, 2);          // v, proj
        {
            float d[2][2][4];
            mma_compute(su, A0_OFF, W0_OFF, d);
            frag_to_f32(d, outF);                   // q
            mma_compute(su, A0_OFF, W0_OFF + 8192, d);
            frag_to_f32(d, kF);                     // k
        }
        cp_wait0(); __syncthreads();

        // ----- stage v + S -----
        prefetch_w(su, W0_OFF, tb + 4, 2);          // w1_0, w2_0
        {
            float d[2][2][4];
            mma_compute(su, A0_OFF, W1_OFF, d);     // v
            float vv[2][8];
#pragma unroll
            for (int j = 0; j < 8; j++) {
                int c = j>>2, t = (j>>1)&1, e = j&1;
                vv[0][j] = d[c][t][e];
                vv[1][j] = d[c][t][2+e];
            }
            frag_store_tile(su + VH_OFF, mt, hf, lane, vv);

            // S phase: warp w = q, lane = (s,h)
            {
                const int qq = w;
                const int s  = lane >> 2;
                const int h  = lane & 3;
                const float4* qp = reinterpret_cast<const float4*>(outF + (s*TT + qq) * OUT_STR + h * 16);
                float4 qv[4];
#pragma unroll
                for (int dd = 0; dd < 4; dd++) qv[dd] = qp[dd];
                float sc[TT];
                float mx = -1e30f;
                for (int kk = 0; kk <= qq; kk++) {
                    const float4* kp = reinterpret_cast<const float4*>(kF + (s*TT + kk) * OUT_STR + h * 16);
                    float a = 0.f;
#pragma unroll
                    for (int dd = 0; dd < 4; dd++) {
                        float4 kv = kp[dd];
                        a = fmaf(qv[dd].x, kv.x, a);
                        a = fmaf(qv[dd].y, kv.y, a);
                        a = fmaf(qv[dd].z, kv.z, a);
                        a = fmaf(qv[dd].w, kv.w, a);
                    }
                    a *= 0.25f;
                    sc[kk] = a;
                    mx = fmaxf(mx, a);
                }
                float ss = 0.f;
                for (int kk = 0; kk <= qq; kk++) { sc[kk] = __expf(sc[kk] - mx); ss += sc[kk]; }
                float inv = __fdividef(1.f, ss);
                __half* sp = SBH + ((s * 4 + h) * TT + qq) * TT;
                for (int kk = 0; kk <= qq; kk++) sp[kk] = __float2half(sc[kk] * inv);
            }
        }
        __syncthreads();

        // ----- y phase -----
        {
            const int qq = w;
            const int s  = lane >> 2;
            const int h  = lane & 3;
            const int rq = s * TT + qq;
            const __half* sp = SBH + ((s * 4 + h) * TT + qq) * TT;
            float y[16];
#pragma unroll
            for (int i = 0; i < 16; i++) y[i] = 0.f;
            for (int kk = 0; kk <= qq; kk++) {
                float wgt = __half2float(sp[kk]);
                int r = s*TT + kk;
                const char* base = smc + VH_OFF + r * 128;
                uint4 u0 = *reinterpret_cast<const uint4*>(base + (((h*2)     ^ (r & 7)) << 4));
                uint4 u1 = *reinterpret_cast<const uint4*>(base + (((h*2 + 1) ^ (r & 7)) << 4));
                uint32_t uw[8] = {u0.x, u0.y, u0.z, u0.w, u1.x, u1.y, u1.z, u1.w};
#pragma unroll
                for (int p = 0; p < 8; p++) {
                    float2 f = __half22float2(*reinterpret_cast<const __half2*>(&uw[p]));
                    y[p*2+0] = fmaf(wgt, f.x, y[p*2+0]);
                    y[p*2+1] = fmaf(wgt, f.y, y[p*2+1]);
                }
            }
            st_a16(smc + A1_OFF, rq, h * 16, y);
        }
        __syncthreads();

        // ----- proj -----
        {
            float d[2][2][4];
            mma_compute(su, A1_OFF, W1_OFF + 8192, d);
            float v[2][8];
#pragma unroll
            for (int j = 0; j < 8; j++) {
                int c = j>>2, t = (j>>1)&1, e = j&1;
                v[0][j] = d[c][t][e]   + hreg[0][j]; hreg[0][j] = v[0][j];
                v[1][j] = d[c][t][2+e] + hreg[1][j]; hreg[1][j] = v[1][j];
            }
            float m[2], iv[2];
            frag_ln(v, rA, hf, mt, lane, red2, m, iv);
            const float* g = ln2_g + li*DD;
            const float* b = ln2_b + li*DD;
            float o[2][8];
#pragma unroll
            for (int j = 0; j < 8; j++) {
                int col = colv[j];
                o[0][j] = (v[0][j]-m[0])*iv[0]*g[col]+b[col];
                o[1][j] = (v[1][j]-m[1])*iv[1]*g[col]+b[col];
            }
            frag_store_tile(su + A0_OFF, mt, hf, lane, o);
        }
        cp_wait0(); __syncthreads();

        // ----- merged FFN stages -----
        for (int ft = 0; ft < 4; ft++) {
            const uint32_t cur = (ft & 1) ? W1_OFF : W0_OFF;
            const uint32_t nxt = (ft & 1) ? W0_OFF : W1_OFF;
            if (ft < 3) prefetch_w(su, nxt, tb + 6 + 2*ft, 2);
            else        prefetch_w(su, nxt, tb + 12, 2);   // next layer (q,k)

            {
                float d[2][2][4];
                mma_compute(su, A0_OFF, cur, d);
                const float* b1 = ffn_b1 + li*FF + ft*64;
                float o[2][8];
#pragma unroll
                for (int j = 0; j < 8; j++) {
                    int c = j>>2, t = (j>>1)&1, e = j&1;
                    int col = colv[j];
                    o[0][j] = gelu_fast(d[c][t][e]   + b1[col]);
                    o[1][j] = gelu_fast(d[c][t][2+e] + b1[col]);
                }
                frag_store_tile(su + A1_OFF, mt, hf, lane, o);
            }
            asm volatile("bar.sync %0, 64;" :: "r"(mt + 1) : "memory");

            {
                float d[2][2][4];
                mma_compute(su, A1_OFF, cur + 8192, d);
#pragma unroll
                for (int j = 0; j < 8; j++) {
                    int c = j>>2, t = (j>>1)&1, e = j&1;
                    float add0 = d[c][t][e], add1 = d[c][t][2+e];
                    if (ft == 0) {
                        float bb = ffn_b2[li*DD + colv[j]];
                        add0 += bb; add1 += bb;
                    }
                    hreg[0][j] += add0;
                    hreg[1][j] += add1;
                }
                if (ft == 3) {
                    float m[2], iv[2];
                    frag_ln(hreg, rA, hf, mt, lane, red2, m, iv);
                    const float* g = ln1_g + (li+1)*DD;
                    const float* b = ln1_b + (li+1)*DD;
                    float o[2][8];
#pragma unroll
                    for (int j = 0; j < 8; j++) {
                        int col = colv[j];
                        o[0][j] = (hreg[0][j]-m[0])*iv[0]*g[col]+b[col];
                        o[1][j] = (hreg[1][j]-m[1])*iv[1]*g[col]+b[col];
                    }
                    frag_store_tile(su + A0_OFF, mt, hf, lane, o);
                    if (li == 1) {
                        // save residual h for last-token rows -> hL
#pragma unroll
                        for (int r = 0; r < 2; r++) {
                            int row = rA + 8*r;
                            if (row % 10 == 9) {
                                float* dst = hL + (row / 10) * 64;
#pragma unroll
                                for (int j = 0; j < 8; j++) dst[colv[j]] = hreg[r][j];
                            }
                        }
                    }
                }
            }
            cp_wait0(); __syncthreads();
        }
    }

    // ================= layer 2 : last-token compact =================
    {
        // ----- stage qk: k full; q compact (pair mt0) -----
        prefetch_w(su, W1_OFF, 26, 2);              // v, proj
        if (w < 2) {
            // gather ln1 rows s*10+9 -> A0C rows s
            if (tid < 64) {
                int cr = tid >> 3, c = tid & 7;
                int r = cr * 10 + 9;
                uint4 vsrc = *reinterpret_cast<const uint4*>(
                    smc + A0_OFF + r * 128 + ((c ^ (r & 7)) << 4));
                *reinterpret_cast<uint4*>(
                    smc + A0C_OFF + cr * 128 + ((c ^ (cr & 7)) << 4)) = vsrc;
            }
            asm volatile("bar.sync 1, 64;" ::: "memory");
            float d[2][2][4];
            mma_compute(su, A0C_OFF, W0_OFF, d);    // q compact (mt=0)
            frag_to_f32(d, outF);                   // rows 0..15 (cr)
        }
        {
            float d[2][2][4];
            mma_compute(su, A0_OFF, W0_OFF + 8192, d);
            frag_to_f32(d, kF);                     // k full
        }
        cp_wait0(); __syncthreads();

        // ----- stage v + S(q=9 only) -----
        prefetch_w(su, W0_OFF, 28, 2);              // w1_0, w2_0
        float sc[TT];                               // probs live in registers (warp 9)
        float sinv = 0.f;
        {
            float d[2][2][4];
            mma_compute(su, A0_OFF, W1_OFF, d);     // v full
            float vv[2][8];
#pragma unroll
            for (int j = 0; j < 8; j++) {
                int c = j>>2, t = (j>>1)&1, e = j&1;
                vv[0][j] = d[c][t][e];
                vv[1][j] = d[c][t][2+e];
            }
            frag_store_tile(su + VH_OFF, mt, hf, lane, vv);

            if (w == 9) {
                const int s = lane >> 2;
                const int h = lane & 3;
                const float4* qp = reinterpret_cast<const float4*>(outF + s * OUT_STR + h * 16);
                float4 qv[4];
#pragma unroll
                for (int dd = 0; dd < 4; dd++) qv[dd] = qp[dd];
                float mx = -1e30f;
                for (int kk = 0; kk < TT; kk++) {
                    const float4* kp = reinterpret_cast<const float4*>(kF + (s*TT + kk) * OUT_STR + h * 16);
                    float a = 0.f;
#pragma unroll
                    for (int dd = 0; dd < 4; dd++) {
                        float4 kv = kp[dd];
                        a = fmaf(qv[dd].x, kv.x, a);
                        a = fmaf(qv[dd].y, kv.y, a);
                        a = fmaf(qv[dd].z, kv.z, a);
                        a = fmaf(qv[dd].w, kv.w, a);
                    }
                    a *= 0.25f;
                    sc[kk] = a;
                    mx = fmaxf(mx, a);
                }
                float ss = 0.f;
                for (int kk = 0; kk < TT; kk++) { sc[kk] = __expf(sc[kk] - mx); ss += sc[kk]; }
                sinv = __fdividef(1.f, ss);
            }
        }
        __syncthreads();

        // ----- y (warp 9) -> A1C rows s -----
        if (w == 9) {
            const int s = lane >> 2;
            const int h = lane & 3;
            float y[16];
#pragma unroll
            for (int i = 0; i < 16; i++) y[i] = 0.f;
            for (int kk = 0; kk < TT; kk++) {
                float wgt = sc[kk] * sinv;
                int r = s*TT + kk;
                const char* base = smc + VH_OFF + r * 128;
                uint4 u0 = *reinterpret_cast<const uint4*>(base + (((h*2)     ^ (r & 7)) << 4));
                uint4 u1 = *reinterpret_cast<const uint4*>(base + (((h*2 + 1) ^ (r & 7)) << 4));
                uint32_t uw[8] = {u0.x, u0.y, u0.z, u0.w, u1.x, u1.y, u1.z, u1.w};
#pragma unroll
                for (int p = 0; p < 8; p++) {
                    float2 f = __half22float2(*reinterpret_cast<const __half2*>(&uw[p]));
                    y[p*2+0] = fmaf(wgt, f.x, y[p*2+0]);
                    y[p*2+1] = fmaf(wgt, f.y, y[p*2+1]);
                }
            }
            st_a16(smc + A1C_OFF, s, h * 16, y);
        }
        __syncthreads();

        // ----- proj compact (pair mt0): h = d + hL ; ln2 -> A0C -----
        if (w < 2) {
            float d[2][2][4];
            mma_compute(su, A1C_OFF, W1_OFF + 8192, d);
            const int cr = lane >> 2;               // 0..7 valid
#pragma unroll
            for (int j = 0; j < 8; j++) {
                int c = j>>2, t = (j>>1)&1, e = j&1;
                hreg[0][j] = d[c][t][e] + hL[cr * 64 + colv[j]];
                hreg[1][j] = d[c][t][2+e];          // pad rows
            }
            float m[2], iv[2];
            frag_ln(hreg, cr, hf, 0, lane, red2, m, iv);
            const float* g = ln2_g + 2*DD;
            const float* b = ln2_b + 2*DD;
            float o[2][8];
#pragma unroll
            for (int j = 0; j < 8; j++) {
                int col = colv[j];
                o[0][j] = (hreg[0][j]-m[0])*iv[0]*g[col]+b[col];
                o[1][j] = (hreg[1][j]-m[1])*iv[1]*g[col]+b[col];
            }
            frag_store_tile(su + A0C_OFF, 0, hf, lane, o);
        }
        cp_wait0(); __syncthreads();

        // ----- compact FFN -----
        for (int ft = 0; ft < 4; ft++) {
            const uint32_t cur = (ft & 1) ? W1_OFF : W0_OFF;
            const uint32_t nxt = (ft & 1) ? W0_OFF : W1_OFF;
            if (ft < 3) prefetch_w(su, nxt, 30 + 2*ft, 2);

            if (w < 2) {
                {
                    float d[2][2][4];
                    mma_compute(su, A0C_OFF, cur, d);
                    const float* b1 = ffn_b1 + 2*FF + ft*64;
                    float o[2][8];
#pragma unroll
                    for (int j = 0; j < 8; j++) {
                        int c = j>>2, t = (j>>1)&1, e = j&1;
                        int col = colv[j];
                        o[0][j] = gelu_fast(d[c][t][e]   + b1[col]);
                        o[1][j] = gelu_fast(d[c][t][2+e] + b1[col]);
                    }
                    frag_store_tile(su + A1C_OFF, 0, hf, lane, o);
                }
                asm volatile("bar.sync 1, 64;" ::: "memory");
                {
                    float d[2][2][4];
                    mma_compute(su, A1C_OFF, cur + 8192, d);
#pragma unroll
                    for (int j = 0; j < 8; j++) {
                        int c = j>>2, t = (j>>1)&1, e = j&1;
                        float add0 = d[c][t][e], add1 = d[c][t][2+e];
                        if (ft == 0) {
                            float bb = ffn_b2[2*DD + colv[j]];
                            add0 += bb; add1 += bb;
                        }
                        hreg[0][j] += add0;
                        hreg[1][j] += add1;
                    }
                    if (ft == 3) {
                        const int cr = lane >> 2;
                        float m[2], iv[2];
                        frag_ln(hreg, cr, hf, 0, lane, red2, m, iv);
#pragma unroll
                        for (int j = 0; j < 8; j += 2) {
                            int col2 = colv[j];
                            *reinterpret_cast<float2*>(outF + cr*OUT_STR + col2) =
                                make_float2((hreg[0][j]-m[0])*iv[0]*lnf_g[col2]+lnf_b[col2],
                                            (hreg[0][j+1]-m[0])*iv[0]*lnf_g[col2+1]+lnf_b[col2+1]);
                        }
                    }
                }
            }
            cp_wait0(); __syncthreads();
        }
    }

    // -------- head: lnf rows are compact (row s) --------
    if (tid < NSEQ * TT) {
        int s = tid / TT;
        int j = tid % TT;
        const float* r = outF + s * OUT_STR;
        float a = head_b[j];
#pragma unroll 16
        for (int dd = 0; dd < DD; dd++) a = fmaf(r[dd], head_w[dd * 10 + j], a);
        out[(blockIdx.x * NSEQ + s) * 10 + j] = a;
    }
}

extern "C" void kernel_launch(void* const* d_in, const int* in_sizes, int n_in,
                              void* d_out, int out_size)
{
    const float* x       = (const float*)d_in[0];
    const float* embed_w = (const float*)d_in[1];
    const float* embed_b = (const float*)d_in[2];
    const float* ln1_g   = (const float*)d_in[3];
    const float* ln1_b   = (const float*)d_in[4];
    const float* qkv_w   = (const float*)d_in[5];
    const float* proj_w  = (const float*)d_in[6];
    const float* ln2_g   = (const float*)d_in[7];
    const float* ln2_b   = (const float*)d_in[8];
    const float* ffn_w1  = (const float*)d_in[9];
    const float* ffn_b1  = (const float*)d_in[10];
    const float* ffn_w2  = (const float*)d_in[11];
    const float* ffn_b2  = (const float*)d_in[12];
    const float* lnf_g   = (const float*)d_in[13];
    const float* lnf_b   = (const float*)d_in[14];
    const float* head_w  = (const float*)d_in[15];
    const float* head_b  = (const float*)d_in[16];
    float* out = (float*)d_out;

    int nTokens = in_sizes[0] / 4;       // B*T
    int grid = nTokens / MROWS;          // 2048

    prep_wtiles<<<36, 256>>>(qkv_w, proj_w, ffn_w1, ffn_w2);

    cudaFuncSetAttribute(waypoint_mma_kernel,
                         cudaFuncAttributeMaxDynamicSharedMemorySize, SMEM_BYTES);

    waypoint_mma_kernel<<<grid, NTH, SMEM_BYTES>>>(
        x, embed_w, embed_b, ln1_g, ln1_b,
        ln2_g, ln2_b, ffn_b1, ffn_b2,
        lnf_g, lnf_b, head_w, head_b, out);
}